// round 7
// baseline (speedup 1.0000x reference)
#include <cuda_runtime.h>
#include <cstdint>

#define NQ 8192
#define MK 8192
#define BB 16
#define CC 512
#define LL 64
#define HH 8
#define DD 64

// fp32 intermediates
__device__ float g_q[NQ * CC];
__device__ float g_k[MK * CC];
__device__ float g_v[MK * CC];
__device__ float g_w[HH * NQ * LL];     // softmax weights scratch (16 MB)
__device__ float g_aux_scratch[NQ * LL];
__device__ int   g_key_start[BB];

// bf16 split operands (hi/lo), packed 2 elements per uint32
__device__ uint32_t g_bQh[NQ * CC / 2], g_bQl[NQ * CC / 2];
__device__ uint32_t g_bKh[MK * CC / 2], g_bKl[MK * CC / 2];
__device__ uint32_t g_bVh[MK * CC / 2], g_bVl[MK * CC / 2];
__device__ uint32_t g_bWih[3 * CC * CC / 2], g_bWil[3 * CC * CC / 2];
__device__ uint32_t g_bWoh[CC * CC / 2],     g_bWol[CC * CC / 2];
__device__ uint32_t g_bAh[NQ * CC / 2],      g_bAl[NQ * CC / 2];

// ---------------------------------------------------------------------------
static __device__ __forceinline__ uint32_t smem_u32(const void* p) {
    uint32_t a;
    asm("{ .reg .u64 t; cvta.to.shared.u64 t, %1; cvt.u32.u64 %0, t; }" : "=r"(a) : "l"(p));
    return a;
}
static __device__ __forceinline__ uint32_t packbf(float f0, float f1) {
    uint32_t r;
    asm("cvt.rn.bf16x2.f32 %0, %1, %2;" : "=r"(r) : "f"(f1), "f"(f0));
    return r;
}
static __device__ __forceinline__ float bflo(uint32_t r) { return __uint_as_float(r << 16); }
static __device__ __forceinline__ float bfhi(uint32_t r) { return __uint_as_float(r & 0xffff0000u); }
static __device__ __forceinline__ uint32_t lds32(uint32_t a) {
    uint32_t v; asm volatile("ld.shared.b32 %0, [%1];" : "=r"(v) : "r"(a)); return v;
}
static __device__ __forceinline__ void cpa16(uint32_t dst, const void* src) {
    asm volatile("cp.async.cg.shared.global [%0], [%1], 16;" :: "r"(dst), "l"(src) : "memory");
}
#define CP_COMMIT asm volatile("cp.async.commit_group;" ::: "memory")
#define CP_WAIT1  asm volatile("cp.async.wait_group 1;" ::: "memory")
#define CP_WAIT0  asm volatile("cp.async.wait_group 0;" ::: "memory")

#define MMA_BF16(c, a0, a1, a2, a3, b0, b1)                                   \
    asm volatile(                                                             \
        "mma.sync.aligned.m16n8k16.row.col.f32.bf16.bf16.f32 "                \
        "{%0,%1,%2,%3},{%4,%5,%6,%7},{%8,%9},{%0,%1,%2,%3};"                  \
        : "+f"((c)[0]), "+f"((c)[1]), "+f"((c)[2]), "+f"((c)[3])              \
        : "r"(a0), "r"(a1), "r"(a2), "r"(a3), "r"(b0), "r"(b1))

// ---------------------------------------------------------------------------
__global__ void key_start_kernel(const int* __restrict__ key_batch_cnt) {
    if (threadIdx.x == 0) {
        int s = 0;
        for (int b = 0; b < BB; b++) { g_key_start[b] = s; s += key_batch_cnt[b]; }
    }
}

// fp32 -> (bf16 hi, bf16 lo) split; blockIdx.y selects q/k/v
__global__ void __launch_bounds__(256) cvt3_kernel(
    const float4* __restrict__ q, const float4* __restrict__ k,
    const float4* __restrict__ v)
{
    const int z = blockIdx.y;
    const float4* src = (z == 0) ? q : (z == 1) ? k : v;
    uint2* hi = (uint2*)((z == 0) ? g_bQh : (z == 1) ? g_bKh : g_bVh);
    uint2* lo = (uint2*)((z == 0) ? g_bQl : (z == 1) ? g_bKl : g_bVl);
    int i = blockIdx.x * blockDim.x + threadIdx.x;
    float4 f = src[i];
    uint32_t h0 = packbf(f.x, f.y);
    uint32_t h1 = packbf(f.z, f.w);
    uint32_t l0 = packbf(f.x - bflo(h0), f.y - bfhi(h0));
    uint32_t l1 = packbf(f.z - bflo(h1), f.w - bfhi(h1));
    hi[i] = make_uint2(h0, h1);
    lo[i] = make_uint2(l0, l1);
}

__global__ void __launch_bounds__(256) cvt_split_kernel(
    const float4* __restrict__ src, uint2* __restrict__ hi, uint2* __restrict__ lo, int n4)
{
    int i = blockIdx.x * blockDim.x + threadIdx.x;
    if (i >= n4) return;
    float4 f = src[i];
    uint32_t h0 = packbf(f.x, f.y);
    uint32_t h1 = packbf(f.z, f.w);
    uint32_t l0 = packbf(f.x - bflo(h0), f.y - bfhi(h0));
    uint32_t l1 = packbf(f.z - bflo(h1), f.w - bfhi(h1));
    hi[i] = make_uint2(h0, h1);
    lo[i] = make_uint2(l0, l1);
}

// ===========================================================================
// Split-bf16 HMMA GEMM (unchanged — at HMMA pipe rate)
// ===========================================================================
#define SROWB 80
#define TILE_B (128 * SROWB)
#define STAGE_B (4 * TILE_B)
#define DSMEM_SIZE (2 * STAGE_B)

__device__ __forceinline__ void gemm_bf16_body(
    const uint32_t* __restrict__ Ah, const uint32_t* __restrict__ Al,
    const uint32_t* __restrict__ Bh, const uint32_t* __restrict__ Bl,
    const float* __restrict__ bias, float* __restrict__ Cout, float alpha)
{
    extern __shared__ char dsm[];
    const uint32_t sbase = smem_u32(dsm);

    const int t = threadIdx.x;
    const int lane = t & 31, warp = t >> 5;
    const int g = lane >> 2, tig = lane & 3;
    const int warpM = warp & 1, warpN = warp >> 1;
    const int row0 = blockIdx.y * 128, col0 = blockIdx.x * 128;

    const int crow = t >> 1, chalf = t & 1;
    const uint32_t dstoff = (uint32_t)(crow * SROWB + chalf * 32);
    const size_t srcAbase = (size_t)(row0 + crow) * (CC / 2) + chalf * 8;
    const size_t srcBbase = (size_t)(col0 + crow) * (CC / 2) + chalf * 8;

    float acc[4][4][4];
#pragma unroll
    for (int m = 0; m < 4; m++)
#pragma unroll
        for (int n = 0; n < 4; n++)
#pragma unroll
            for (int j = 0; j < 4; j++) acc[m][n][j] = 0.0f;

#define ISSUE(kt, buf)                                                         \
    do {                                                                       \
        uint32_t sb = sbase + (buf) * STAGE_B;                                 \
        size_t ksrc = (size_t)(kt) * 16;                                       \
        cpa16(sb + dstoff,                  Ah + srcAbase + ksrc);             \
        cpa16(sb + dstoff + 16,             Ah + srcAbase + ksrc + 4);         \
        cpa16(sb + TILE_B + dstoff,         Al + srcAbase + ksrc);             \
        cpa16(sb + TILE_B + dstoff + 16,    Al + srcAbase + ksrc + 4);         \
        cpa16(sb + 2*TILE_B + dstoff,       Bh + srcBbase + ksrc);             \
        cpa16(sb + 2*TILE_B + dstoff + 16,  Bh + srcBbase + ksrc + 4);         \
        cpa16(sb + 3*TILE_B + dstoff,       Bl + srcBbase + ksrc);             \
        cpa16(sb + 3*TILE_B + dstoff + 16,  Bl + srcBbase + ksrc + 4);         \
    } while (0)

    const int NT = CC / 32;
    ISSUE(0, 0);
    CP_COMMIT;

    for (int kt = 0; kt < NT; kt++) {
        if (kt + 1 < NT) {
            ISSUE(kt + 1, (kt + 1) & 1);
            CP_COMMIT;
            CP_WAIT1;
        } else {
            CP_WAIT0;
        }
        __syncthreads();

        const uint32_t ab = sbase + (kt & 1) * STAGE_B;
#pragma unroll
        for (int sub = 0; sub < 2; sub++) {
            const uint32_t koff = sub * 32;
            uint32_t af[4][4];

#pragma unroll
            for (int m = 0; m < 4; m++) {
                uint32_t ro = ab + (uint32_t)((warpM * 64 + m * 16 + g) * SROWB) + koff + tig * 4;
                af[m][0] = lds32(ro);
                af[m][1] = lds32(ro + 8 * SROWB);
                af[m][2] = lds32(ro + 16);
                af[m][3] = lds32(ro + 8 * SROWB + 16);
            }
#pragma unroll
            for (int n = 0; n < 4; n++) {
                uint32_t bo = ab + 2 * TILE_B +
                    (uint32_t)((warpN * 32 + n * 8 + g) * SROWB) + koff + tig * 4;
                uint32_t bh0 = lds32(bo), bh1 = lds32(bo + 16);
                uint32_t bl0 = lds32(bo + TILE_B), bl1 = lds32(bo + TILE_B + 16);
#pragma unroll
                for (int m = 0; m < 4; m++) {
                    MMA_BF16(acc[m][n], af[m][0], af[m][1], af[m][2], af[m][3], bh0, bh1);
                    MMA_BF16(acc[m][n], af[m][0], af[m][1], af[m][2], af[m][3], bl0, bl1);
                }
            }

#pragma unroll
            for (int m = 0; m < 4; m++) {
                uint32_t ro = ab + TILE_B +
                    (uint32_t)((warpM * 64 + m * 16 + g) * SROWB) + koff + tig * 4;
                af[m][0] = lds32(ro);
                af[m][1] = lds32(ro + 8 * SROWB);
                af[m][2] = lds32(ro + 16);
                af[m][3] = lds32(ro + 8 * SROWB + 16);
            }
#pragma unroll
            for (int n = 0; n < 4; n++) {
                uint32_t bo = ab + 2 * TILE_B +
                    (uint32_t)((warpN * 32 + n * 8 + g) * SROWB) + koff + tig * 4;
                uint32_t bh0 = lds32(bo), bh1 = lds32(bo + 16);
#pragma unroll
                for (int m = 0; m < 4; m++)
                    MMA_BF16(acc[m][n], af[m][0], af[m][1], af[m][2], af[m][3], bh0, bh1);
            }
        }
        __syncthreads();
    }
#undef ISSUE

#pragma unroll
    for (int m = 0; m < 4; m++) {
        int rg = row0 + warpM * 64 + m * 16 + g;
#pragma unroll
        for (int n = 0; n < 4; n++) {
            int col = col0 + warpN * 32 + n * 8 + tig * 2;
            float b0 = __ldg(&bias[col]), b1 = __ldg(&bias[col + 1]);
            float2 o;
            o.x = alpha * (acc[m][n][0] + b0);
            o.y = alpha * (acc[m][n][1] + b1);
            *reinterpret_cast<float2*>(&Cout[(size_t)rg * CC + col]) = o;
            o.x = alpha * (acc[m][n][2] + b0);
            o.y = alpha * (acc[m][n][3] + b1);
            *reinterpret_cast<float2*>(&Cout[(size_t)(rg + 8) * CC + col]) = o;
        }
    }
}

__global__ void __launch_bounds__(256, 2) proj3_mma(const float* __restrict__ bin) {
    const int z = blockIdx.z;
    const uint32_t* Ahz = (z == 0) ? g_bQh : (z == 1) ? g_bKh : g_bVh;
    const uint32_t* Alz = (z == 0) ? g_bQl : (z == 1) ? g_bKl : g_bVl;
    float* Cz = (z == 0) ? g_q : (z == 1) ? g_k : g_v;
    const float alpha = (z == 0) ? 0.125f : 1.0f;
    gemm_bf16_body(Ahz, Alz,
                   g_bWih + (size_t)z * (CC * CC / 2),
                   g_bWil + (size_t)z * (CC * CC / 2),
                   bin + z * CC, Cz, alpha);
}

__global__ void __launch_bounds__(256, 2) outproj_mma(
    const float* __restrict__ bout, float* __restrict__ out) {
    gemm_bf16_body(g_bAh, g_bAl, g_bWoh, g_bWol, bout, out, 1.0f);
}

// ===========================================================================
// Batch/head-sliced smem attention. CTA = (head, batch), 512 threads.
// Phase 1: K-slice [512 x 64] in smem (68-float padded rows) -> scores,
//          softmax, weights to g_w.
// Phase 2: V-slice in same smem -> weighted sum -> split-bf16 output.
// ===========================================================================
#define KROW 68                                 // padded row (floats)
#define ATTN_SMEM (512 * KROW * 4)              // 139,264 B

__global__ void __launch_bounds__(512) attn_sliced(
    const int* __restrict__ index_pair)
{
    extern __shared__ float sk[];
    const int h = blockIdx.x, b = blockIdx.y;
    const int t = threadIdx.x, warp = t >> 5, lane = t & 31;
    const int ks = g_key_start[b];
    const int l_oct = lane & 7, dq = lane >> 3;

    // ---- load K slice ----
    {
        int seg = t & 7;
#pragma unroll
        for (int p = 0; p < 8; p++) {
            int row = (t >> 3) + p * 64;
            const float4* src = reinterpret_cast<const float4*>(
                &g_k[(size_t)(ks + row) * CC + h * DD + seg * 8]);
            float4 v0 = src[0], v1 = src[1];
            *reinterpret_cast<float4*>(&sk[row * KROW + seg * 8])     = v0;
            *reinterpret_cast<float4*>(&sk[row * KROW + seg * 8 + 4]) = v1;
        }
    }
    __syncthreads();

    // ---- phase 1: scores + softmax ----
#pragma unroll 1
    for (int j = 0; j < 32; j++) {
        const int qi = warp + 16 * j;
        const int n = b * 512 + qi;
        const float* qbase = &g_q[(size_t)n * CC + h * DD + dq * 16];
        float4 qv0 = *reinterpret_cast<const float4*>(qbase);
        float4 qv1 = *reinterpret_cast<const float4*>(qbase + 4);
        float4 qv2 = *reinterpret_cast<const float4*>(qbase + 8);
        float4 qv3 = *reinterpret_cast<const float4*>(qbase + 12);

        float sc[8];
#pragma unroll
        for (int p = 0; p < 8; p++) {
            int l = p * 8 + l_oct;
            int raw = __ldg(&index_pair[n * LL + l]);
            int row = (raw >= 0) ? raw : 0;
            const float4* kr = reinterpret_cast<const float4*>(&sk[row * KROW + dq * 16]);
            float4 k0 = kr[0], k1 = kr[1], k2 = kr[2], k3 = kr[3];
            float s = k0.x * qv0.x;
            s = fmaf(k0.y, qv0.y, s); s = fmaf(k0.z, qv0.z, s); s = fmaf(k0.w, qv0.w, s);
            s = fmaf(k1.x, qv1.x, s); s = fmaf(k1.y, qv1.y, s);
            s = fmaf(k1.z, qv1.z, s); s = fmaf(k1.w, qv1.w, s);
            s = fmaf(k2.x, qv2.x, s); s = fmaf(k2.y, qv2.y, s);
            s = fmaf(k2.z, qv2.z, s); s = fmaf(k2.w, qv2.w, s);
            s = fmaf(k3.x, qv3.x, s); s = fmaf(k3.y, qv3.y, s);
            s = fmaf(k3.z, qv3.z, s); s = fmaf(k3.w, qv3.w, s);
            s += __shfl_xor_sync(0xffffffffu, s, 8);
            s += __shfl_xor_sync(0xffffffffu, s, 16);
            sc[p] = (raw >= 0) ? s : -1000.0f;
        }

        float m = sc[0];
#pragma unroll
        for (int p = 1; p < 8; p++) m = fmaxf(m, sc[p]);
        m = fmaxf(m, __shfl_xor_sync(0xffffffffu, m, 1));
        m = fmaxf(m, __shfl_xor_sync(0xffffffffu, m, 2));
        m = fmaxf(m, __shfl_xor_sync(0xffffffffu, m, 4));
        float sum = 0.0f;
#pragma unroll
        for (int p = 0; p < 8; p++) { sc[p] = __expf(sc[p] - m); sum += sc[p]; }
        sum += __shfl_xor_sync(0xffffffffu, sum, 1);
        sum += __shfl_xor_sync(0xffffffffu, sum, 2);
        sum += __shfl_xor_sync(0xffffffffu, sum, 4);
        float inv = 1.0f / sum;
        if (dq == 0) {
            float* wdst = &g_w[(size_t)h * (NQ * LL) + (size_t)n * LL];
#pragma unroll
            for (int p = 0; p < 8; p++)
                wdst[p * 8 + l_oct] = sc[p] * inv;
        }
    }
    __syncthreads();

    // ---- load V slice (overwrite K) ----
    {
        int seg = t & 7;
#pragma unroll
        for (int p = 0; p < 8; p++) {
            int row = (t >> 3) + p * 64;
            const float4* src = reinterpret_cast<const float4*>(
                &g_v[(size_t)(ks + row) * CC + h * DD + seg * 8]);
            float4 v0 = src[0], v1 = src[1];
            *reinterpret_cast<float4*>(&sk[row * KROW + seg * 8])     = v0;
            *reinterpret_cast<float4*>(&sk[row * KROW + seg * 8 + 4]) = v1;
        }
    }
    __syncthreads();

    // ---- phase 2: weighted sum ----
#pragma unroll 1
    for (int j = 0; j < 32; j++) {
        const int qi = warp + 16 * j;
        const int n = b * 512 + qi;
        float2 wv = *reinterpret_cast<const float2*>(
            &g_w[(size_t)h * (NQ * LL) + (size_t)n * LL + lane * 2]);
        int2 iv = *reinterpret_cast<const int2*>(&index_pair[n * LL + lane * 2]);
        iv.x = (iv.x >= 0) ? iv.x : 0;
        iv.y = (iv.y >= 0) ? iv.y : 0;

        float2 acc = make_float2(0.0f, 0.0f);
#pragma unroll
        for (int l = 0; l < 64; l++) {
            int src_lane = l >> 1;
            float wl  = __shfl_sync(0xffffffffu, (l & 1) ? wv.y : wv.x, src_lane);
            int   row = __shfl_sync(0xffffffffu, (l & 1) ? iv.y : iv.x, src_lane);
            float2 vv = *reinterpret_cast<const float2*>(&sk[row * KROW + lane * 2]);
            acc.x = fmaf(wl, vv.x, acc.x);
            acc.y = fmaf(wl, vv.y, acc.y);
        }
        uint32_t hh = packbf(acc.x, acc.y);
        uint32_t ll = packbf(acc.x - bflo(hh), acc.y - bfhi(hh));
        size_t o2 = ((size_t)n * CC + h * DD + lane * 2) >> 1;
        g_bAh[o2] = hh;
        g_bAl[o2] = ll;
    }
}

// aux[n,l] = mean over heads of w
__global__ void __launch_bounds__(256) aux_kernel(float* __restrict__ aux_out) {
    int i = blockIdx.x * 256 + threadIdx.x;
    float s = 0.0f;
#pragma unroll
    for (int h = 0; h < HH; h++) s += g_w[(size_t)h * (NQ * LL) + i];
    aux_out[i] = s * 0.125f;
}

// ---------------------------------------------------------------------------
extern "C" void kernel_launch(void* const* d_in, const int* in_sizes, int n_in,
                              void* d_out, int out_size) {
    const float* query  = (const float*)d_in[0];
    const float* key    = (const float*)d_in[1];
    const float* value  = (const float*)d_in[2];
    const float* Win    = (const float*)d_in[3];
    const float* bin    = (const float*)d_in[4];
    const float* Wout   = (const float*)d_in[5];
    const float* bout   = (const float*)d_in[6];
    const int*   index_pair       = (const int*)d_in[7];
    const int*   key_batch_cnt    = (const int*)d_in[9];
    float* out = (float*)d_out;

    float* auxs;
    cudaGetSymbolAddress((void**)&auxs, g_aux_scratch);
    float* aux_out = (out_size >= NQ * CC + NQ * LL) ? (out + (size_t)NQ * CC) : auxs;

    uint32_t *bWih, *bWil, *bWoh, *bWol;
    cudaGetSymbolAddress((void**)&bWih, g_bWih); cudaGetSymbolAddress((void**)&bWil, g_bWil);
    cudaGetSymbolAddress((void**)&bWoh, g_bWoh); cudaGetSymbolAddress((void**)&bWol, g_bWol);

    cudaFuncSetAttribute(proj3_mma,   cudaFuncAttributeMaxDynamicSharedMemorySize, DSMEM_SIZE);
    cudaFuncSetAttribute(outproj_mma, cudaFuncAttributeMaxDynamicSharedMemorySize, DSMEM_SIZE);
    cudaFuncSetAttribute(attn_sliced, cudaFuncAttributeMaxDynamicSharedMemorySize, ATTN_SMEM);

    key_start_kernel<<<1, 32>>>(key_batch_cnt);

    dim3 gcvt(NQ * CC / 4 / 256, 3);
    cvt3_kernel<<<gcvt, 256>>>((const float4*)query, (const float4*)key,
                               (const float4*)value);
    cvt_split_kernel<<<3 * CC * CC / 4 / 256, 256>>>(
        (const float4*)Win, (uint2*)bWih, (uint2*)bWil, 3 * CC * CC / 4);
    cvt_split_kernel<<<CC * CC / 4 / 256, 256>>>(
        (const float4*)Wout, (uint2*)bWoh, (uint2*)bWol, CC * CC / 4);

    dim3 gproj(CC / 128, NQ / 128, 3);
    proj3_mma<<<gproj, 256, DSMEM_SIZE>>>(bin);

    dim3 gattn(HH, BB);
    attn_sliced<<<gattn, 512, ATTN_SMEM>>>(index_pair);

    aux_kernel<<<NQ * LL / 256, 256>>>(aux_out);

    dim3 gout(CC / 128, NQ / 128);
    outproj_mma<<<gout, 256, DSMEM_SIZE>>>(bout, out);
}

// round 9
// speedup vs baseline: 1.0437x; 1.0437x over previous
#include <cuda_runtime.h>
#include <cstdint>

#define NQ 8192
#define MK 8192
#define BB 16
#define CC 512
#define LL 64
#define HH 8
#define DD 64

// fp32 intermediates
__device__ float g_q[NQ * CC];
__device__ float g_k[MK * CC];
__device__ float g_v[MK * CC];
__device__ float g_S[(size_t)BB * HH * 512 * 512];   // dense scores, 128 MB
__device__ float g_w[HH * NQ * LL];                  // softmax weights (16 MB)
__device__ float g_aux_scratch[NQ * LL];
__device__ float g_zero[512];                        // zero bias (static zero-init)
__device__ int   g_key_start[BB];

// bf16 split operands (hi/lo), packed 2 elements per uint32.
// g_bQ*/g_bK* first hold the raw inputs (projection A operands), then are
// overwritten with the PROJECTED q/k for the score GEMM.
__device__ uint32_t g_bQh[NQ * CC / 2], g_bQl[NQ * CC / 2];
__device__ uint32_t g_bKh[MK * CC / 2], g_bKl[MK * CC / 2];
__device__ uint32_t g_bVh[MK * CC / 2], g_bVl[MK * CC / 2];
__device__ uint32_t g_bWih[3 * CC * CC / 2], g_bWil[3 * CC * CC / 2];
__device__ uint32_t g_bWoh[CC * CC / 2],     g_bWol[CC * CC / 2];
__device__ uint32_t g_bAh[NQ * CC / 2],      g_bAl[NQ * CC / 2];

// ---------------------------------------------------------------------------
static __device__ __forceinline__ uint32_t smem_u32(const void* p) {
    uint32_t a;
    asm("{ .reg .u64 t; cvta.to.shared.u64 t, %1; cvt.u32.u64 %0, t; }" : "=r"(a) : "l"(p));
    return a;
}
static __device__ __forceinline__ uint32_t packbf(float f0, float f1) {
    uint32_t r;
    asm("cvt.rn.bf16x2.f32 %0, %1, %2;" : "=r"(r) : "f"(f1), "f"(f0));
    return r;
}
static __device__ __forceinline__ float bflo(uint32_t r) { return __uint_as_float(r << 16); }
static __device__ __forceinline__ float bfhi(uint32_t r) { return __uint_as_float(r & 0xffff0000u); }
static __device__ __forceinline__ uint32_t lds32(uint32_t a) {
    uint32_t v; asm volatile("ld.shared.b32 %0, [%1];" : "=r"(v) : "r"(a)); return v;
}
static __device__ __forceinline__ void cpa16(uint32_t dst, const void* src) {
    asm volatile("cp.async.cg.shared.global [%0], [%1], 16;" :: "r"(dst), "l"(src) : "memory");
}
#define CP_COMMIT asm volatile("cp.async.commit_group;" ::: "memory")
#define CP_WAIT1  asm volatile("cp.async.wait_group 1;" ::: "memory")
#define CP_WAIT0  asm volatile("cp.async.wait_group 0;" ::: "memory")

#define MMA_BF16(c, a0, a1, a2, a3, b0, b1)                                   \
    asm volatile(                                                             \
        "mma.sync.aligned.m16n8k16.row.col.f32.bf16.bf16.f32 "                \
        "{%0,%1,%2,%3},{%4,%5,%6,%7},{%8,%9},{%0,%1,%2,%3};"                  \
        : "+f"((c)[0]), "+f"((c)[1]), "+f"((c)[2]), "+f"((c)[3])              \
        : "r"(a0), "r"(a1), "r"(a2), "r"(a3), "r"(b0), "r"(b1))

// ---------------------------------------------------------------------------
__global__ void key_start_kernel(const int* __restrict__ key_batch_cnt) {
    if (threadIdx.x == 0) {
        int s = 0;
        for (int b = 0; b < BB; b++) { g_key_start[b] = s; s += key_batch_cnt[b]; }
    }
}

// fp32 -> (bf16 hi, bf16 lo) split; blockIdx.y selects q/k/v
__global__ void __launch_bounds__(256) cvt3_kernel(
    const float4* __restrict__ q, const float4* __restrict__ k,
    const float4* __restrict__ v)
{
    const int z = blockIdx.y;
    const float4* src = (z == 0) ? q : (z == 1) ? k : v;
    uint2* hi = (uint2*)((z == 0) ? g_bQh : (z == 1) ? g_bKh : g_bVh);
    uint2* lo = (uint2*)((z == 0) ? g_bQl : (z == 1) ? g_bKl : g_bVl);
    int i = blockIdx.x * blockDim.x + threadIdx.x;
    float4 f = src[i];
    uint32_t h0 = packbf(f.x, f.y);
    uint32_t h1 = packbf(f.z, f.w);
    uint32_t l0 = packbf(f.x - bflo(h0), f.y - bfhi(h0));
    uint32_t l1 = packbf(f.z - bflo(h1), f.w - bfhi(h1));
    hi[i] = make_uint2(h0, h1);
    lo[i] = make_uint2(l0, l1);
}

// projected q/k -> split bf16 (overwrites the dead input arrays)
__global__ void __launch_bounds__(256) cvt_qk_kernel() {
    const int z = blockIdx.y;
    const float4* src = (const float4*)((z == 0) ? g_q : g_k);
    uint2* hi = (uint2*)((z == 0) ? g_bQh : g_bKh);
    uint2* lo = (uint2*)((z == 0) ? g_bQl : g_bKl);
    int i = blockIdx.x * blockDim.x + threadIdx.x;
    float4 f = src[i];
    uint32_t h0 = packbf(f.x, f.y);
    uint32_t h1 = packbf(f.z, f.w);
    uint32_t l0 = packbf(f.x - bflo(h0), f.y - bfhi(h0));
    uint32_t l1 = packbf(f.z - bflo(h1), f.w - bfhi(h1));
    hi[i] = make_uint2(h0, h1);
    lo[i] = make_uint2(l0, l1);
}

__global__ void __launch_bounds__(256) cvt_split_kernel(
    const float4* __restrict__ src, uint2* __restrict__ hi, uint2* __restrict__ lo, int n4)
{
    int i = blockIdx.x * blockDim.x + threadIdx.x;
    if (i >= n4) return;
    float4 f = src[i];
    uint32_t h0 = packbf(f.x, f.y);
    uint32_t h1 = packbf(f.z, f.w);
    uint32_t l0 = packbf(f.x - bflo(h0), f.y - bfhi(h0));
    uint32_t l1 = packbf(f.z - bflo(h1), f.w - bfhi(h1));
    hi[i] = make_uint2(h0, h1);
    lo[i] = make_uint2(l0, l1);
}

// ===========================================================================
// Split-bf16 HMMA GEMM body (proven). NT = number of 32-float k-stages.
// ===========================================================================
#define SROWB 80
#define TILE_B (128 * SROWB)
#define STAGE_B (4 * TILE_B)
#define DSMEM_SIZE (2 * STAGE_B)

__device__ __forceinline__ void gemm_bf16_body(
    const uint32_t* __restrict__ Ah, const uint32_t* __restrict__ Al,
    const uint32_t* __restrict__ Bh, const uint32_t* __restrict__ Bl,
    const float* __restrict__ bias, float* __restrict__ Cout, float alpha,
    int NT)
{
    extern __shared__ char dsm[];
    const uint32_t sbase = smem_u32(dsm);

    const int t = threadIdx.x;
    const int lane = t & 31, warp = t >> 5;
    const int g = lane >> 2, tig = lane & 3;
    const int warpM = warp & 1, warpN = warp >> 1;
    const int row0 = blockIdx.y * 128, col0 = blockIdx.x * 128;

    const int crow = t >> 1, chalf = t & 1;
    const uint32_t dstoff = (uint32_t)(crow * SROWB + chalf * 32);
    const size_t srcAbase = (size_t)(row0 + crow) * (CC / 2) + chalf * 8;
    const size_t srcBbase = (size_t)(col0 + crow) * (CC / 2) + chalf * 8;

    float acc[4][4][4];
#pragma unroll
    for (int m = 0; m < 4; m++)
#pragma unroll
        for (int n = 0; n < 4; n++)
#pragma unroll
            for (int j = 0; j < 4; j++) acc[m][n][j] = 0.0f;

#define ISSUE(kt, buf)                                                         \
    do {                                                                       \
        uint32_t sb = sbase + (buf) * STAGE_B;                                 \
        size_t ksrc = (size_t)(kt) * 16;                                       \
        cpa16(sb + dstoff,                  Ah + srcAbase + ksrc);             \
        cpa16(sb + dstoff + 16,             Ah + srcAbase + ksrc + 4);         \
        cpa16(sb + TILE_B + dstoff,         Al + srcAbase + ksrc);             \
        cpa16(sb + TILE_B + dstoff + 16,    Al + srcAbase + ksrc + 4);         \
        cpa16(sb + 2*TILE_B + dstoff,       Bh + srcBbase + ksrc);             \
        cpa16(sb + 2*TILE_B + dstoff + 16,  Bh + srcBbase + ksrc + 4);         \
        cpa16(sb + 3*TILE_B + dstoff,       Bl + srcBbase + ksrc);             \
        cpa16(sb + 3*TILE_B + dstoff + 16,  Bl + srcBbase + ksrc + 4);         \
    } while (0)

    ISSUE(0, 0);
    CP_COMMIT;

    for (int kt = 0; kt < NT; kt++) {
        if (kt + 1 < NT) {
            ISSUE(kt + 1, (kt + 1) & 1);
            CP_COMMIT;
            CP_WAIT1;
        } else {
            CP_WAIT0;
        }
        __syncthreads();

        const uint32_t ab = sbase + (kt & 1) * STAGE_B;
#pragma unroll
        for (int sub = 0; sub < 2; sub++) {
            const uint32_t koff = sub * 32;
            uint32_t af[4][4];

#pragma unroll
            for (int m = 0; m < 4; m++) {
                uint32_t ro = ab + (uint32_t)((warpM * 64 + m * 16 + g) * SROWB) + koff + tig * 4;
                af[m][0] = lds32(ro);
                af[m][1] = lds32(ro + 8 * SROWB);
                af[m][2] = lds32(ro + 16);
                af[m][3] = lds32(ro + 8 * SROWB + 16);
            }
#pragma unroll
            for (int n = 0; n < 4; n++) {
                uint32_t bo = ab + 2 * TILE_B +
                    (uint32_t)((warpN * 32 + n * 8 + g) * SROWB) + koff + tig * 4;
                uint32_t bh0 = lds32(bo), bh1 = lds32(bo + 16);
                uint32_t bl0 = lds32(bo + TILE_B), bl1 = lds32(bo + TILE_B + 16);
#pragma unroll
                for (int m = 0; m < 4; m++) {
                    MMA_BF16(acc[m][n], af[m][0], af[m][1], af[m][2], af[m][3], bh0, bh1);
                    MMA_BF16(acc[m][n], af[m][0], af[m][1], af[m][2], af[m][3], bl0, bl1);
                }
            }

#pragma unroll
            for (int m = 0; m < 4; m++) {
                uint32_t ro = ab + TILE_B +
                    (uint32_t)((warpM * 64 + m * 16 + g) * SROWB) + koff + tig * 4;
                af[m][0] = lds32(ro);
                af[m][1] = lds32(ro + 8 * SROWB);
                af[m][2] = lds32(ro + 16);
                af[m][3] = lds32(ro + 8 * SROWB + 16);
            }
#pragma unroll
            for (int n = 0; n < 4; n++) {
                uint32_t bo = ab + 2 * TILE_B +
                    (uint32_t)((warpN * 32 + n * 8 + g) * SROWB) + koff + tig * 4;
                uint32_t bh0 = lds32(bo), bh1 = lds32(bo + 16);
#pragma unroll
                for (int m = 0; m < 4; m++)
                    MMA_BF16(acc[m][n], af[m][0], af[m][1], af[m][2], af[m][3], bh0, bh1);
            }
        }
        __syncthreads();
    }
#undef ISSUE

#pragma unroll
    for (int m = 0; m < 4; m++) {
        int rg = row0 + warpM * 64 + m * 16 + g;
#pragma unroll
        for (int n = 0; n < 4; n++) {
            int col = col0 + warpN * 32 + n * 8 + tig * 2;
            float b0 = __ldg(&bias[col]), b1 = __ldg(&bias[col + 1]);
            float2 o;
            o.x = alpha * (acc[m][n][0] + b0);
            o.y = alpha * (acc[m][n][1] + b1);
            *reinterpret_cast<float2*>(&Cout[(size_t)rg * CC + col]) = o;
            o.x = alpha * (acc[m][n][2] + b0);
            o.y = alpha * (acc[m][n][3] + b1);
            *reinterpret_cast<float2*>(&Cout[(size_t)(rg + 8) * CC + col]) = o;
        }
    }
}

__global__ void __launch_bounds__(256, 2) proj3_mma(const float* __restrict__ bin) {
    const int z = blockIdx.z;
    const uint32_t* Ahz = (z == 0) ? g_bQh : (z == 1) ? g_bKh : g_bVh;
    const uint32_t* Alz = (z == 0) ? g_bQl : (z == 1) ? g_bKl : g_bVl;
    float* Cz = (z == 0) ? g_q : (z == 1) ? g_k : g_v;
    const float alpha = (z == 0) ? 0.125f : 1.0f;
    gemm_bf16_body(Ahz, Alz,
                   g_bWih + (size_t)z * (CC * CC / 2),
                   g_bWil + (size_t)z * (CC * CC / 2),
                   bin + z * CC, Cz, alpha, CC / 32);
}

__global__ void __launch_bounds__(256, 2) outproj_mma(
    const float* __restrict__ bout, float* __restrict__ out) {
    gemm_bf16_body(g_bAh, g_bAl, g_bWoh, g_bWol, bout, out, 1.0f, CC / 32);
}

// Dense scores per (batch, head): S = q_slice @ k_slice^T, 512x512, Kdim=64.
// Consumes the PROJECTED q/k (re-split to bf16 by cvt_qk_kernel).
// grid = (4, 4, 128): x = key tile, y = query tile, z = b*8+h.
__global__ void __launch_bounds__(256, 2) score_mma() {
    const int z = blockIdx.z;
    const int b = z >> 3, h = z & 7;
    const int ks = g_key_start[b];
    const size_t qoff = (size_t)(b * 512) * (CC / 2) + h * 32;
    const size_t koff = (size_t)ks * (CC / 2) + h * 32;
    float* Sout = g_S + (size_t)z * 512 * 512;
    gemm_bf16_body(g_bQh + qoff, g_bQl + qoff,
                   g_bKh + koff, g_bKl + koff,
                   g_zero, Sout, 1.0f, 2);
}

// ===========================================================================
// Softmax over gathered scores. Block = query n (256 thr); warp w = head w.
// ===========================================================================
__global__ void __launch_bounds__(256) softmax_kernel(
    const int* __restrict__ index_pair,
    const int* __restrict__ index_pair_batch,
    float* __restrict__ aux_out)
{
    __shared__ float saux[HH][LL];
    const int n = blockIdx.x;
    const int h = threadIdx.x >> 5, lane = threadIdx.x & 31;
    const int b = index_pair_batch[n];
    const int qi = n - b * 512;
    const float* Srow = &g_S[((size_t)(b * 8 + h) * 512 + qi) * 512];

    int2 iv = *reinterpret_cast<const int2*>(&index_pair[n * LL + lane * 2]);
    float s0 = (iv.x >= 0) ? __ldg(&Srow[iv.x]) : -1000.0f;
    float s1 = (iv.y >= 0) ? __ldg(&Srow[iv.y]) : -1000.0f;

    float m = fmaxf(s0, s1);
#pragma unroll
    for (int off = 16; off; off >>= 1)
        m = fmaxf(m, __shfl_xor_sync(0xffffffffu, m, off));
    s0 = __expf(s0 - m);
    s1 = __expf(s1 - m);
    float sum = s0 + s1;
#pragma unroll
    for (int off = 16; off; off >>= 1)
        sum += __shfl_xor_sync(0xffffffffu, sum, off);
    float inv = 1.0f / sum;
    s0 *= inv; s1 *= inv;

    *reinterpret_cast<float2*>(
        &g_w[((size_t)h * NQ + n) * LL + lane * 2]) = make_float2(s0, s1);
    saux[h][lane * 2]     = s0;
    saux[h][lane * 2 + 1] = s1;
    __syncthreads();

    if (threadIdx.x < LL) {
        float s = 0.0f;
#pragma unroll
        for (int hh = 0; hh < HH; hh++) s += saux[hh][threadIdx.x];
        aux_out[(size_t)n * LL + threadIdx.x] = s * 0.125f;
    }
}

// ===========================================================================
// Weighted-V from smem slice (conflict-free broadcast reads).
// ===========================================================================
#define KROW 68
#define ATTN_SMEM (512 * KROW * 4)

__global__ void __launch_bounds__(512) wv_kernel(const int* __restrict__ index_pair)
{
    extern __shared__ float sk[];
    const int h = blockIdx.x, b = blockIdx.y;
    const int t = threadIdx.x, warp = t >> 5, lane = t & 31;
    const int ks = g_key_start[b];

    {
        int seg = t & 7;
#pragma unroll
        for (int p = 0; p < 8; p++) {
            int row = (t >> 3) + p * 64;
            const float4* src = reinterpret_cast<const float4*>(
                &g_v[(size_t)(ks + row) * CC + h * DD + seg * 8]);
            float4 v0 = src[0], v1 = src[1];
            *reinterpret_cast<float4*>(&sk[row * KROW + seg * 8])     = v0;
            *reinterpret_cast<float4*>(&sk[row * KROW + seg * 8 + 4]) = v1;
        }
    }
    __syncthreads();

#pragma unroll 1
    for (int j = 0; j < 32; j++) {
        const int qi = warp + 16 * j;
        const int n = b * 512 + qi;
        float2 wv = *reinterpret_cast<const float2*>(
            &g_w[((size_t)h * NQ + n) * LL + lane * 2]);
        int2 iv = *reinterpret_cast<const int2*>(&index_pair[n * LL + lane * 2]);
        iv.x = (iv.x >= 0) ? iv.x : 0;
        iv.y = (iv.y >= 0) ? iv.y : 0;

        float2 acc = make_float2(0.0f, 0.0f);
#pragma unroll
        for (int l = 0; l < 64; l++) {
            int src_lane = l >> 1;
            float wl  = __shfl_sync(0xffffffffu, (l & 1) ? wv.y : wv.x, src_lane);
            int   row = __shfl_sync(0xffffffffu, (l & 1) ? iv.y : iv.x, src_lane);
            float2 vv = *reinterpret_cast<const float2*>(&sk[row * KROW + lane * 2]);
            acc.x = fmaf(wl, vv.x, acc.x);
            acc.y = fmaf(wl, vv.y, acc.y);
        }
        uint32_t hh = packbf(acc.x, acc.y);
        uint32_t ll = packbf(acc.x - bflo(hh), acc.y - bfhi(hh));
        size_t o2 = ((size_t)n * CC + h * DD + lane * 2) >> 1;
        g_bAh[o2] = hh;
        g_bAl[o2] = ll;
    }
}

// ---------------------------------------------------------------------------
extern "C" void kernel_launch(void* const* d_in, const int* in_sizes, int n_in,
                              void* d_out, int out_size) {
    const float* query  = (const float*)d_in[0];
    const float* key    = (const float*)d_in[1];
    const float* value  = (const float*)d_in[2];
    const float* Win    = (const float*)d_in[3];
    const float* bin    = (const float*)d_in[4];
    const float* Wout   = (const float*)d_in[5];
    const float* bout   = (const float*)d_in[6];
    const int*   index_pair       = (const int*)d_in[7];
    const int*   key_batch_cnt    = (const int*)d_in[9];
    const int*   index_pair_batch = (const int*)d_in[10];
    float* out = (float*)d_out;

    float* auxs;
    cudaGetSymbolAddress((void**)&auxs, g_aux_scratch);
    float* aux_out = (out_size >= NQ * CC + NQ * LL) ? (out + (size_t)NQ * CC) : auxs;

    uint32_t *bWih, *bWil, *bWoh, *bWol;
    cudaGetSymbolAddress((void**)&bWih, g_bWih); cudaGetSymbolAddress((void**)&bWil, g_bWil);
    cudaGetSymbolAddress((void**)&bWoh, g_bWoh); cudaGetSymbolAddress((void**)&bWol, g_bWol);

    cudaFuncSetAttribute(proj3_mma,   cudaFuncAttributeMaxDynamicSharedMemorySize, DSMEM_SIZE);
    cudaFuncSetAttribute(outproj_mma, cudaFuncAttributeMaxDynamicSharedMemorySize, DSMEM_SIZE);
    cudaFuncSetAttribute(score_mma,   cudaFuncAttributeMaxDynamicSharedMemorySize, DSMEM_SIZE);
    cudaFuncSetAttribute(wv_kernel,   cudaFuncAttributeMaxDynamicSharedMemorySize, ATTN_SMEM);

    key_start_kernel<<<1, 32>>>(key_batch_cnt);

    // raw inputs -> split bf16 (projection operands)
    dim3 gcvt(NQ * CC / 4 / 256, 3);
    cvt3_kernel<<<gcvt, 256>>>((const float4*)query, (const float4*)key,
                               (const float4*)value);
    cvt_split_kernel<<<3 * CC * CC / 4 / 256, 256>>>(
        (const float4*)Win, (uint2*)bWih, (uint2*)bWil, 3 * CC * CC / 4);
    cvt_split_kernel<<<CC * CC / 4 / 256, 256>>>(
        (const float4*)Wout, (uint2*)bWoh, (uint2*)bWol, CC * CC / 4);

    // projections (q scaled by 0.125)
    dim3 gproj(CC / 128, NQ / 128, 3);
    proj3_mma<<<gproj, 256, DSMEM_SIZE>>>(bin);

    // PROJECTED q/k -> split bf16 (overwrites dead input arrays)
    dim3 gqk(NQ * CC / 4 / 256, 2);
    cvt_qk_kernel<<<gqk, 256>>>();

    // dense scores, gather-softmax (+aux), smem weighted-V
    dim3 gscore(4, 4, BB * HH);
    score_mma<<<gscore, 256, DSMEM_SIZE>>>();

    softmax_kernel<<<NQ, 256>>>(index_pair, index_pair_batch, aux_out);

    dim3 gwv(HH, BB);
    wv_kernel<<<gwv, 512, ATTN_SMEM>>>(index_pair);

    dim3 gout(CC / 128, NQ / 128);
    outproj_mma<<<gout, 256, DSMEM_SIZE>>>(bout, out);
}

// round 10
// speedup vs baseline: 1.0895x; 1.0439x over previous
#include <cuda_runtime.h>
#include <cstdint>

#define NQ 8192
#define MK 8192
#define BB 16
#define CC 512
#define LL 64
#define HH 8
#define DD 64

// fp32 intermediates
__device__ float g_q[NQ * CC];
__device__ float g_k[MK * CC];
__device__ float g_v[MK * CC];
__device__ float g_w[HH * NQ * LL];     // softmax weights scratch (16 MB)
__device__ float g_aux_scratch[NQ * LL];
__device__ int   g_key_start[BB];

// bf16 split operands (hi/lo), packed 2 elements per uint32
__device__ uint32_t g_bQh[NQ * CC / 2], g_bQl[NQ * CC / 2];
__device__ uint32_t g_bKh[MK * CC / 2], g_bKl[MK * CC / 2];
__device__ uint32_t g_bVh[MK * CC / 2], g_bVl[MK * CC / 2];
__device__ uint32_t g_bWih[3 * CC * CC / 2], g_bWil[3 * CC * CC / 2];
__device__ uint32_t g_bWoh[CC * CC / 2],     g_bWol[CC * CC / 2];
__device__ uint32_t g_bAh[NQ * CC / 2],      g_bAl[NQ * CC / 2];

// ---------------------------------------------------------------------------
static __device__ __forceinline__ uint32_t smem_u32(const void* p) {
    uint32_t a;
    asm("{ .reg .u64 t; cvta.to.shared.u64 t, %1; cvt.u32.u64 %0, t; }" : "=r"(a) : "l"(p));
    return a;
}
static __device__ __forceinline__ uint32_t packbf(float f0, float f1) {
    uint32_t r;
    asm("cvt.rn.bf16x2.f32 %0, %1, %2;" : "=r"(r) : "f"(f1), "f"(f0));
    return r;
}
static __device__ __forceinline__ float bflo(uint32_t r) { return __uint_as_float(r << 16); }
static __device__ __forceinline__ float bfhi(uint32_t r) { return __uint_as_float(r & 0xffff0000u); }
static __device__ __forceinline__ uint32_t lds32(uint32_t a) {
    uint32_t v; asm volatile("ld.shared.b32 %0, [%1];" : "=r"(v) : "r"(a)); return v;
}
static __device__ __forceinline__ void cpa16(uint32_t dst, const void* src) {
    asm volatile("cp.async.cg.shared.global [%0], [%1], 16;" :: "r"(dst), "l"(src) : "memory");
}
#define CP_COMMIT asm volatile("cp.async.commit_group;" ::: "memory")
#define CP_WAIT1  asm volatile("cp.async.wait_group 1;" ::: "memory")
#define CP_WAIT0  asm volatile("cp.async.wait_group 0;" ::: "memory")

#define MMA_BF16(c, a0, a1, a2, a3, b0, b1)                                   \
    asm volatile(                                                             \
        "mma.sync.aligned.m16n8k16.row.col.f32.bf16.bf16.f32 "                \
        "{%0,%1,%2,%3},{%4,%5,%6,%7},{%8,%9},{%0,%1,%2,%3};"                  \
        : "+f"((c)[0]), "+f"((c)[1]), "+f"((c)[2]), "+f"((c)[3])              \
        : "r"(a0), "r"(a1), "r"(a2), "r"(a3), "r"(b0), "r"(b1))

// ---------------------------------------------------------------------------
__global__ void key_start_kernel(const int* __restrict__ key_batch_cnt) {
    if (threadIdx.x == 0) {
        int s = 0;
        for (int b = 0; b < BB; b++) { g_key_start[b] = s; s += key_batch_cnt[b]; }
    }
}

// fp32 -> (bf16 hi, bf16 lo) split; blockIdx.y selects q/k/v
__global__ void __launch_bounds__(256) cvt3_kernel(
    const float4* __restrict__ q, const float4* __restrict__ k,
    const float4* __restrict__ v)
{
    const int z = blockIdx.y;
    const float4* src = (z == 0) ? q : (z == 1) ? k : v;
    uint2* hi = (uint2*)((z == 0) ? g_bQh : (z == 1) ? g_bKh : g_bVh);
    uint2* lo = (uint2*)((z == 0) ? g_bQl : (z == 1) ? g_bKl : g_bVl);
    int i = blockIdx.x * blockDim.x + threadIdx.x;
    float4 f = src[i];
    uint32_t h0 = packbf(f.x, f.y);
    uint32_t h1 = packbf(f.z, f.w);
    uint32_t l0 = packbf(f.x - bflo(h0), f.y - bfhi(h0));
    uint32_t l1 = packbf(f.z - bflo(h1), f.w - bfhi(h1));
    hi[i] = make_uint2(h0, h1);
    lo[i] = make_uint2(l0, l1);
}

__global__ void __launch_bounds__(256) cvt_split_kernel(
    const float4* __restrict__ src, uint2* __restrict__ hi, uint2* __restrict__ lo, int n4)
{
    int i = blockIdx.x * blockDim.x + threadIdx.x;
    if (i >= n4) return;
    float4 f = src[i];
    uint32_t h0 = packbf(f.x, f.y);
    uint32_t h1 = packbf(f.z, f.w);
    uint32_t l0 = packbf(f.x - bflo(h0), f.y - bfhi(h0));
    uint32_t l1 = packbf(f.z - bflo(h1), f.w - bfhi(h1));
    hi[i] = make_uint2(h0, h1);
    lo[i] = make_uint2(l0, l1);
}

// ===========================================================================
// Split-bf16 HMMA GEMM (unchanged, proven)
// ===========================================================================
#define SROWB 80
#define TILE_B (128 * SROWB)
#define STAGE_B (4 * TILE_B)
#define DSMEM_SIZE (2 * STAGE_B)

__device__ __forceinline__ void gemm_bf16_body(
    const uint32_t* __restrict__ Ah, const uint32_t* __restrict__ Al,
    const uint32_t* __restrict__ Bh, const uint32_t* __restrict__ Bl,
    const float* __restrict__ bias, float* __restrict__ Cout, float alpha)
{
    extern __shared__ char dsm[];
    const uint32_t sbase = smem_u32(dsm);

    const int t = threadIdx.x;
    const int lane = t & 31, warp = t >> 5;
    const int g = lane >> 2, tig = lane & 3;
    const int warpM = warp & 1, warpN = warp >> 1;
    const int row0 = blockIdx.y * 128, col0 = blockIdx.x * 128;

    const int crow = t >> 1, chalf = t & 1;
    const uint32_t dstoff = (uint32_t)(crow * SROWB + chalf * 32);
    const size_t srcAbase = (size_t)(row0 + crow) * (CC / 2) + chalf * 8;
    const size_t srcBbase = (size_t)(col0 + crow) * (CC / 2) + chalf * 8;

    float acc[4][4][4];
#pragma unroll
    for (int m = 0; m < 4; m++)
#pragma unroll
        for (int n = 0; n < 4; n++)
#pragma unroll
            for (int j = 0; j < 4; j++) acc[m][n][j] = 0.0f;

#define ISSUE(kt, buf)                                                         \
    do {                                                                       \
        uint32_t sb = sbase + (buf) * STAGE_B;                                 \
        size_t ksrc = (size_t)(kt) * 16;                                       \
        cpa16(sb + dstoff,                  Ah + srcAbase + ksrc);             \
        cpa16(sb + dstoff + 16,             Ah + srcAbase + ksrc + 4);         \
        cpa16(sb + TILE_B + dstoff,         Al + srcAbase + ksrc);             \
        cpa16(sb + TILE_B + dstoff + 16,    Al + srcAbase + ksrc + 4);         \
        cpa16(sb + 2*TILE_B + dstoff,       Bh + srcBbase + ksrc);             \
        cpa16(sb + 2*TILE_B + dstoff + 16,  Bh + srcBbase + ksrc + 4);         \
        cpa16(sb + 3*TILE_B + dstoff,       Bl + srcBbase + ksrc);             \
        cpa16(sb + 3*TILE_B + dstoff + 16,  Bl + srcBbase + ksrc + 4);         \
    } while (0)

    const int NT = CC / 32;
    ISSUE(0, 0);
    CP_COMMIT;

    for (int kt = 0; kt < NT; kt++) {
        if (kt + 1 < NT) {
            ISSUE(kt + 1, (kt + 1) & 1);
            CP_COMMIT;
            CP_WAIT1;
        } else {
            CP_WAIT0;
        }
        __syncthreads();

        const uint32_t ab = sbase + (kt & 1) * STAGE_B;
#pragma unroll
        for (int sub = 0; sub < 2; sub++) {
            const uint32_t koff = sub * 32;
            uint32_t af[4][4];

#pragma unroll
            for (int m = 0; m < 4; m++) {
                uint32_t ro = ab + (uint32_t)((warpM * 64 + m * 16 + g) * SROWB) + koff + tig * 4;
                af[m][0] = lds32(ro);
                af[m][1] = lds32(ro + 8 * SROWB);
                af[m][2] = lds32(ro + 16);
                af[m][3] = lds32(ro + 8 * SROWB + 16);
            }
#pragma unroll
            for (int n = 0; n < 4; n++) {
                uint32_t bo = ab + 2 * TILE_B +
                    (uint32_t)((warpN * 32 + n * 8 + g) * SROWB) + koff + tig * 4;
                uint32_t bh0 = lds32(bo), bh1 = lds32(bo + 16);
                uint32_t bl0 = lds32(bo + TILE_B), bl1 = lds32(bo + TILE_B + 16);
#pragma unroll
                for (int m = 0; m < 4; m++) {
                    MMA_BF16(acc[m][n], af[m][0], af[m][1], af[m][2], af[m][3], bh0, bh1);
                    MMA_BF16(acc[m][n], af[m][0], af[m][1], af[m][2], af[m][3], bl0, bl1);
                }
            }

#pragma unroll
            for (int m = 0; m < 4; m++) {
                uint32_t ro = ab + TILE_B +
                    (uint32_t)((warpM * 64 + m * 16 + g) * SROWB) + koff + tig * 4;
                af[m][0] = lds32(ro);
                af[m][1] = lds32(ro + 8 * SROWB);
                af[m][2] = lds32(ro + 16);
                af[m][3] = lds32(ro + 8 * SROWB + 16);
            }
#pragma unroll
            for (int n = 0; n < 4; n++) {
                uint32_t bo = ab + 2 * TILE_B +
                    (uint32_t)((warpN * 32 + n * 8 + g) * SROWB) + koff + tig * 4;
                uint32_t bh0 = lds32(bo), bh1 = lds32(bo + 16);
#pragma unroll
                for (int m = 0; m < 4; m++)
                    MMA_BF16(acc[m][n], af[m][0], af[m][1], af[m][2], af[m][3], bh0, bh1);
            }
        }
        __syncthreads();
    }
#undef ISSUE

#pragma unroll
    for (int m = 0; m < 4; m++) {
        int rg = row0 + warpM * 64 + m * 16 + g;
#pragma unroll
        for (int n = 0; n < 4; n++) {
            int col = col0 + warpN * 32 + n * 8 + tig * 2;
            float b0 = __ldg(&bias[col]), b1 = __ldg(&bias[col + 1]);
            float2 o;
            o.x = alpha * (acc[m][n][0] + b0);
            o.y = alpha * (acc[m][n][1] + b1);
            *reinterpret_cast<float2*>(&Cout[(size_t)rg * CC + col]) = o;
            o.x = alpha * (acc[m][n][2] + b0);
            o.y = alpha * (acc[m][n][3] + b1);
            *reinterpret_cast<float2*>(&Cout[(size_t)(rg + 8) * CC + col]) = o;
        }
    }
}

__global__ void __launch_bounds__(256, 2) proj3_mma(const float* __restrict__ bin) {
    const int z = blockIdx.z;
    const uint32_t* Ahz = (z == 0) ? g_bQh : (z == 1) ? g_bKh : g_bVh;
    const uint32_t* Alz = (z == 0) ? g_bQl : (z == 1) ? g_bKl : g_bVl;
    float* Cz = (z == 0) ? g_q : (z == 1) ? g_k : g_v;
    const float alpha = (z == 0) ? 0.125f : 1.0f;
    gemm_bf16_body(Ahz, Alz,
                   g_bWih + (size_t)z * (CC * CC / 2),
                   g_bWil + (size_t)z * (CC * CC / 2),
                   bin + z * CC, Cz, alpha);
}

__global__ void __launch_bounds__(256, 2) outproj_mma(
    const float* __restrict__ bout, float* __restrict__ out) {
    gemm_bf16_body(g_bAh, g_bAl, g_bWoh, g_bWol, bout, out, 1.0f);
}

// ===========================================================================
// Sliced attention v2. CTA = (head, batch), 512 threads.
// Phase 1: octet-broadcast gathered-row reads -> conflict-free LDS.128.
//   lane = (qtr = lane>>3, d_oct = lane&7); quarter qtr owns l = qtr*16+li;
//   octet shares row, lanes read chunks d_oct and d_oct+8:
//   start bank = 4*(row+d_oct) mod 32 -> distinct for any row.
// Phase 2: proven broadcast weighted-V.
// ===========================================================================
#define KROW 68
#define ATTN_SMEM (512 * KROW * 4)

__global__ void __launch_bounds__(512) attn2_kernel(const int* __restrict__ index_pair)
{
    extern __shared__ float sk[];
    const int h = blockIdx.x, b = blockIdx.y;
    const int t = threadIdx.x, warp = t >> 5, lane = t & 31;
    const int qtr = lane >> 3, d_oct = lane & 7;
    const int ks = g_key_start[b];

    // ---- stage K slice [512 x 64] ----
    {
        int seg = t & 7;
#pragma unroll
        for (int p = 0; p < 8; p++) {
            int row = (t >> 3) + p * 64;
            const float4* src = reinterpret_cast<const float4*>(
                &g_k[(size_t)(ks + row) * CC + h * DD + seg * 8]);
            float4 v0 = src[0], v1 = src[1];
            *reinterpret_cast<float4*>(&sk[row * KROW + seg * 8])     = v0;
            *reinterpret_cast<float4*>(&sk[row * KROW + seg * 8 + 4]) = v1;
        }
    }
    __syncthreads();

    // ---- phase 1: scores + softmax -> g_w ----
#pragma unroll 1
    for (int j = 0; j < 32; j++) {
        const int qi = warp + 16 * j;
        const int n = b * 512 + qi;
        int2 iv = *reinterpret_cast<const int2*>(&index_pair[n * LL + lane * 2]);
        const float* qb = &g_q[(size_t)n * CC + h * DD];
        float4 q0 = *reinterpret_cast<const float4*>(&qb[d_oct * 4]);
        float4 q1 = *reinterpret_cast<const float4*>(&qb[32 + d_oct * 4]);

        float sc[16];
#pragma unroll
        for (int li = 0; li < 16; li++) {
            int src = qtr * 8 + (li >> 1);
            int raw = __shfl_sync(0xffffffffu, (li & 1) ? iv.y : iv.x, src);
            int row = (raw >= 0) ? raw : 0;
            const float* kr = &sk[row * KROW];
            float4 k0 = *reinterpret_cast<const float4*>(&kr[d_oct * 4]);
            float4 k1 = *reinterpret_cast<const float4*>(&kr[32 + d_oct * 4]);
            float s = q0.x * k0.x;
            s = fmaf(q0.y, k0.y, s); s = fmaf(q0.z, k0.z, s); s = fmaf(q0.w, k0.w, s);
            s = fmaf(q1.x, k1.x, s); s = fmaf(q1.y, k1.y, s);
            s = fmaf(q1.z, k1.z, s); s = fmaf(q1.w, k1.w, s);
            s += __shfl_xor_sync(0xffffffffu, s, 1);
            s += __shfl_xor_sync(0xffffffffu, s, 2);
            s += __shfl_xor_sync(0xffffffffu, s, 4);
            sc[li] = (raw >= 0) ? s : -1000.0f;
        }

        float m = sc[0];
#pragma unroll
        for (int li = 1; li < 16; li++) m = fmaxf(m, sc[li]);
        m = fmaxf(m, __shfl_xor_sync(0xffffffffu, m, 8));
        m = fmaxf(m, __shfl_xor_sync(0xffffffffu, m, 16));
        float sum = 0.0f;
#pragma unroll
        for (int li = 0; li < 16; li++) { sc[li] = __expf(sc[li] - m); sum += sc[li]; }
        sum += __shfl_xor_sync(0xffffffffu, sum, 8);
        sum += __shfl_xor_sync(0xffffffffu, sum, 16);
        float inv = 1.0f / sum;

        float* wdst = &g_w[((size_t)h * NQ + n) * LL];
        wdst[qtr * 16 + d_oct]     = sc[d_oct] * inv;
        wdst[qtr * 16 + d_oct + 8] = sc[d_oct + 8] * inv;
    }
    __syncthreads();

    // ---- stage V slice (overwrite K) ----
    {
        int seg = t & 7;
#pragma unroll
        for (int p = 0; p < 8; p++) {
            int row = (t >> 3) + p * 64;
            const float4* src = reinterpret_cast<const float4*>(
                &g_v[(size_t)(ks + row) * CC + h * DD + seg * 8]);
            float4 v0 = src[0], v1 = src[1];
            *reinterpret_cast<float4*>(&sk[row * KROW + seg * 8])     = v0;
            *reinterpret_cast<float4*>(&sk[row * KROW + seg * 8 + 4]) = v1;
        }
    }
    __syncthreads();

    // ---- phase 2: weighted sum (proven broadcast pattern) ----
#pragma unroll 1
    for (int j = 0; j < 32; j++) {
        const int qi = warp + 16 * j;
        const int n = b * 512 + qi;
        float2 wv = *reinterpret_cast<const float2*>(
            &g_w[((size_t)h * NQ + n) * LL + lane * 2]);
        int2 iv = *reinterpret_cast<const int2*>(&index_pair[n * LL + lane * 2]);
        iv.x = (iv.x >= 0) ? iv.x : 0;
        iv.y = (iv.y >= 0) ? iv.y : 0;

        float2 acc = make_float2(0.0f, 0.0f);
#pragma unroll
        for (int l = 0; l < 64; l++) {
            int src_lane = l >> 1;
            float wl  = __shfl_sync(0xffffffffu, (l & 1) ? wv.y : wv.x, src_lane);
            int   row = __shfl_sync(0xffffffffu, (l & 1) ? iv.y : iv.x, src_lane);
            float2 vv = *reinterpret_cast<const float2*>(&sk[row * KROW + lane * 2]);
            acc.x = fmaf(wl, vv.x, acc.x);
            acc.y = fmaf(wl, vv.y, acc.y);
        }
        uint32_t hh = packbf(acc.x, acc.y);
        uint32_t ll = packbf(acc.x - bflo(hh), acc.y - bfhi(hh));
        size_t o2 = ((size_t)n * CC + h * DD + lane * 2) >> 1;
        g_bAh[o2] = hh;
        g_bAl[o2] = ll;
    }
}

// aux[n,l] = mean over heads of w
__global__ void __launch_bounds__(256) aux_kernel(float* __restrict__ aux_out) {
    int i = blockIdx.x * 256 + threadIdx.x;
    float s = 0.0f;
#pragma unroll
    for (int h = 0; h < HH; h++) s += g_w[(size_t)h * (NQ * LL) + i];
    aux_out[i] = s * 0.125f;
}

// ---------------------------------------------------------------------------
extern "C" void kernel_launch(void* const* d_in, const int* in_sizes, int n_in,
                              void* d_out, int out_size) {
    const float* query  = (const float*)d_in[0];
    const float* key    = (const float*)d_in[1];
    const float* value  = (const float*)d_in[2];
    const float* Win    = (const float*)d_in[3];
    const float* bin    = (const float*)d_in[4];
    const float* Wout   = (const float*)d_in[5];
    const float* bout   = (const float*)d_in[6];
    const int*   index_pair       = (const int*)d_in[7];
    const int*   key_batch_cnt    = (const int*)d_in[9];
    float* out = (float*)d_out;

    float* auxs;
    cudaGetSymbolAddress((void**)&auxs, g_aux_scratch);
    float* aux_out = (out_size >= NQ * CC + NQ * LL) ? (out + (size_t)NQ * CC) : auxs;

    uint32_t *bWih, *bWil, *bWoh, *bWol;
    cudaGetSymbolAddress((void**)&bWih, g_bWih); cudaGetSymbolAddress((void**)&bWil, g_bWil);
    cudaGetSymbolAddress((void**)&bWoh, g_bWoh); cudaGetSymbolAddress((void**)&bWol, g_bWol);

    cudaFuncSetAttribute(proj3_mma,    cudaFuncAttributeMaxDynamicSharedMemorySize, DSMEM_SIZE);
    cudaFuncSetAttribute(outproj_mma,  cudaFuncAttributeMaxDynamicSharedMemorySize, DSMEM_SIZE);
    cudaFuncSetAttribute(attn2_kernel, cudaFuncAttributeMaxDynamicSharedMemorySize, ATTN_SMEM);

    key_start_kernel<<<1, 32>>>(key_batch_cnt);

    dim3 gcvt(NQ * CC / 4 / 256, 3);
    cvt3_kernel<<<gcvt, 256>>>((const float4*)query, (const float4*)key,
                               (const float4*)value);
    cvt_split_kernel<<<3 * CC * CC / 4 / 256, 256>>>(
        (const float4*)Win, (uint2*)bWih, (uint2*)bWil, 3 * CC * CC / 4);
    cvt_split_kernel<<<CC * CC / 4 / 256, 256>>>(
        (const float4*)Wout, (uint2*)bWoh, (uint2*)bWol, CC * CC / 4);

    dim3 gproj(CC / 128, NQ / 128, 3);
    proj3_mma<<<gproj, 256, DSMEM_SIZE>>>(bin);

    dim3 gattn(HH, BB);
    attn2_kernel<<<gattn, 512, ATTN_SMEM>>>(index_pair);

    aux_kernel<<<NQ * LL / 256, 256>>>(aux_out);

    dim3 gout(CC / 128, NQ / 128);
    outproj_mma<<<gout, 256, DSMEM_SIZE>>>(bout, out);
}

// round 11
// speedup vs baseline: 1.1152x; 1.0235x over previous
#include <cuda_runtime.h>
#include <cstdint>

#define NQ 8192
#define MK 8192
#define BB 16
#define CC 512
#define LL 64
#define HH 8
#define DD 64

// fp32 intermediates
__device__ float g_q[NQ * CC];
__device__ float g_k[MK * CC];
__device__ float g_v[MK * CC];
__device__ float g_w[HH * NQ * LL];     // softmax weights scratch (16 MB)
__device__ float g_aux_scratch[NQ * LL];
__device__ int   g_key_start[BB];

// bf16 split operands (hi/lo), packed 2 elements per uint32
__device__ uint32_t g_bQh[NQ * CC / 2], g_bQl[NQ * CC / 2];
__device__ uint32_t g_bKh[MK * CC / 2], g_bKl[MK * CC / 2];
__device__ uint32_t g_bVh[MK * CC / 2], g_bVl[MK * CC / 2];
__device__ uint32_t g_bWih[3 * CC * CC / 2], g_bWil[3 * CC * CC / 2];
__device__ uint32_t g_bWoh[CC * CC / 2],     g_bWol[CC * CC / 2];
__device__ uint32_t g_bAh[NQ * CC / 2],      g_bAl[NQ * CC / 2];

// ---------------------------------------------------------------------------
static __device__ __forceinline__ uint32_t smem_u32(const void* p) {
    uint32_t a;
    asm("{ .reg .u64 t; cvta.to.shared.u64 t, %1; cvt.u32.u64 %0, t; }" : "=r"(a) : "l"(p));
    return a;
}
static __device__ __forceinline__ uint32_t packbf(float f0, float f1) {
    uint32_t r;
    asm("cvt.rn.bf16x2.f32 %0, %1, %2;" : "=r"(r) : "f"(f1), "f"(f0));
    return r;
}
static __device__ __forceinline__ float bflo(uint32_t r) { return __uint_as_float(r << 16); }
static __device__ __forceinline__ float bfhi(uint32_t r) { return __uint_as_float(r & 0xffff0000u); }
static __device__ __forceinline__ uint32_t lds32(uint32_t a) {
    uint32_t v; asm volatile("ld.shared.b32 %0, [%1];" : "=r"(v) : "r"(a)); return v;
}
static __device__ __forceinline__ void cpa16(uint32_t dst, const void* src) {
    asm volatile("cp.async.cg.shared.global [%0], [%1], 16;" :: "r"(dst), "l"(src) : "memory");
}
#define CP_COMMIT asm volatile("cp.async.commit_group;" ::: "memory")
#define CP_WAIT1  asm volatile("cp.async.wait_group 1;" ::: "memory")
#define CP_WAIT0  asm volatile("cp.async.wait_group 0;" ::: "memory")

#define MMA_BF16(c, a0, a1, a2, a3, b0, b1)                                   \
    asm volatile(                                                             \
        "mma.sync.aligned.m16n8k16.row.col.f32.bf16.bf16.f32 "                \
        "{%0,%1,%2,%3},{%4,%5,%6,%7},{%8,%9},{%0,%1,%2,%3};"                  \
        : "+f"((c)[0]), "+f"((c)[1]), "+f"((c)[2]), "+f"((c)[3])              \
        : "r"(a0), "r"(a1), "r"(a2), "r"(a3), "r"(b0), "r"(b1))

// ---------------------------------------------------------------------------
__global__ void key_start_kernel(const int* __restrict__ key_batch_cnt) {
    if (threadIdx.x == 0) {
        int s = 0;
        for (int b = 0; b < BB; b++) { g_key_start[b] = s; s += key_batch_cnt[b]; }
    }
}

// fp32 -> (bf16 hi, bf16 lo) split; blockIdx.y selects q/k/v
__global__ void __launch_bounds__(256) cvt3_kernel(
    const float4* __restrict__ q, const float4* __restrict__ k,
    const float4* __restrict__ v)
{
    const int z = blockIdx.y;
    const float4* src = (z == 0) ? q : (z == 1) ? k : v;
    uint2* hi = (uint2*)((z == 0) ? g_bQh : (z == 1) ? g_bKh : g_bVh);
    uint2* lo = (uint2*)((z == 0) ? g_bQl : (z == 1) ? g_bKl : g_bVl);
    int i = blockIdx.x * blockDim.x + threadIdx.x;
    float4 f = src[i];
    uint32_t h0 = packbf(f.x, f.y);
    uint32_t h1 = packbf(f.z, f.w);
    uint32_t l0 = packbf(f.x - bflo(h0), f.y - bfhi(h0));
    uint32_t l1 = packbf(f.z - bflo(h1), f.w - bfhi(h1));
    hi[i] = make_uint2(h0, h1);
    lo[i] = make_uint2(l0, l1);
}

__global__ void __launch_bounds__(256) cvt_split_kernel(
    const float4* __restrict__ src, uint2* __restrict__ hi, uint2* __restrict__ lo, int n4)
{
    int i = blockIdx.x * blockDim.x + threadIdx.x;
    if (i >= n4) return;
    float4 f = src[i];
    uint32_t h0 = packbf(f.x, f.y);
    uint32_t h1 = packbf(f.z, f.w);
    uint32_t l0 = packbf(f.x - bflo(h0), f.y - bfhi(h0));
    uint32_t l1 = packbf(f.z - bflo(h1), f.w - bfhi(h1));
    hi[i] = make_uint2(h0, h1);
    lo[i] = make_uint2(l0, l1);
}

// ===========================================================================
// Split-bf16 HMMA GEMM (unchanged, proven)
// ===========================================================================
#define SROWB 80
#define TILE_B (128 * SROWB)
#define STAGE_B (4 * TILE_B)
#define DSMEM_SIZE (2 * STAGE_B)

__device__ __forceinline__ void gemm_bf16_body(
    const uint32_t* __restrict__ Ah, const uint32_t* __restrict__ Al,
    const uint32_t* __restrict__ Bh, const uint32_t* __restrict__ Bl,
    const float* __restrict__ bias, float* __restrict__ Cout, float alpha)
{
    extern __shared__ char dsm[];
    const uint32_t sbase = smem_u32(dsm);

    const int t = threadIdx.x;
    const int lane = t & 31, warp = t >> 5;
    const int g = lane >> 2, tig = lane & 3;
    const int warpM = warp & 1, warpN = warp >> 1;
    const int row0 = blockIdx.y * 128, col0 = blockIdx.x * 128;

    const int crow = t >> 1, chalf = t & 1;
    const uint32_t dstoff = (uint32_t)(crow * SROWB + chalf * 32);
    const size_t srcAbase = (size_t)(row0 + crow) * (CC / 2) + chalf * 8;
    const size_t srcBbase = (size_t)(col0 + crow) * (CC / 2) + chalf * 8;

    float acc[4][4][4];
#pragma unroll
    for (int m = 0; m < 4; m++)
#pragma unroll
        for (int n = 0; n < 4; n++)
#pragma unroll
            for (int j = 0; j < 4; j++) acc[m][n][j] = 0.0f;

#define ISSUE(kt, buf)                                                         \
    do {                                                                       \
        uint32_t sb = sbase + (buf) * STAGE_B;                                 \
        size_t ksrc = (size_t)(kt) * 16;                                       \
        cpa16(sb + dstoff,                  Ah + srcAbase + ksrc);             \
        cpa16(sb + dstoff + 16,             Ah + srcAbase + ksrc + 4);         \
        cpa16(sb + TILE_B + dstoff,         Al + srcAbase + ksrc);             \
        cpa16(sb + TILE_B + dstoff + 16,    Al + srcAbase + ksrc + 4);         \
        cpa16(sb + 2*TILE_B + dstoff,       Bh + srcBbase + ksrc);             \
        cpa16(sb + 2*TILE_B + dstoff + 16,  Bh + srcBbase + ksrc + 4);         \
        cpa16(sb + 3*TILE_B + dstoff,       Bl + srcBbase + ksrc);             \
        cpa16(sb + 3*TILE_B + dstoff + 16,  Bl + srcBbase + ksrc + 4);         \
    } while (0)

    const int NT = CC / 32;
    ISSUE(0, 0);
    CP_COMMIT;

    for (int kt = 0; kt < NT; kt++) {
        if (kt + 1 < NT) {
            ISSUE(kt + 1, (kt + 1) & 1);
            CP_COMMIT;
            CP_WAIT1;
        } else {
            CP_WAIT0;
        }
        __syncthreads();

        const uint32_t ab = sbase + (kt & 1) * STAGE_B;
#pragma unroll
        for (int sub = 0; sub < 2; sub++) {
            const uint32_t koff = sub * 32;
            uint32_t af[4][4];

#pragma unroll
            for (int m = 0; m < 4; m++) {
                uint32_t ro = ab + (uint32_t)((warpM * 64 + m * 16 + g) * SROWB) + koff + tig * 4;
                af[m][0] = lds32(ro);
                af[m][1] = lds32(ro + 8 * SROWB);
                af[m][2] = lds32(ro + 16);
                af[m][3] = lds32(ro + 8 * SROWB + 16);
            }
#pragma unroll
            for (int n = 0; n < 4; n++) {
                uint32_t bo = ab + 2 * TILE_B +
                    (uint32_t)((warpN * 32 + n * 8 + g) * SROWB) + koff + tig * 4;
                uint32_t bh0 = lds32(bo), bh1 = lds32(bo + 16);
                uint32_t bl0 = lds32(bo + TILE_B), bl1 = lds32(bo + TILE_B + 16);
#pragma unroll
                for (int m = 0; m < 4; m++) {
                    MMA_BF16(acc[m][n], af[m][0], af[m][1], af[m][2], af[m][3], bh0, bh1);
                    MMA_BF16(acc[m][n], af[m][0], af[m][1], af[m][2], af[m][3], bl0, bl1);
                }
            }

#pragma unroll
            for (int m = 0; m < 4; m++) {
                uint32_t ro = ab + TILE_B +
                    (uint32_t)((warpM * 64 + m * 16 + g) * SROWB) + koff + tig * 4;
                af[m][0] = lds32(ro);
                af[m][1] = lds32(ro + 8 * SROWB);
                af[m][2] = lds32(ro + 16);
                af[m][3] = lds32(ro + 8 * SROWB + 16);
            }
#pragma unroll
            for (int n = 0; n < 4; n++) {
                uint32_t bo = ab + 2 * TILE_B +
                    (uint32_t)((warpN * 32 + n * 8 + g) * SROWB) + koff + tig * 4;
                uint32_t bh0 = lds32(bo), bh1 = lds32(bo + 16);
#pragma unroll
                for (int m = 0; m < 4; m++)
                    MMA_BF16(acc[m][n], af[m][0], af[m][1], af[m][2], af[m][3], bh0, bh1);
            }
        }
        __syncthreads();
    }
#undef ISSUE

#pragma unroll
    for (int m = 0; m < 4; m++) {
        int rg = row0 + warpM * 64 + m * 16 + g;
#pragma unroll
        for (int n = 0; n < 4; n++) {
            int col = col0 + warpN * 32 + n * 8 + tig * 2;
            float b0 = __ldg(&bias[col]), b1 = __ldg(&bias[col + 1]);
            float2 o;
            o.x = alpha * (acc[m][n][0] + b0);
            o.y = alpha * (acc[m][n][1] + b1);
            *reinterpret_cast<float2*>(&Cout[(size_t)rg * CC + col]) = o;
            o.x = alpha * (acc[m][n][2] + b0);
            o.y = alpha * (acc[m][n][3] + b1);
            *reinterpret_cast<float2*>(&Cout[(size_t)(rg + 8) * CC + col]) = o;
        }
    }
}

__global__ void __launch_bounds__(256, 2) proj3_mma(const float* __restrict__ bin) {
    const int z = blockIdx.z;
    const uint32_t* Ahz = (z == 0) ? g_bQh : (z == 1) ? g_bKh : g_bVh;
    const uint32_t* Alz = (z == 0) ? g_bQl : (z == 1) ? g_bKl : g_bVl;
    float* Cz = (z == 0) ? g_q : (z == 1) ? g_k : g_v;
    const float alpha = (z == 0) ? 0.125f : 1.0f;
    gemm_bf16_body(Ahz, Alz,
                   g_bWih + (size_t)z * (CC * CC / 2),
                   g_bWil + (size_t)z * (CC * CC / 2),
                   bin + z * CC, Cz, alpha);
}

__global__ void __launch_bounds__(256, 2) outproj_mma(
    const float* __restrict__ bout, float* __restrict__ out) {
    gemm_bf16_body(g_bAh, g_bAl, g_bWoh, g_bWol, bout, out, 1.0f);
}

// ===========================================================================
// Sliced attention v3. CTA = (head, batch), 1024 threads (32 warps) so the
// latency-bound LDS/SHFL chains get 8 warps/SMSP instead of 4.
// Phase 1: octet-broadcast gathered-row reads (conflict-free LDS.128).
// Phase 2: broadcast weighted-V (proven).
// ===========================================================================
#define KROW 68
#define ATTN_SMEM (512 * KROW * 4)

__global__ void __launch_bounds__(1024) attn2_kernel(const int* __restrict__ index_pair)
{
    extern __shared__ float sk[];
    const int h = blockIdx.x, b = blockIdx.y;
    const int t = threadIdx.x, warp = t >> 5, lane = t & 31;
    const int qtr = lane >> 3, d_oct = lane & 7;
    const int ks = g_key_start[b];

    // ---- stage K slice [512 x 64] ----
    {
        int seg = t & 7;
#pragma unroll
        for (int p = 0; p < 4; p++) {
            int row = (t >> 3) + p * 128;
            const float4* src = reinterpret_cast<const float4*>(
                &g_k[(size_t)(ks + row) * CC + h * DD + seg * 8]);
            float4 v0 = src[0], v1 = src[1];
            *reinterpret_cast<float4*>(&sk[row * KROW + seg * 8])     = v0;
            *reinterpret_cast<float4*>(&sk[row * KROW + seg * 8 + 4]) = v1;
        }
    }
    __syncthreads();

    // ---- phase 1: scores + softmax -> g_w (16 queries per warp) ----
#pragma unroll 1
    for (int j = 0; j < 16; j++) {
        const int qi = warp + 32 * j;
        const int n = b * 512 + qi;
        int2 iv = *reinterpret_cast<const int2*>(&index_pair[n * LL + lane * 2]);
        const float* qb = &g_q[(size_t)n * CC + h * DD];
        float4 q0 = *reinterpret_cast<const float4*>(&qb[d_oct * 4]);
        float4 q1 = *reinterpret_cast<const float4*>(&qb[32 + d_oct * 4]);

        float sc[16];
#pragma unroll
        for (int li = 0; li < 16; li++) {
            int src = qtr * 8 + (li >> 1);
            int raw = __shfl_sync(0xffffffffu, (li & 1) ? iv.y : iv.x, src);
            int row = (raw >= 0) ? raw : 0;
            const float* kr = &sk[row * KROW];
            float4 k0 = *reinterpret_cast<const float4*>(&kr[d_oct * 4]);
            float4 k1 = *reinterpret_cast<const float4*>(&kr[32 + d_oct * 4]);
            float s = q0.x * k0.x;
            s = fmaf(q0.y, k0.y, s); s = fmaf(q0.z, k0.z, s); s = fmaf(q0.w, k0.w, s);
            s = fmaf(q1.x, k1.x, s); s = fmaf(q1.y, k1.y, s);
            s = fmaf(q1.z, k1.z, s); s = fmaf(q1.w, k1.w, s);
            s += __shfl_xor_sync(0xffffffffu, s, 1);
            s += __shfl_xor_sync(0xffffffffu, s, 2);
            s += __shfl_xor_sync(0xffffffffu, s, 4);
            sc[li] = (raw >= 0) ? s : -1000.0f;
        }

        float m = sc[0];
#pragma unroll
        for (int li = 1; li < 16; li++) m = fmaxf(m, sc[li]);
        m = fmaxf(m, __shfl_xor_sync(0xffffffffu, m, 8));
        m = fmaxf(m, __shfl_xor_sync(0xffffffffu, m, 16));
        float sum = 0.0f;
#pragma unroll
        for (int li = 0; li < 16; li++) { sc[li] = __expf(sc[li] - m); sum += sc[li]; }
        sum += __shfl_xor_sync(0xffffffffu, sum, 8);
        sum += __shfl_xor_sync(0xffffffffu, sum, 16);
        float inv = 1.0f / sum;

        float* wdst = &g_w[((size_t)h * NQ + n) * LL];
        wdst[qtr * 16 + d_oct]     = sc[d_oct] * inv;
        wdst[qtr * 16 + d_oct + 8] = sc[d_oct + 8] * inv;
    }
    __syncthreads();

    // ---- stage V slice (overwrite K) ----
    {
        int seg = t & 7;
#pragma unroll
        for (int p = 0; p < 4; p++) {
            int row = (t >> 3) + p * 128;
            const float4* src = reinterpret_cast<const float4*>(
                &g_v[(size_t)(ks + row) * CC + h * DD + seg * 8]);
            float4 v0 = src[0], v1 = src[1];
            *reinterpret_cast<float4*>(&sk[row * KROW + seg * 8])     = v0;
            *reinterpret_cast<float4*>(&sk[row * KROW + seg * 8 + 4]) = v1;
        }
    }
    __syncthreads();

    // ---- phase 2: weighted sum (broadcast pattern) ----
#pragma unroll 1
    for (int j = 0; j < 16; j++) {
        const int qi = warp + 32 * j;
        const int n = b * 512 + qi;
        float2 wv = *reinterpret_cast<const float2*>(
            &g_w[((size_t)h * NQ + n) * LL + lane * 2]);
        int2 iv = *reinterpret_cast<const int2*>(&index_pair[n * LL + lane * 2]);
        iv.x = (iv.x >= 0) ? iv.x : 0;
        iv.y = (iv.y >= 0) ? iv.y : 0;

        float2 acc = make_float2(0.0f, 0.0f);
#pragma unroll
        for (int l = 0; l < 64; l++) {
            int src_lane = l >> 1;
            float wl  = __shfl_sync(0xffffffffu, (l & 1) ? wv.y : wv.x, src_lane);
            int   row = __shfl_sync(0xffffffffu, (l & 1) ? iv.y : iv.x, src_lane);
            float2 vv = *reinterpret_cast<const float2*>(&sk[row * KROW + lane * 2]);
            acc.x = fmaf(wl, vv.x, acc.x);
            acc.y = fmaf(wl, vv.y, acc.y);
        }
        uint32_t hh = packbf(acc.x, acc.y);
        uint32_t ll = packbf(acc.x - bflo(hh), acc.y - bfhi(hh));
        size_t o2 = ((size_t)n * CC + h * DD + lane * 2) >> 1;
        g_bAh[o2] = hh;
        g_bAl[o2] = ll;
    }
}

// aux[n,l] = mean over heads of w
__global__ void __launch_bounds__(256) aux_kernel(float* __restrict__ aux_out) {
    int i = blockIdx.x * 256 + threadIdx.x;
    float s = 0.0f;
#pragma unroll
    for (int h = 0; h < HH; h++) s += g_w[(size_t)h * (NQ * LL) + i];
    aux_out[i] = s * 0.125f;
}

// ---------------------------------------------------------------------------
extern "C" void kernel_launch(void* const* d_in, const int* in_sizes, int n_in,
                              void* d_out, int out_size) {
    const float* query  = (const float*)d_in[0];
    const float* key    = (const float*)d_in[1];
    const float* value  = (const float*)d_in[2];
    const float* Win    = (const float*)d_in[3];
    const float* bin    = (const float*)d_in[4];
    const float* Wout   = (const float*)d_in[5];
    const float* bout   = (const float*)d_in[6];
    const int*   index_pair       = (const int*)d_in[7];
    const int*   key_batch_cnt    = (const int*)d_in[9];
    float* out = (float*)d_out;

    float* auxs;
    cudaGetSymbolAddress((void**)&auxs, g_aux_scratch);
    float* aux_out = (out_size >= NQ * CC + NQ * LL) ? (out + (size_t)NQ * CC) : auxs;

    uint32_t *bWih, *bWil, *bWoh, *bWol;
    cudaGetSymbolAddress((void**)&bWih, g_bWih); cudaGetSymbolAddress((void**)&bWil, g_bWil);
    cudaGetSymbolAddress((void**)&bWoh, g_bWoh); cudaGetSymbolAddress((void**)&bWol, g_bWol);

    cudaFuncSetAttribute(proj3_mma,    cudaFuncAttributeMaxDynamicSharedMemorySize, DSMEM_SIZE);
    cudaFuncSetAttribute(outproj_mma,  cudaFuncAttributeMaxDynamicSharedMemorySize, DSMEM_SIZE);
    cudaFuncSetAttribute(attn2_kernel, cudaFuncAttributeMaxDynamicSharedMemorySize, ATTN_SMEM);

    key_start_kernel<<<1, 32>>>(key_batch_cnt);

    dim3 gcvt(NQ * CC / 4 / 256, 3);
    cvt3_kernel<<<gcvt, 256>>>((const float4*)query, (const float4*)key,
                               (const float4*)value);
    cvt_split_kernel<<<3 * CC * CC / 4 / 256, 256>>>(
        (const float4*)Win, (uint2*)bWih, (uint2*)bWil, 3 * CC * CC / 4);
    cvt_split_kernel<<<CC * CC / 4 / 256, 256>>>(
        (const float4*)Wout, (uint2*)bWoh, (uint2*)bWol, CC * CC / 4);

    dim3 gproj(CC / 128, NQ / 128, 3);
    proj3_mma<<<gproj, 256, DSMEM_SIZE>>>(bin);

    dim3 gattn(HH, BB);
    attn2_kernel<<<gattn, 1024, ATTN_SMEM>>>(index_pair);

    aux_kernel<<<NQ * LL / 256, 256>>>(aux_out);

    dim3 gout(CC / 128, NQ / 128);
    outproj_mma<<<gout, 256, DSMEM_SIZE>>>(bout, out);
}

// round 12
// speedup vs baseline: 1.1263x; 1.0100x over previous
#include <cuda_runtime.h>
#include <cstdint>

#define NQ 8192
#define MK 8192
#define BB 16
#define CC 512
#define LL 64
#define HH 8
#define DD 64

// fp32 intermediates
__device__ float g_q[NQ * CC];
__device__ float g_k[MK * CC];
__device__ float g_v[MK * CC];
__device__ float g_w[HH * NQ * LL];     // softmax weights scratch (16 MB)
__device__ float g_aux_scratch[NQ * LL];
__device__ int   g_key_start[BB];

// bf16 split operands (hi/lo), packed 2 elements per uint32
__device__ uint32_t g_bQh[NQ * CC / 2], g_bQl[NQ * CC / 2];
__device__ uint32_t g_bKh[MK * CC / 2], g_bKl[MK * CC / 2];
__device__ uint32_t g_bVh[MK * CC / 2], g_bVl[MK * CC / 2];
__device__ uint32_t g_bWih[3 * CC * CC / 2], g_bWil[3 * CC * CC / 2];
__device__ uint32_t g_bWoh[CC * CC / 2],     g_bWol[CC * CC / 2];
__device__ uint32_t g_bAh[NQ * CC / 2],      g_bAl[NQ * CC / 2];

// ---------------------------------------------------------------------------
static __device__ __forceinline__ uint32_t smem_u32(const void* p) {
    uint32_t a;
    asm("{ .reg .u64 t; cvta.to.shared.u64 t, %1; cvt.u32.u64 %0, t; }" : "=r"(a) : "l"(p));
    return a;
}
static __device__ __forceinline__ uint32_t packbf(float f0, float f1) {
    uint32_t r;
    asm("cvt.rn.bf16x2.f32 %0, %1, %2;" : "=r"(r) : "f"(f1), "f"(f0));
    return r;
}
static __device__ __forceinline__ float bflo(uint32_t r) { return __uint_as_float(r << 16); }
static __device__ __forceinline__ float bfhi(uint32_t r) { return __uint_as_float(r & 0xffff0000u); }
static __device__ __forceinline__ void cpa16(uint32_t dst, const void* src) {
    asm volatile("cp.async.cg.shared.global [%0], [%1], 16;" :: "r"(dst), "l"(src) : "memory");
}
#define CP_COMMIT asm volatile("cp.async.commit_group;" ::: "memory")
#define CP_WAIT1  asm volatile("cp.async.wait_group 1;" ::: "memory")
#define CP_WAIT0  asm volatile("cp.async.wait_group 0;" ::: "memory")

#define MMA_BF16(c, a0, a1, a2, a3, b0, b1)                                   \
    asm volatile(                                                             \
        "mma.sync.aligned.m16n8k16.row.col.f32.bf16.bf16.f32 "                \
        "{%0,%1,%2,%3},{%4,%5,%6,%7},{%8,%9},{%0,%1,%2,%3};"                  \
        : "+f"((c)[0]), "+f"((c)[1]), "+f"((c)[2]), "+f"((c)[3])              \
        : "r"(a0), "r"(a1), "r"(a2), "r"(a3), "r"(b0), "r"(b1))

#define LDSM4(r, a)                                                           \
    asm volatile("ldmatrix.sync.aligned.m8n8.x4.shared.b16 {%0,%1,%2,%3}, [%4];" \
        : "=r"((r)[0]), "=r"((r)[1]), "=r"((r)[2]), "=r"((r)[3]) : "r"(a))
#define LDSM2(r0, r1, a)                                                      \
    asm volatile("ldmatrix.sync.aligned.m8n8.x2.shared.b16 {%0,%1}, [%2];"    \
        : "=r"(r0), "=r"(r1) : "r"(a))

// ---------------------------------------------------------------------------
__global__ void key_start_kernel(const int* __restrict__ key_batch_cnt) {
    if (threadIdx.x == 0) {
        int s = 0;
        for (int b = 0; b < BB; b++) { g_key_start[b] = s; s += key_batch_cnt[b]; }
    }
}

// fp32 -> (bf16 hi, bf16 lo) split; blockIdx.y selects q/k/v
__global__ void __launch_bounds__(256) cvt3_kernel(
    const float4* __restrict__ q, const float4* __restrict__ k,
    const float4* __restrict__ v)
{
    const int z = blockIdx.y;
    const float4* src = (z == 0) ? q : (z == 1) ? k : v;
    uint2* hi = (uint2*)((z == 0) ? g_bQh : (z == 1) ? g_bKh : g_bVh);
    uint2* lo = (uint2*)((z == 0) ? g_bQl : (z == 1) ? g_bKl : g_bVl);
    int i = blockIdx.x * blockDim.x + threadIdx.x;
    float4 f = src[i];
    uint32_t h0 = packbf(f.x, f.y);
    uint32_t h1 = packbf(f.z, f.w);
    uint32_t l0 = packbf(f.x - bflo(h0), f.y - bfhi(h0));
    uint32_t l1 = packbf(f.z - bflo(h1), f.w - bfhi(h1));
    hi[i] = make_uint2(h0, h1);
    lo[i] = make_uint2(l0, l1);
}

__global__ void __launch_bounds__(256) cvt_split_kernel(
    const float4* __restrict__ src, uint2* __restrict__ hi, uint2* __restrict__ lo, int n4)
{
    int i = blockIdx.x * blockDim.x + threadIdx.x;
    if (i >= n4) return;
    float4 f = src[i];
    uint32_t h0 = packbf(f.x, f.y);
    uint32_t h1 = packbf(f.z, f.w);
    uint32_t l0 = packbf(f.x - bflo(h0), f.y - bfhi(h0));
    uint32_t l1 = packbf(f.z - bflo(h1), f.w - bfhi(h1));
    hi[i] = make_uint2(h0, h1);
    lo[i] = make_uint2(l0, l1);
}

// ===========================================================================
// Split-bf16 HMMA GEMM with ldmatrix fragment loads.
// 128x128 CTA tile, 8 warps (2x4) of 64x32, m16n8k16, BK=32, cp.async 2-stage.
// ===========================================================================
#define SROWB 80
#define TILE_B (128 * SROWB)
#define STAGE_B (4 * TILE_B)
#define DSMEM_SIZE (2 * STAGE_B)

__device__ __forceinline__ void gemm_bf16_body(
    const uint32_t* __restrict__ Ah, const uint32_t* __restrict__ Al,
    const uint32_t* __restrict__ Bh, const uint32_t* __restrict__ Bl,
    const float* __restrict__ bias, float* __restrict__ Cout, float alpha)
{
    extern __shared__ char dsm[];
    const uint32_t sbase = smem_u32(dsm);

    const int t = threadIdx.x;
    const int lane = t & 31, warp = t >> 5;
    const int g = lane >> 2, tig = lane & 3;
    const int warpM = warp & 1, warpN = warp >> 1;
    const int row0 = blockIdx.y * 128, col0 = blockIdx.x * 128;

    // ldmatrix per-lane address components
    const int lrow = lane & 7, lq = lane >> 3;        // quad 0..3
    const uint32_t aoff =
        (uint32_t)((warpM * 64 + lrow + (lq & 1) * 8) * SROWB) + (uint32_t)((lq >> 1) * 16);
    const uint32_t boff =
        (uint32_t)((warpN * 32 + lrow) * SROWB) + (uint32_t)((lq & 1) * 16);

    const int crow = t >> 1, chalf = t & 1;
    const uint32_t dstoff = (uint32_t)(crow * SROWB + chalf * 32);
    const size_t srcAbase = (size_t)(row0 + crow) * (CC / 2) + chalf * 8;
    const size_t srcBbase = (size_t)(col0 + crow) * (CC / 2) + chalf * 8;

    float acc[4][4][4];
#pragma unroll
    for (int m = 0; m < 4; m++)
#pragma unroll
        for (int n = 0; n < 4; n++)
#pragma unroll
            for (int j = 0; j < 4; j++) acc[m][n][j] = 0.0f;

#define ISSUE(kt, buf)                                                         \
    do {                                                                       \
        uint32_t sb = sbase + (buf) * STAGE_B;                                 \
        size_t ksrc = (size_t)(kt) * 16;                                       \
        cpa16(sb + dstoff,                  Ah + srcAbase + ksrc);             \
        cpa16(sb + dstoff + 16,             Ah + srcAbase + ksrc + 4);         \
        cpa16(sb + TILE_B + dstoff,         Al + srcAbase + ksrc);             \
        cpa16(sb + TILE_B + dstoff + 16,    Al + srcAbase + ksrc + 4);         \
        cpa16(sb + 2*TILE_B + dstoff,       Bh + srcBbase + ksrc);             \
        cpa16(sb + 2*TILE_B + dstoff + 16,  Bh + srcBbase + ksrc + 4);         \
        cpa16(sb + 3*TILE_B + dstoff,       Bl + srcBbase + ksrc);             \
        cpa16(sb + 3*TILE_B + dstoff + 16,  Bl + srcBbase + ksrc + 4);         \
    } while (0)

    const int NT = CC / 32;
    ISSUE(0, 0);
    CP_COMMIT;

    for (int kt = 0; kt < NT; kt++) {
        if (kt + 1 < NT) {
            ISSUE(kt + 1, (kt + 1) & 1);
            CP_COMMIT;
            CP_WAIT1;
        } else {
            CP_WAIT0;
        }
        __syncthreads();

        const uint32_t ab = sbase + (kt & 1) * STAGE_B;
#pragma unroll
        for (int sub = 0; sub < 2; sub++) {
            const uint32_t koff = sub * 32;
            const uint32_t aAddr = ab + aoff + koff;              // A hi base
            const uint32_t bAddr = ab + 2 * TILE_B + boff + koff; // B hi base
            uint32_t af[4][4];

            // ---- pass 1: A-hi frags (ldmatrix x4); Ah*Bh + Ah*Bl ----
#pragma unroll
            for (int m = 0; m < 4; m++)
                LDSM4(af[m], aAddr + (uint32_t)(m * 16 * SROWB));
#pragma unroll
            for (int n = 0; n < 4; n++) {
                uint32_t bb = bAddr + (uint32_t)(n * 8 * SROWB);
                uint32_t bh0, bh1, bl0, bl1;
                LDSM2(bh0, bh1, bb);
                LDSM2(bl0, bl1, bb + TILE_B);
#pragma unroll
                for (int m = 0; m < 4; m++) {
                    MMA_BF16(acc[m][n], af[m][0], af[m][1], af[m][2], af[m][3], bh0, bh1);
                    MMA_BF16(acc[m][n], af[m][0], af[m][1], af[m][2], af[m][3], bl0, bl1);
                }
            }

            // ---- pass 2: A-lo frags (reuse regs); Al*Bh ----
#pragma unroll
            for (int m = 0; m < 4; m++)
                LDSM4(af[m], aAddr + TILE_B + (uint32_t)(m * 16 * SROWB));
#pragma unroll
            for (int n = 0; n < 4; n++) {
                uint32_t bh0, bh1;
                LDSM2(bh0, bh1, bAddr + (uint32_t)(n * 8 * SROWB));
#pragma unroll
                for (int m = 0; m < 4; m++)
                    MMA_BF16(acc[m][n], af[m][0], af[m][1], af[m][2], af[m][3], bh0, bh1);
            }
        }
        __syncthreads();
    }
#undef ISSUE

#pragma unroll
    for (int m = 0; m < 4; m++) {
        int rg = row0 + warpM * 64 + m * 16 + g;
#pragma unroll
        for (int n = 0; n < 4; n++) {
            int col = col0 + warpN * 32 + n * 8 + tig * 2;
            float b0 = __ldg(&bias[col]), b1 = __ldg(&bias[col + 1]);
            float2 o;
            o.x = alpha * (acc[m][n][0] + b0);
            o.y = alpha * (acc[m][n][1] + b1);
            *reinterpret_cast<float2*>(&Cout[(size_t)rg * CC + col]) = o;
            o.x = alpha * (acc[m][n][2] + b0);
            o.y = alpha * (acc[m][n][3] + b1);
            *reinterpret_cast<float2*>(&Cout[(size_t)(rg + 8) * CC + col]) = o;
        }
    }
}

__global__ void __launch_bounds__(256, 2) proj3_mma(const float* __restrict__ bin) {
    const int z = blockIdx.z;
    const uint32_t* Ahz = (z == 0) ? g_bQh : (z == 1) ? g_bKh : g_bVh;
    const uint32_t* Alz = (z == 0) ? g_bQl : (z == 1) ? g_bKl : g_bVl;
    float* Cz = (z == 0) ? g_q : (z == 1) ? g_k : g_v;
    const float alpha = (z == 0) ? 0.125f : 1.0f;
    gemm_bf16_body(Ahz, Alz,
                   g_bWih + (size_t)z * (CC * CC / 2),
                   g_bWil + (size_t)z * (CC * CC / 2),
                   bin + z * CC, Cz, alpha);
}

__global__ void __launch_bounds__(256, 2) outproj_mma(
    const float* __restrict__ bout, float* __restrict__ out) {
    gemm_bf16_body(g_bAh, g_bAl, g_bWoh, g_bWol, bout, out, 1.0f);
}

// ===========================================================================
// Sliced attention (R11 champion, unchanged): 1024 threads, octet-broadcast
// conflict-free phase 1, broadcast weighted-V phase 2.
// ===========================================================================
#define KROW 68
#define ATTN_SMEM (512 * KROW * 4)

__global__ void __launch_bounds__(1024) attn2_kernel(const int* __restrict__ index_pair)
{
    extern __shared__ float sk[];
    const int h = blockIdx.x, b = blockIdx.y;
    const int t = threadIdx.x, warp = t >> 5, lane = t & 31;
    const int qtr = lane >> 3, d_oct = lane & 7;
    const int ks = g_key_start[b];

    {
        int seg = t & 7;
#pragma unroll
        for (int p = 0; p < 4; p++) {
            int row = (t >> 3) + p * 128;
            const float4* src = reinterpret_cast<const float4*>(
                &g_k[(size_t)(ks + row) * CC + h * DD + seg * 8]);
            float4 v0 = src[0], v1 = src[1];
            *reinterpret_cast<float4*>(&sk[row * KROW + seg * 8])     = v0;
            *reinterpret_cast<float4*>(&sk[row * KROW + seg * 8 + 4]) = v1;
        }
    }
    __syncthreads();

#pragma unroll 1
    for (int j = 0; j < 16; j++) {
        const int qi = warp + 32 * j;
        const int n = b * 512 + qi;
        int2 iv = *reinterpret_cast<const int2*>(&index_pair[n * LL + lane * 2]);
        const float* qb = &g_q[(size_t)n * CC + h * DD];
        float4 q0 = *reinterpret_cast<const float4*>(&qb[d_oct * 4]);
        float4 q1 = *reinterpret_cast<const float4*>(&qb[32 + d_oct * 4]);

        float sc[16];
#pragma unroll
        for (int li = 0; li < 16; li++) {
            int src = qtr * 8 + (li >> 1);
            int raw = __shfl_sync(0xffffffffu, (li & 1) ? iv.y : iv.x, src);
            int row = (raw >= 0) ? raw : 0;
            const float* kr = &sk[row * KROW];
            float4 k0 = *reinterpret_cast<const float4*>(&kr[d_oct * 4]);
            float4 k1 = *reinterpret_cast<const float4*>(&kr[32 + d_oct * 4]);
            float s = q0.x * k0.x;
            s = fmaf(q0.y, k0.y, s); s = fmaf(q0.z, k0.z, s); s = fmaf(q0.w, k0.w, s);
            s = fmaf(q1.x, k1.x, s); s = fmaf(q1.y, k1.y, s);
            s = fmaf(q1.z, k1.z, s); s = fmaf(q1.w, k1.w, s);
            s += __shfl_xor_sync(0xffffffffu, s, 1);
            s += __shfl_xor_sync(0xffffffffu, s, 2);
            s += __shfl_xor_sync(0xffffffffu, s, 4);
            sc[li] = (raw >= 0) ? s : -1000.0f;
        }

        float m = sc[0];
#pragma unroll
        for (int li = 1; li < 16; li++) m = fmaxf(m, sc[li]);
        m = fmaxf(m, __shfl_xor_sync(0xffffffffu, m, 8));
        m = fmaxf(m, __shfl_xor_sync(0xffffffffu, m, 16));
        float sum = 0.0f;
#pragma unroll
        for (int li = 0; li < 16; li++) { sc[li] = __expf(sc[li] - m); sum += sc[li]; }
        sum += __shfl_xor_sync(0xffffffffu, sum, 8);
        sum += __shfl_xor_sync(0xffffffffu, sum, 16);
        float inv = 1.0f / sum;

        float* wdst = &g_w[((size_t)h * NQ + n) * LL];
        wdst[qtr * 16 + d_oct]     = sc[d_oct] * inv;
        wdst[qtr * 16 + d_oct + 8] = sc[d_oct + 8] * inv;
    }
    __syncthreads();

    {
        int seg = t & 7;
#pragma unroll
        for (int p = 0; p < 4; p++) {
            int row = (t >> 3) + p * 128;
            const float4* src = reinterpret_cast<const float4*>(
                &g_v[(size_t)(ks + row) * CC + h * DD + seg * 8]);
            float4 v0 = src[0], v1 = src[1];
            *reinterpret_cast<float4*>(&sk[row * KROW + seg * 8])     = v0;
            *reinterpret_cast<float4*>(&sk[row * KROW + seg * 8 + 4]) = v1;
        }
    }
    __syncthreads();

#pragma unroll 1
    for (int j = 0; j < 16; j++) {
        const int qi = warp + 32 * j;
        const int n = b * 512 + qi;
        float2 wv = *reinterpret_cast<const float2*>(
            &g_w[((size_t)h * NQ + n) * LL + lane * 2]);
        int2 iv = *reinterpret_cast<const int2*>(&index_pair[n * LL + lane * 2]);
        iv.x = (iv.x >= 0) ? iv.x : 0;
        iv.y = (iv.y >= 0) ? iv.y : 0;

        float2 acc = make_float2(0.0f, 0.0f);
#pragma unroll
        for (int l = 0; l < 64; l++) {
            int src_lane = l >> 1;
            float wl  = __shfl_sync(0xffffffffu, (l & 1) ? wv.y : wv.x, src_lane);
            int   row = __shfl_sync(0xffffffffu, (l & 1) ? iv.y : iv.x, src_lane);
            float2 vv = *reinterpret_cast<const float2*>(&sk[row * KROW + lane * 2]);
            acc.x = fmaf(wl, vv.x, acc.x);
            acc.y = fmaf(wl, vv.y, acc.y);
        }
        uint32_t hh = packbf(acc.x, acc.y);
        uint32_t ll = packbf(acc.x - bflo(hh), acc.y - bfhi(hh));
        size_t o2 = ((size_t)n * CC + h * DD + lane * 2) >> 1;
        g_bAh[o2] = hh;
        g_bAl[o2] = ll;
    }
}

// aux[n,l] = mean over heads of w
__global__ void __launch_bounds__(256) aux_kernel(float* __restrict__ aux_out) {
    int i = blockIdx.x * 256 + threadIdx.x;
    float s = 0.0f;
#pragma unroll
    for (int h = 0; h < HH; h++) s += g_w[(size_t)h * (NQ * LL) + i];
    aux_out[i] = s * 0.125f;
}

// ---------------------------------------------------------------------------
extern "C" void kernel_launch(void* const* d_in, const int* in_sizes, int n_in,
                              void* d_out, int out_size) {
    const float* query  = (const float*)d_in[0];
    const float* key    = (const float*)d_in[1];
    const float* value  = (const float*)d_in[2];
    const float* Win    = (const float*)d_in[3];
    const float* bin    = (const float*)d_in[4];
    const float* Wout   = (const float*)d_in[5];
    const float* bout   = (const float*)d_in[6];
    const int*   index_pair       = (const int*)d_in[7];
    const int*   key_batch_cnt    = (const int*)d_in[9];
    float* out = (float*)d_out;

    float* auxs;
    cudaGetSymbolAddress((void**)&auxs, g_aux_scratch);
    float* aux_out = (out_size >= NQ * CC + NQ * LL) ? (out + (size_t)NQ * CC) : auxs;

    uint32_t *bWih, *bWil, *bWoh, *bWol;
    cudaGetSymbolAddress((void**)&bWih, g_bWih); cudaGetSymbolAddress((void**)&bWil, g_bWil);
    cudaGetSymbolAddress((void**)&bWoh, g_bWoh); cudaGetSymbolAddress((void**)&bWol, g_bWol);

    cudaFuncSetAttribute(proj3_mma,    cudaFuncAttributeMaxDynamicSharedMemorySize, DSMEM_SIZE);
    cudaFuncSetAttribute(outproj_mma,  cudaFuncAttributeMaxDynamicSharedMemorySize, DSMEM_SIZE);
    cudaFuncSetAttribute(attn2_kernel, cudaFuncAttributeMaxDynamicSharedMemorySize, ATTN_SMEM);

    key_start_kernel<<<1, 32>>>(key_batch_cnt);

    dim3 gcvt(NQ * CC / 4 / 256, 3);
    cvt3_kernel<<<gcvt, 256>>>((const float4*)query, (const float4*)key,
                               (const float4*)value);
    cvt_split_kernel<<<3 * CC * CC / 4 / 256, 256>>>(
        (const float4*)Win, (uint2*)bWih, (uint2*)bWil, 3 * CC * CC / 4);
    cvt_split_kernel<<<CC * CC / 4 / 256, 256>>>(
        (const float4*)Wout, (uint2*)bWoh, (uint2*)bWol, CC * CC / 4);

    dim3 gproj(CC / 128, NQ / 128, 3);
    proj3_mma<<<gproj, 256, DSMEM_SIZE>>>(bin);

    dim3 gattn(HH, BB);
    attn2_kernel<<<gattn, 1024, ATTN_SMEM>>>(index_pair);

    aux_kernel<<<NQ * LL / 256, 256>>>(aux_out);

    dim3 gout(CC / 128, NQ / 128);
    outproj_mma<<<gout, 256, DSMEM_SIZE>>>(bout, out);
}

// round 13
// speedup vs baseline: 1.1631x; 1.0326x over previous
#include <cuda_runtime.h>
#include <cstdint>

#define NQ 8192
#define MK 8192
#define BB 16
#define CC 512
#define LL 64
#define HH 8
#define DD 64

// fp32 intermediates
__device__ float g_q[NQ * CC];
__device__ float g_k[MK * CC];
__device__ float g_v[MK * CC];
__device__ float g_w[HH * NQ * LL];     // softmax weights scratch (16 MB)
__device__ float g_aux_scratch[NQ * LL];
__device__ int   g_key_start[BB];

// bf16 split operands (hi/lo), packed 2 elements per uint32
__device__ uint32_t g_bQh[NQ * CC / 2], g_bQl[NQ * CC / 2];
__device__ uint32_t g_bKh[MK * CC / 2], g_bKl[MK * CC / 2];
__device__ uint32_t g_bVh[MK * CC / 2], g_bVl[MK * CC / 2];
__device__ uint32_t g_bWih[3 * CC * CC / 2], g_bWil[3 * CC * CC / 2];
__device__ uint32_t g_bWoh[CC * CC / 2],     g_bWol[CC * CC / 2];
__device__ uint32_t g_bAh[NQ * CC / 2],      g_bAl[NQ * CC / 2];

// ---------------------------------------------------------------------------
static __device__ __forceinline__ uint32_t smem_u32(const void* p) {
    uint32_t a;
    asm("{ .reg .u64 t; cvta.to.shared.u64 t, %1; cvt.u32.u64 %0, t; }" : "=r"(a) : "l"(p));
    return a;
}
static __device__ __forceinline__ uint32_t packbf(float f0, float f1) {
    uint32_t r;
    asm("cvt.rn.bf16x2.f32 %0, %1, %2;" : "=r"(r) : "f"(f1), "f"(f0));
    return r;
}
static __device__ __forceinline__ float bflo(uint32_t r) { return __uint_as_float(r << 16); }
static __device__ __forceinline__ float bfhi(uint32_t r) { return __uint_as_float(r & 0xffff0000u); }
static __device__ __forceinline__ void cpa16(uint32_t dst, const void* src) {
    asm volatile("cp.async.cg.shared.global [%0], [%1], 16;" :: "r"(dst), "l"(src) : "memory");
}
#define CP_COMMIT asm volatile("cp.async.commit_group;" ::: "memory")
#define CP_WAIT1  asm volatile("cp.async.wait_group 1;" ::: "memory")
#define CP_WAIT0  asm volatile("cp.async.wait_group 0;" ::: "memory")

#define MMA_BF16(c, a0, a1, a2, a3, b0, b1)                                   \
    asm volatile(                                                             \
        "mma.sync.aligned.m16n8k16.row.col.f32.bf16.bf16.f32 "                \
        "{%0,%1,%2,%3},{%4,%5,%6,%7},{%8,%9},{%0,%1,%2,%3};"                  \
        : "+f"((c)[0]), "+f"((c)[1]), "+f"((c)[2]), "+f"((c)[3])              \
        : "r"(a0), "r"(a1), "r"(a2), "r"(a3), "r"(b0), "r"(b1))

#define LDSM4(r, a)                                                           \
    asm volatile("ldmatrix.sync.aligned.m8n8.x4.shared.b16 {%0,%1,%2,%3}, [%4];" \
        : "=r"((r)[0]), "=r"((r)[1]), "=r"((r)[2]), "=r"((r)[3]) : "r"(a))
#define LDSM2(r0, r1, a)                                                      \
    asm volatile("ldmatrix.sync.aligned.m8n8.x2.shared.b16 {%0,%1}, [%2];"    \
        : "=r"(r0), "=r"(r1) : "r"(a))

// ---------------------------------------------------------------------------
__global__ void key_start_kernel(const int* __restrict__ key_batch_cnt) {
    if (threadIdx.x == 0) {
        int s = 0;
        for (int b = 0; b < BB; b++) { g_key_start[b] = s; s += key_batch_cnt[b]; }
    }
}

// fp32 -> (bf16 hi, bf16 lo) split; blockIdx.y selects q/k/v
__global__ void __launch_bounds__(256) cvt3_kernel(
    const float4* __restrict__ q, const float4* __restrict__ k,
    const float4* __restrict__ v)
{
    const int z = blockIdx.y;
    const float4* src = (z == 0) ? q : (z == 1) ? k : v;
    uint2* hi = (uint2*)((z == 0) ? g_bQh : (z == 1) ? g_bKh : g_bVh);
    uint2* lo = (uint2*)((z == 0) ? g_bQl : (z == 1) ? g_bKl : g_bVl);
    int i = blockIdx.x * blockDim.x + threadIdx.x;
    float4 f = src[i];
    uint32_t h0 = packbf(f.x, f.y);
    uint32_t h1 = packbf(f.z, f.w);
    uint32_t l0 = packbf(f.x - bflo(h0), f.y - bfhi(h0));
    uint32_t l1 = packbf(f.z - bflo(h1), f.w - bfhi(h1));
    hi[i] = make_uint2(h0, h1);
    lo[i] = make_uint2(l0, l1);
}

__global__ void __launch_bounds__(256) cvt_split_kernel(
    const float4* __restrict__ src, uint2* __restrict__ hi, uint2* __restrict__ lo, int n4)
{
    int i = blockIdx.x * blockDim.x + threadIdx.x;
    if (i >= n4) return;
    float4 f = src[i];
    uint32_t h0 = packbf(f.x, f.y);
    uint32_t h1 = packbf(f.z, f.w);
    uint32_t l0 = packbf(f.x - bflo(h0), f.y - bfhi(h0));
    uint32_t l1 = packbf(f.z - bflo(h1), f.w - bfhi(h1));
    hi[i] = make_uint2(h0, h1);
    lo[i] = make_uint2(l0, l1);
}

// ===========================================================================
// Split-bf16 HMMA GEMM with ldmatrix fragment loads (R12 champion, unchanged)
// ===========================================================================
#define SROWB 80
#define TILE_B (128 * SROWB)
#define STAGE_B (4 * TILE_B)
#define DSMEM_SIZE (2 * STAGE_B)

__device__ __forceinline__ void gemm_bf16_body(
    const uint32_t* __restrict__ Ah, const uint32_t* __restrict__ Al,
    const uint32_t* __restrict__ Bh, const uint32_t* __restrict__ Bl,
    const float* __restrict__ bias, float* __restrict__ Cout, float alpha)
{
    extern __shared__ char dsm[];
    const uint32_t sbase = smem_u32(dsm);

    const int t = threadIdx.x;
    const int lane = t & 31, warp = t >> 5;
    const int g = lane >> 2, tig = lane & 3;
    const int warpM = warp & 1, warpN = warp >> 1;
    const int row0 = blockIdx.y * 128, col0 = blockIdx.x * 128;

    const int lrow = lane & 7, lq = lane >> 3;
    const uint32_t aoff =
        (uint32_t)((warpM * 64 + lrow + (lq & 1) * 8) * SROWB) + (uint32_t)((lq >> 1) * 16);
    const uint32_t boff =
        (uint32_t)((warpN * 32 + lrow) * SROWB) + (uint32_t)((lq & 1) * 16);

    const int crow = t >> 1, chalf = t & 1;
    const uint32_t dstoff = (uint32_t)(crow * SROWB + chalf * 32);
    const size_t srcAbase = (size_t)(row0 + crow) * (CC / 2) + chalf * 8;
    const size_t srcBbase = (size_t)(col0 + crow) * (CC / 2) + chalf * 8;

    float acc[4][4][4];
#pragma unroll
    for (int m = 0; m < 4; m++)
#pragma unroll
        for (int n = 0; n < 4; n++)
#pragma unroll
            for (int j = 0; j < 4; j++) acc[m][n][j] = 0.0f;

#define ISSUE(kt, buf)                                                         \
    do {                                                                       \
        uint32_t sb = sbase + (buf) * STAGE_B;                                 \
        size_t ksrc = (size_t)(kt) * 16;                                       \
        cpa16(sb + dstoff,                  Ah + srcAbase + ksrc);             \
        cpa16(sb + dstoff + 16,             Ah + srcAbase + ksrc + 4);         \
        cpa16(sb + TILE_B + dstoff,         Al + srcAbase + ksrc);             \
        cpa16(sb + TILE_B + dstoff + 16,    Al + srcAbase + ksrc + 4);         \
        cpa16(sb + 2*TILE_B + dstoff,       Bh + srcBbase + ksrc);             \
        cpa16(sb + 2*TILE_B + dstoff + 16,  Bh + srcBbase + ksrc + 4);         \
        cpa16(sb + 3*TILE_B + dstoff,       Bl + srcBbase + ksrc);             \
        cpa16(sb + 3*TILE_B + dstoff + 16,  Bl + srcBbase + ksrc + 4);         \
    } while (0)

    const int NT = CC / 32;
    ISSUE(0, 0);
    CP_COMMIT;

    for (int kt = 0; kt < NT; kt++) {
        if (kt + 1 < NT) {
            ISSUE(kt + 1, (kt + 1) & 1);
            CP_COMMIT;
            CP_WAIT1;
        } else {
            CP_WAIT0;
        }
        __syncthreads();

        const uint32_t ab = sbase + (kt & 1) * STAGE_B;
#pragma unroll
        for (int sub = 0; sub < 2; sub++) {
            const uint32_t koff = sub * 32;
            const uint32_t aAddr = ab + aoff + koff;
            const uint32_t bAddr = ab + 2 * TILE_B + boff + koff;
            uint32_t af[4][4];

#pragma unroll
            for (int m = 0; m < 4; m++)
                LDSM4(af[m], aAddr + (uint32_t)(m * 16 * SROWB));
#pragma unroll
            for (int n = 0; n < 4; n++) {
                uint32_t bb = bAddr + (uint32_t)(n * 8 * SROWB);
                uint32_t bh0, bh1, bl0, bl1;
                LDSM2(bh0, bh1, bb);
                LDSM2(bl0, bl1, bb + TILE_B);
#pragma unroll
                for (int m = 0; m < 4; m++) {
                    MMA_BF16(acc[m][n], af[m][0], af[m][1], af[m][2], af[m][3], bh0, bh1);
                    MMA_BF16(acc[m][n], af[m][0], af[m][1], af[m][2], af[m][3], bl0, bl1);
                }
            }

#pragma unroll
            for (int m = 0; m < 4; m++)
                LDSM4(af[m], aAddr + TILE_B + (uint32_t)(m * 16 * SROWB));
#pragma unroll
            for (int n = 0; n < 4; n++) {
                uint32_t bh0, bh1;
                LDSM2(bh0, bh1, bAddr + (uint32_t)(n * 8 * SROWB));
#pragma unroll
                for (int m = 0; m < 4; m++)
                    MMA_BF16(acc[m][n], af[m][0], af[m][1], af[m][2], af[m][3], bh0, bh1);
            }
        }
        __syncthreads();
    }
#undef ISSUE

#pragma unroll
    for (int m = 0; m < 4; m++) {
        int rg = row0 + warpM * 64 + m * 16 + g;
#pragma unroll
        for (int n = 0; n < 4; n++) {
            int col = col0 + warpN * 32 + n * 8 + tig * 2;
            float b0 = __ldg(&bias[col]), b1 = __ldg(&bias[col + 1]);
            float2 o;
            o.x = alpha * (acc[m][n][0] + b0);
            o.y = alpha * (acc[m][n][1] + b1);
            *reinterpret_cast<float2*>(&Cout[(size_t)rg * CC + col]) = o;
            o.x = alpha * (acc[m][n][2] + b0);
            o.y = alpha * (acc[m][n][3] + b1);
            *reinterpret_cast<float2*>(&Cout[(size_t)(rg + 8) * CC + col]) = o;
        }
    }
}

__global__ void __launch_bounds__(256, 2) proj3_mma(const float* __restrict__ bin) {
    const int z = blockIdx.z;
    const uint32_t* Ahz = (z == 0) ? g_bQh : (z == 1) ? g_bKh : g_bVh;
    const uint32_t* Alz = (z == 0) ? g_bQl : (z == 1) ? g_bKl : g_bVl;
    float* Cz = (z == 0) ? g_q : (z == 1) ? g_k : g_v;
    const float alpha = (z == 0) ? 0.125f : 1.0f;
    gemm_bf16_body(Ahz, Alz,
                   g_bWih + (size_t)z * (CC * CC / 2),
                   g_bWil + (size_t)z * (CC * CC / 2),
                   bin + z * CC, Cz, alpha);
}

__global__ void __launch_bounds__(256, 2) outproj_mma(
    const float* __restrict__ bout, float* __restrict__ out) {
    gemm_bf16_body(g_bAh, g_bAl, g_bWoh, g_bWol, bout, out, 1.0f);
}

// ===========================================================================
// Sliced attention v4. CTA = (head, batch), 1024 threads.
// Phase 1: octet-broadcast conflict-free score gathers (unchanged).
// Phase 2: per-warp smem (w, row*KROW) pair buffer -> 2 MIO ops per l
//          (broadcast LDS.64 pair + LDS.64 v) instead of 2 SHFL + 1 LDS.
// ===========================================================================
#define KROW 68
#define PBUF_BASE (512 * KROW)                        // float index of pair bufs
#define ATTN_SMEM ((PBUF_BASE + 32 * 128) * 4)        // 155,648 B

__global__ void __launch_bounds__(1024) attn2_kernel(const int* __restrict__ index_pair)
{
    extern __shared__ float sk[];
    const int h = blockIdx.x, b = blockIdx.y;
    const int t = threadIdx.x, warp = t >> 5, lane = t & 31;
    const int qtr = lane >> 3, d_oct = lane & 7;
    const int ks = g_key_start[b];

    // ---- stage K slice [512 x 64] ----
    {
        int seg = t & 7;
#pragma unroll
        for (int p = 0; p < 4; p++) {
            int row = (t >> 3) + p * 128;
            const float4* src = reinterpret_cast<const float4*>(
                &g_k[(size_t)(ks + row) * CC + h * DD + seg * 8]);
            float4 v0 = src[0], v1 = src[1];
            *reinterpret_cast<float4*>(&sk[row * KROW + seg * 8])     = v0;
            *reinterpret_cast<float4*>(&sk[row * KROW + seg * 8 + 4]) = v1;
        }
    }
    __syncthreads();

    // ---- phase 1: scores + softmax -> g_w (16 queries per warp) ----
#pragma unroll 1
    for (int j = 0; j < 16; j++) {
        const int qi = warp + 32 * j;
        const int n = b * 512 + qi;
        int2 iv = *reinterpret_cast<const int2*>(&index_pair[n * LL + lane * 2]);
        const float* qb = &g_q[(size_t)n * CC + h * DD];
        float4 q0 = *reinterpret_cast<const float4*>(&qb[d_oct * 4]);
        float4 q1 = *reinterpret_cast<const float4*>(&qb[32 + d_oct * 4]);

        float sc[16];
#pragma unroll
        for (int li = 0; li < 16; li++) {
            int src = qtr * 8 + (li >> 1);
            int raw = __shfl_sync(0xffffffffu, (li & 1) ? iv.y : iv.x, src);
            int row = (raw >= 0) ? raw : 0;
            const float* kr = &sk[row * KROW];
            float4 k0 = *reinterpret_cast<const float4*>(&kr[d_oct * 4]);
            float4 k1 = *reinterpret_cast<const float4*>(&kr[32 + d_oct * 4]);
            float s = q0.x * k0.x;
            s = fmaf(q0.y, k0.y, s); s = fmaf(q0.z, k0.z, s); s = fmaf(q0.w, k0.w, s);
            s = fmaf(q1.x, k1.x, s); s = fmaf(q1.y, k1.y, s);
            s = fmaf(q1.z, k1.z, s); s = fmaf(q1.w, k1.w, s);
            s += __shfl_xor_sync(0xffffffffu, s, 1);
            s += __shfl_xor_sync(0xffffffffu, s, 2);
            s += __shfl_xor_sync(0xffffffffu, s, 4);
            sc[li] = (raw >= 0) ? s : -1000.0f;
        }

        float m = sc[0];
#pragma unroll
        for (int li = 1; li < 16; li++) m = fmaxf(m, sc[li]);
        m = fmaxf(m, __shfl_xor_sync(0xffffffffu, m, 8));
        m = fmaxf(m, __shfl_xor_sync(0xffffffffu, m, 16));
        float sum = 0.0f;
#pragma unroll
        for (int li = 0; li < 16; li++) { sc[li] = __expf(sc[li] - m); sum += sc[li]; }
        sum += __shfl_xor_sync(0xffffffffu, sum, 8);
        sum += __shfl_xor_sync(0xffffffffu, sum, 16);
        float inv = 1.0f / sum;

        float* wdst = &g_w[((size_t)h * NQ + n) * LL];
        wdst[qtr * 16 + d_oct]     = sc[d_oct] * inv;
        wdst[qtr * 16 + d_oct + 8] = sc[d_oct + 8] * inv;
    }
    __syncthreads();

    // ---- stage V slice (overwrite K) ----
    {
        int seg = t & 7;
#pragma unroll
        for (int p = 0; p < 4; p++) {
            int row = (t >> 3) + p * 128;
            const float4* src = reinterpret_cast<const float4*>(
                &g_v[(size_t)(ks + row) * CC + h * DD + seg * 8]);
            float4 v0 = src[0], v1 = src[1];
            *reinterpret_cast<float4*>(&sk[row * KROW + seg * 8])     = v0;
            *reinterpret_cast<float4*>(&sk[row * KROW + seg * 8 + 4]) = v1;
        }
    }
    __syncthreads();

    // ---- phase 2: weighted sum via smem pair buffer ----
    const int pbase = PBUF_BASE + warp * 128;
#pragma unroll 1
    for (int j = 0; j < 16; j++) {
        const int qi = warp + 32 * j;
        const int n = b * 512 + qi;
        float2 wv = *reinterpret_cast<const float2*>(
            &g_w[((size_t)h * NQ + n) * LL + lane * 2]);
        int2 iv = *reinterpret_cast<const int2*>(&index_pair[n * LL + lane * 2]);
        int r0 = ((iv.x >= 0) ? iv.x : 0) * KROW;
        int r1 = ((iv.y >= 0) ? iv.y : 0) * KROW;

        __syncwarp();                       // prior reads of pbuf done
        float4 st4;
        st4.x = wv.x; st4.y = __int_as_float(r0);
        st4.z = wv.y; st4.w = __int_as_float(r1);
        *reinterpret_cast<float4*>(&sk[pbase + lane * 4]) = st4;
        __syncwarp();                       // pairs visible warp-wide

        float2 acc = make_float2(0.0f, 0.0f);
#pragma unroll
        for (int l = 0; l < 64; l++) {
            float2 pr = *reinterpret_cast<const float2*>(&sk[pbase + l * 2]);
            int ro = __float_as_int(pr.y);
            float2 vv = *reinterpret_cast<const float2*>(&sk[ro + lane * 2]);
            acc.x = fmaf(pr.x, vv.x, acc.x);
            acc.y = fmaf(pr.x, vv.y, acc.y);
        }
        uint32_t hh = packbf(acc.x, acc.y);
        uint32_t ll = packbf(acc.x - bflo(hh), acc.y - bfhi(hh));
        size_t o2 = ((size_t)n * CC + h * DD + lane * 2) >> 1;
        g_bAh[o2] = hh;
        g_bAl[o2] = ll;
    }
}

// aux[n,l] = mean over heads of w
__global__ void __launch_bounds__(256) aux_kernel(float* __restrict__ aux_out) {
    int i = blockIdx.x * 256 + threadIdx.x;
    float s = 0.0f;
#pragma unroll
    for (int h = 0; h < HH; h++) s += g_w[(size_t)h * (NQ * LL) + i];
    aux_out[i] = s * 0.125f;
}

// ---------------------------------------------------------------------------
extern "C" void kernel_launch(void* const* d_in, const int* in_sizes, int n_in,
                              void* d_out, int out_size) {
    const float* query  = (const float*)d_in[0];
    const float* key    = (const float*)d_in[1];
    const float* value  = (const float*)d_in[2];
    const float* Win    = (const float*)d_in[3];
    const float* bin    = (const float*)d_in[4];
    const float* Wout   = (const float*)d_in[5];
    const float* bout   = (const float*)d_in[6];
    const int*   index_pair       = (const int*)d_in[7];
    const int*   key_batch_cnt    = (const int*)d_in[9];
    float* out = (float*)d_out;

    float* auxs;
    cudaGetSymbolAddress((void**)&auxs, g_aux_scratch);
    float* aux_out = (out_size >= NQ * CC + NQ * LL) ? (out + (size_t)NQ * CC) : auxs;

    uint32_t *bWih, *bWil, *bWoh, *bWol;
    cudaGetSymbolAddress((void**)&bWih, g_bWih); cudaGetSymbolAddress((void**)&bWil, g_bWil);
    cudaGetSymbolAddress((void**)&bWoh, g_bWoh); cudaGetSymbolAddress((void**)&bWol, g_bWol);

    cudaFuncSetAttribute(proj3_mma,    cudaFuncAttributeMaxDynamicSharedMemorySize, DSMEM_SIZE);
    cudaFuncSetAttribute(outproj_mma,  cudaFuncAttributeMaxDynamicSharedMemorySize, DSMEM_SIZE);
    cudaFuncSetAttribute(attn2_kernel, cudaFuncAttributeMaxDynamicSharedMemorySize, ATTN_SMEM);

    key_start_kernel<<<1, 32>>>(key_batch_cnt);

    dim3 gcvt(NQ * CC / 4 / 256, 3);
    cvt3_kernel<<<gcvt, 256>>>((const float4*)query, (const float4*)key,
                               (const float4*)value);
    cvt_split_kernel<<<3 * CC * CC / 4 / 256, 256>>>(
        (const float4*)Win, (uint2*)bWih, (uint2*)bWil, 3 * CC * CC / 4);
    cvt_split_kernel<<<CC * CC / 4 / 256, 256>>>(
        (const float4*)Wout, (uint2*)bWoh, (uint2*)bWol, CC * CC / 4);

    dim3 gproj(CC / 128, NQ / 128, 3);
    proj3_mma<<<gproj, 256, DSMEM_SIZE>>>(bin);

    dim3 gattn(HH, BB);
    attn2_kernel<<<gattn, 1024, ATTN_SMEM>>>(index_pair);

    aux_kernel<<<NQ * LL / 256, 256>>>(aux_out);

    dim3 gout(CC / 128, NQ / 128);
    outproj_mma<<<gout, 256, DSMEM_SIZE>>>(bout, out);
}

// round 14
// speedup vs baseline: 1.1694x; 1.0054x over previous
#include <cuda_runtime.h>
#include <cstdint>

#define NQ 8192
#define MK 8192
#define BB 16
#define CC 512
#define LL 64
#define HH 8
#define DD 64

// fp32 intermediates
__device__ float g_q[NQ * CC];
__device__ float g_k[MK * CC];
__device__ float g_v[MK * CC];
__device__ float g_w[HH * NQ * LL];     // softmax weights scratch (16 MB)
__device__ float g_aux_scratch[NQ * LL];
__device__ int   g_key_start[BB];

// bf16 split operands (hi/lo), packed 2 elements per uint32
__device__ uint32_t g_bQh[NQ * CC / 2], g_bQl[NQ * CC / 2];
__device__ uint32_t g_bKh[MK * CC / 2], g_bKl[MK * CC / 2];
__device__ uint32_t g_bVh[MK * CC / 2], g_bVl[MK * CC / 2];
__device__ uint32_t g_bWih[3 * CC * CC / 2], g_bWil[3 * CC * CC / 2];
__device__ uint32_t g_bWoh[CC * CC / 2],     g_bWol[CC * CC / 2];
__device__ uint32_t g_bAh[NQ * CC / 2],      g_bAl[NQ * CC / 2];

// ---------------------------------------------------------------------------
static __device__ __forceinline__ uint32_t smem_u32(const void* p) {
    uint32_t a;
    asm("{ .reg .u64 t; cvta.to.shared.u64 t, %1; cvt.u32.u64 %0, t; }" : "=r"(a) : "l"(p));
    return a;
}
static __device__ __forceinline__ uint32_t packbf(float f0, float f1) {
    uint32_t r;
    asm("cvt.rn.bf16x2.f32 %0, %1, %2;" : "=r"(r) : "f"(f1), "f"(f0));
    return r;
}
static __device__ __forceinline__ float bflo(uint32_t r) { return __uint_as_float(r << 16); }
static __device__ __forceinline__ float bfhi(uint32_t r) { return __uint_as_float(r & 0xffff0000u); }
static __device__ __forceinline__ void cpa16(uint32_t dst, const void* src) {
    asm volatile("cp.async.cg.shared.global [%0], [%1], 16;" :: "r"(dst), "l"(src) : "memory");
}
#define CP_COMMIT asm volatile("cp.async.commit_group;" ::: "memory")
#define CP_WAIT1  asm volatile("cp.async.wait_group 1;" ::: "memory")
#define CP_WAIT0  asm volatile("cp.async.wait_group 0;" ::: "memory")

#define MMA_BF16(c, a0, a1, a2, a3, b0, b1)                                   \
    asm volatile(                                                             \
        "mma.sync.aligned.m16n8k16.row.col.f32.bf16.bf16.f32 "                \
        "{%0,%1,%2,%3},{%4,%5,%6,%7},{%8,%9},{%0,%1,%2,%3};"                  \
        : "+f"((c)[0]), "+f"((c)[1]), "+f"((c)[2]), "+f"((c)[3])              \
        : "r"(a0), "r"(a1), "r"(a2), "r"(a3), "r"(b0), "r"(b1))

#define LDSM4(r, a)                                                           \
    asm volatile("ldmatrix.sync.aligned.m8n8.x4.shared.b16 {%0,%1,%2,%3}, [%4];" \
        : "=r"((r)[0]), "=r"((r)[1]), "=r"((r)[2]), "=r"((r)[3]) : "r"(a))
#define LDSM2(r0, r1, a)                                                      \
    asm volatile("ldmatrix.sync.aligned.m8n8.x2.shared.b16 {%0,%1}, [%2];"    \
        : "=r"(r0), "=r"(r1) : "r"(a))

// ---------------------------------------------------------------------------
__global__ void key_start_kernel(const int* __restrict__ key_batch_cnt) {
    if (threadIdx.x == 0) {
        int s = 0;
        for (int b = 0; b < BB; b++) { g_key_start[b] = s; s += key_batch_cnt[b]; }
    }
}

// fp32 -> (bf16 hi, bf16 lo) split; blockIdx.y selects q/k/v
__global__ void __launch_bounds__(256) cvt3_kernel(
    const float4* __restrict__ q, const float4* __restrict__ k,
    const float4* __restrict__ v)
{
    const int z = blockIdx.y;
    const float4* src = (z == 0) ? q : (z == 1) ? k : v;
    uint2* hi = (uint2*)((z == 0) ? g_bQh : (z == 1) ? g_bKh : g_bVh);
    uint2* lo = (uint2*)((z == 0) ? g_bQl : (z == 1) ? g_bKl : g_bVl);
    int i = blockIdx.x * blockDim.x + threadIdx.x;
    float4 f = src[i];
    uint32_t h0 = packbf(f.x, f.y);
    uint32_t h1 = packbf(f.z, f.w);
    uint32_t l0 = packbf(f.x - bflo(h0), f.y - bfhi(h0));
    uint32_t l1 = packbf(f.z - bflo(h1), f.w - bfhi(h1));
    hi[i] = make_uint2(h0, h1);
    lo[i] = make_uint2(l0, l1);
}

__global__ void __launch_bounds__(256) cvt_split_kernel(
    const float4* __restrict__ src, uint2* __restrict__ hi, uint2* __restrict__ lo, int n4)
{
    int i = blockIdx.x * blockDim.x + threadIdx.x;
    if (i >= n4) return;
    float4 f = src[i];
    uint32_t h0 = packbf(f.x, f.y);
    uint32_t h1 = packbf(f.z, f.w);
    uint32_t l0 = packbf(f.x - bflo(h0), f.y - bfhi(h0));
    uint32_t l1 = packbf(f.z - bflo(h1), f.w - bfhi(h1));
    hi[i] = make_uint2(h0, h1);
    lo[i] = make_uint2(l0, l1);
}

// ===========================================================================
// Split-bf16 HMMA GEMM with ldmatrix fragment loads (champion, unchanged)
// ===========================================================================
#define SROWB 80
#define TILE_B (128 * SROWB)
#define STAGE_B (4 * TILE_B)
#define DSMEM_SIZE (2 * STAGE_B)

__device__ __forceinline__ void gemm_bf16_body(
    const uint32_t* __restrict__ Ah, const uint32_t* __restrict__ Al,
    const uint32_t* __restrict__ Bh, const uint32_t* __restrict__ Bl,
    const float* __restrict__ bias, float* __restrict__ Cout, float alpha)
{
    extern __shared__ char dsm[];
    const uint32_t sbase = smem_u32(dsm);

    const int t = threadIdx.x;
    const int lane = t & 31, warp = t >> 5;
    const int g = lane >> 2, tig = lane & 3;
    const int warpM = warp & 1, warpN = warp >> 1;
    const int row0 = blockIdx.y * 128, col0 = blockIdx.x * 128;

    const int lrow = lane & 7, lq = lane >> 3;
    const uint32_t aoff =
        (uint32_t)((warpM * 64 + lrow + (lq & 1) * 8) * SROWB) + (uint32_t)((lq >> 1) * 16);
    const uint32_t boff =
        (uint32_t)((warpN * 32 + lrow) * SROWB) + (uint32_t)((lq & 1) * 16);

    const int crow = t >> 1, chalf = t & 1;
    const uint32_t dstoff = (uint32_t)(crow * SROWB + chalf * 32);
    const size_t srcAbase = (size_t)(row0 + crow) * (CC / 2) + chalf * 8;
    const size_t srcBbase = (size_t)(col0 + crow) * (CC / 2) + chalf * 8;

    float acc[4][4][4];
#pragma unroll
    for (int m = 0; m < 4; m++)
#pragma unroll
        for (int n = 0; n < 4; n++)
#pragma unroll
            for (int j = 0; j < 4; j++) acc[m][n][j] = 0.0f;

#define ISSUE(kt, buf)                                                         \
    do {                                                                       \
        uint32_t sb = sbase + (buf) * STAGE_B;                                 \
        size_t ksrc = (size_t)(kt) * 16;                                       \
        cpa16(sb + dstoff,                  Ah + srcAbase + ksrc);             \
        cpa16(sb + dstoff + 16,             Ah + srcAbase + ksrc + 4);         \
        cpa16(sb + TILE_B + dstoff,         Al + srcAbase + ksrc);             \
        cpa16(sb + TILE_B + dstoff + 16,    Al + srcAbase + ksrc + 4);         \
        cpa16(sb + 2*TILE_B + dstoff,       Bh + srcBbase + ksrc);             \
        cpa16(sb + 2*TILE_B + dstoff + 16,  Bh + srcBbase + ksrc + 4);         \
        cpa16(sb + 3*TILE_B + dstoff,       Bl + srcBbase + ksrc);             \
        cpa16(sb + 3*TILE_B + dstoff + 16,  Bl + srcBbase + ksrc + 4);         \
    } while (0)

    const int NT = CC / 32;
    ISSUE(0, 0);
    CP_COMMIT;

    for (int kt = 0; kt < NT; kt++) {
        if (kt + 1 < NT) {
            ISSUE(kt + 1, (kt + 1) & 1);
            CP_COMMIT;
            CP_WAIT1;
        } else {
            CP_WAIT0;
        }
        __syncthreads();

        const uint32_t ab = sbase + (kt & 1) * STAGE_B;
#pragma unroll
        for (int sub = 0; sub < 2; sub++) {
            const uint32_t koff = sub * 32;
            const uint32_t aAddr = ab + aoff + koff;
            const uint32_t bAddr = ab + 2 * TILE_B + boff + koff;
            uint32_t af[4][4];

#pragma unroll
            for (int m = 0; m < 4; m++)
                LDSM4(af[m], aAddr + (uint32_t)(m * 16 * SROWB));
#pragma unroll
            for (int n = 0; n < 4; n++) {
                uint32_t bb = bAddr + (uint32_t)(n * 8 * SROWB);
                uint32_t bh0, bh1, bl0, bl1;
                LDSM2(bh0, bh1, bb);
                LDSM2(bl0, bl1, bb + TILE_B);
#pragma unroll
                for (int m = 0; m < 4; m++) {
                    MMA_BF16(acc[m][n], af[m][0], af[m][1], af[m][2], af[m][3], bh0, bh1);
                    MMA_BF16(acc[m][n], af[m][0], af[m][1], af[m][2], af[m][3], bl0, bl1);
                }
            }

#pragma unroll
            for (int m = 0; m < 4; m++)
                LDSM4(af[m], aAddr + TILE_B + (uint32_t)(m * 16 * SROWB));
#pragma unroll
            for (int n = 0; n < 4; n++) {
                uint32_t bh0, bh1;
                LDSM2(bh0, bh1, bAddr + (uint32_t)(n * 8 * SROWB));
#pragma unroll
                for (int m = 0; m < 4; m++)
                    MMA_BF16(acc[m][n], af[m][0], af[m][1], af[m][2], af[m][3], bh0, bh1);
            }
        }
        __syncthreads();
    }
#undef ISSUE

#pragma unroll
    for (int m = 0; m < 4; m++) {
        int rg = row0 + warpM * 64 + m * 16 + g;
#pragma unroll
        for (int n = 0; n < 4; n++) {
            int col = col0 + warpN * 32 + n * 8 + tig * 2;
            float b0 = __ldg(&bias[col]), b1 = __ldg(&bias[col + 1]);
            float2 o;
            o.x = alpha * (acc[m][n][0] + b0);
            o.y = alpha * (acc[m][n][1] + b1);
            *reinterpret_cast<float2*>(&Cout[(size_t)rg * CC + col]) = o;
            o.x = alpha * (acc[m][n][2] + b0);
            o.y = alpha * (acc[m][n][3] + b1);
            *reinterpret_cast<float2*>(&Cout[(size_t)(rg + 8) * CC + col]) = o;
        }
    }
}

__global__ void __launch_bounds__(256, 2) proj3_mma(const float* __restrict__ bin) {
    const int z = blockIdx.z;
    const uint32_t* Ahz = (z == 0) ? g_bQh : (z == 1) ? g_bKh : g_bVh;
    const uint32_t* Alz = (z == 0) ? g_bQl : (z == 1) ? g_bKl : g_bVl;
    float* Cz = (z == 0) ? g_q : (z == 1) ? g_k : g_v;
    const float alpha = (z == 0) ? 0.125f : 1.0f;
    gemm_bf16_body(Ahz, Alz,
                   g_bWih + (size_t)z * (CC * CC / 2),
                   g_bWil + (size_t)z * (CC * CC / 2),
                   bin + z * CC, Cz, alpha);
}

__global__ void __launch_bounds__(256, 2) outproj_mma(
    const float* __restrict__ bout, float* __restrict__ out) {
    gemm_bf16_body(g_bAh, g_bAl, g_bWoh, g_bWol, bout, out, 1.0f);
}

// ===========================================================================
// Sliced attention v5. CTA = (head, batch), 1024 threads.
// - K/V staged via cp.async (16B chunks).
// - Per-query global loads software-pipelined (prefetch j+1 during j).
// - Phase 1: octet-broadcast conflict-free score gathers.
// - Phase 2: per-warp smem pair buffer (2 MIO ops per l).
// ===========================================================================
#define KROW 68
#define PBUF_BASE (512 * KROW)
#define ATTN_SMEM ((PBUF_BASE + 32 * 128) * 4)

__global__ void __launch_bounds__(1024) attn2_kernel(const int* __restrict__ index_pair)
{
    extern __shared__ float sk[];
    const uint32_t skaddr = smem_u32(sk);
    const int h = blockIdx.x, b = blockIdx.y;
    const int t = threadIdx.x, warp = t >> 5, lane = t & 31;
    const int qtr = lane >> 3, d_oct = lane & 7;
    const int ks = g_key_start[b];

    // ---- stage K slice [512 x 64] via cp.async ----
    {
        int seg = t & 15;           // 16B chunk 0..15
        int r0 = t >> 4;            // 0..63
#pragma unroll
        for (int p = 0; p < 8; p++) {
            int row = r0 + p * 64;
            cpa16(skaddr + (uint32_t)(row * KROW * 4 + seg * 16),
                  &g_k[(size_t)(ks + row) * CC + h * DD + seg * 4]);
        }
        CP_COMMIT; CP_WAIT0;
    }
    __syncthreads();

    // ---- phase 1: scores + softmax -> g_w (16 queries per warp, pipelined) --
    {
        int n0 = b * 512 + warp;
        int2 iv = *reinterpret_cast<const int2*>(&index_pair[n0 * LL + lane * 2]);
        const float* qb0 = &g_q[(size_t)n0 * CC + h * DD];
        float4 q0 = *reinterpret_cast<const float4*>(&qb0[d_oct * 4]);
        float4 q1 = *reinterpret_cast<const float4*>(&qb0[32 + d_oct * 4]);

#pragma unroll 1
        for (int j = 0; j < 16; j++) {
            const int n = b * 512 + warp + 32 * j;
            // prefetch next query's globals
            int2 ivn; float4 q0n, q1n;
            if (j < 15) {
                int nn = n + 32;
                ivn = *reinterpret_cast<const int2*>(&index_pair[nn * LL + lane * 2]);
                const float* qbn = &g_q[(size_t)nn * CC + h * DD];
                q0n = *reinterpret_cast<const float4*>(&qbn[d_oct * 4]);
                q1n = *reinterpret_cast<const float4*>(&qbn[32 + d_oct * 4]);
            }

            float sc[16];
#pragma unroll
            for (int li = 0; li < 16; li++) {
                int src = qtr * 8 + (li >> 1);
                int raw = __shfl_sync(0xffffffffu, (li & 1) ? iv.y : iv.x, src);
                int row = (raw >= 0) ? raw : 0;
                const float* kr = &sk[row * KROW];
                float4 k0 = *reinterpret_cast<const float4*>(&kr[d_oct * 4]);
                float4 k1 = *reinterpret_cast<const float4*>(&kr[32 + d_oct * 4]);
                float s = q0.x * k0.x;
                s = fmaf(q0.y, k0.y, s); s = fmaf(q0.z, k0.z, s); s = fmaf(q0.w, k0.w, s);
                s = fmaf(q1.x, k1.x, s); s = fmaf(q1.y, k1.y, s);
                s = fmaf(q1.z, k1.z, s); s = fmaf(q1.w, k1.w, s);
                s += __shfl_xor_sync(0xffffffffu, s, 1);
                s += __shfl_xor_sync(0xffffffffu, s, 2);
                s += __shfl_xor_sync(0xffffffffu, s, 4);
                sc[li] = (raw >= 0) ? s : -1000.0f;
            }

            float m = sc[0];
#pragma unroll
            for (int li = 1; li < 16; li++) m = fmaxf(m, sc[li]);
            m = fmaxf(m, __shfl_xor_sync(0xffffffffu, m, 8));
            m = fmaxf(m, __shfl_xor_sync(0xffffffffu, m, 16));
            float sum = 0.0f;
#pragma unroll
            for (int li = 0; li < 16; li++) { sc[li] = __expf(sc[li] - m); sum += sc[li]; }
            sum += __shfl_xor_sync(0xffffffffu, sum, 8);
            sum += __shfl_xor_sync(0xffffffffu, sum, 16);
            float inv = 1.0f / sum;

            float* wdst = &g_w[((size_t)h * NQ + n) * LL];
            wdst[qtr * 16 + d_oct]     = sc[d_oct] * inv;
            wdst[qtr * 16 + d_oct + 8] = sc[d_oct + 8] * inv;

            iv = ivn; q0 = q0n; q1 = q1n;
        }
    }
    __syncthreads();

    // ---- stage V slice (overwrite K) via cp.async ----
    {
        int seg = t & 15;
        int r0 = t >> 4;
#pragma unroll
        for (int p = 0; p < 8; p++) {
            int row = r0 + p * 64;
            cpa16(skaddr + (uint32_t)(row * KROW * 4 + seg * 16),
                  &g_v[(size_t)(ks + row) * CC + h * DD + seg * 4]);
        }
        CP_COMMIT; CP_WAIT0;
    }
    __syncthreads();

    // ---- phase 2: weighted sum via smem pair buffer (pipelined) ----
    {
        const int pbase = PBUF_BASE + warp * 128;
        int n0 = b * 512 + warp;
        float2 wv = *reinterpret_cast<const float2*>(
            &g_w[((size_t)h * NQ + n0) * LL + lane * 2]);
        int2 iv = *reinterpret_cast<const int2*>(&index_pair[n0 * LL + lane * 2]);

#pragma unroll 1
        for (int j = 0; j < 16; j++) {
            const int n = b * 512 + warp + 32 * j;
            float2 wvn; int2 ivn;
            if (j < 15) {
                int nn = n + 32;
                wvn = *reinterpret_cast<const float2*>(
                    &g_w[((size_t)h * NQ + nn) * LL + lane * 2]);
                ivn = *reinterpret_cast<const int2*>(&index_pair[nn * LL + lane * 2]);
            }

            int r0 = ((iv.x >= 0) ? iv.x : 0) * KROW;
            int r1 = ((iv.y >= 0) ? iv.y : 0) * KROW;

            __syncwarp();
            float4 st4;
            st4.x = wv.x; st4.y = __int_as_float(r0);
            st4.z = wv.y; st4.w = __int_as_float(r1);
            *reinterpret_cast<float4*>(&sk[pbase + lane * 4]) = st4;
            __syncwarp();

            float2 acc = make_float2(0.0f, 0.0f);
#pragma unroll
            for (int l = 0; l < 64; l++) {
                float2 pr = *reinterpret_cast<const float2*>(&sk[pbase + l * 2]);
                int ro = __float_as_int(pr.y);
                float2 vv = *reinterpret_cast<const float2*>(&sk[ro + lane * 2]);
                acc.x = fmaf(pr.x, vv.x, acc.x);
                acc.y = fmaf(pr.x, vv.y, acc.y);
            }
            uint32_t hh = packbf(acc.x, acc.y);
            uint32_t ll = packbf(acc.x - bflo(hh), acc.y - bfhi(hh));
            size_t o2 = ((size_t)n * CC + h * DD + lane * 2) >> 1;
            g_bAh[o2] = hh;
            g_bAl[o2] = ll;

            wv = wvn; iv = ivn;
        }
    }
}

// aux[n,l] = mean over heads of w
__global__ void __launch_bounds__(256) aux_kernel(float* __restrict__ aux_out) {
    int i = blockIdx.x * 256 + threadIdx.x;
    float s = 0.0f;
#pragma unroll
    for (int h = 0; h < HH; h++) s += g_w[(size_t)h * (NQ * LL) + i];
    aux_out[i] = s * 0.125f;
}

// ---------------------------------------------------------------------------
extern "C" void kernel_launch(void* const* d_in, const int* in_sizes, int n_in,
                              void* d_out, int out_size) {
    const float* query  = (const float*)d_in[0];
    const float* key    = (const float*)d_in[1];
    const float* value  = (const float*)d_in[2];
    const float* Win    = (const float*)d_in[3];
    const float* bin    = (const float*)d_in[4];
    const float* Wout   = (const float*)d_in[5];
    const float* bout   = (const float*)d_in[6];
    const int*   index_pair       = (const int*)d_in[7];
    const int*   key_batch_cnt    = (const int*)d_in[9];
    float* out = (float*)d_out;

    float* auxs;
    cudaGetSymbolAddress((void**)&auxs, g_aux_scratch);
    float* aux_out = (out_size >= NQ * CC + NQ * LL) ? (out + (size_t)NQ * CC) : auxs;

    uint32_t *bWih, *bWil, *bWoh, *bWol;
    cudaGetSymbolAddress((void**)&bWih, g_bWih); cudaGetSymbolAddress((void**)&bWil, g_bWil);
    cudaGetSymbolAddress((void**)&bWoh, g_bWoh); cudaGetSymbolAddress((void**)&bWol, g_bWol);

    cudaFuncSetAttribute(proj3_mma,    cudaFuncAttributeMaxDynamicSharedMemorySize, DSMEM_SIZE);
    cudaFuncSetAttribute(outproj_mma,  cudaFuncAttributeMaxDynamicSharedMemorySize, DSMEM_SIZE);
    cudaFuncSetAttribute(attn2_kernel, cudaFuncAttributeMaxDynamicSharedMemorySize, ATTN_SMEM);

    key_start_kernel<<<1, 32>>>(key_batch_cnt);

    dim3 gcvt(NQ * CC / 4 / 256, 3);
    cvt3_kernel<<<gcvt, 256>>>((const float4*)query, (const float4*)key,
                               (const float4*)value);
    cvt_split_kernel<<<3 * CC * CC / 4 / 256, 256>>>(
        (const float4*)Win, (uint2*)bWih, (uint2*)bWil, 3 * CC * CC / 4);
    cvt_split_kernel<<<CC * CC / 4 / 256, 256>>>(
        (const float4*)Wout, (uint2*)bWoh, (uint2*)bWol, CC * CC / 4);

    dim3 gproj(CC / 128, NQ / 128, 3);
    proj3_mma<<<gproj, 256, DSMEM_SIZE>>>(bin);

    dim3 gattn(HH, BB);
    attn2_kernel<<<gattn, 1024, ATTN_SMEM>>>(index_pair);

    aux_kernel<<<NQ * LL / 256, 256>>>(aux_out);

    dim3 gout(CC / 128, NQ / 128);
    outproj_mma<<<gout, 256, DSMEM_SIZE>>>(bout, out);
}

// round 15
// speedup vs baseline: 1.1820x; 1.0108x over previous
#include <cuda_runtime.h>
#include <cstdint>

#define NQ 8192
#define MK 8192
#define BB 16
#define CC 512
#define LL 64
#define HH 8
#define DD 64

// fp32 intermediates
__device__ float g_q[NQ * CC];
__device__ float g_k[MK * CC];
__device__ float g_v[MK * CC];
__device__ float g_w[HH * NQ * LL];     // softmax weights scratch (16 MB)
__device__ float g_aux_scratch[NQ * LL];
__device__ int   g_key_start[BB];

// bf16 split operands (hi/lo), packed 2 elements per uint32
__device__ uint32_t g_bQh[NQ * CC / 2], g_bQl[NQ * CC / 2];
__device__ uint32_t g_bKh[MK * CC / 2], g_bKl[MK * CC / 2];
__device__ uint32_t g_bVh[MK * CC / 2], g_bVl[MK * CC / 2];
__device__ uint32_t g_bWih[3 * CC * CC / 2], g_bWil[3 * CC * CC / 2];
__device__ uint32_t g_bWoh[CC * CC / 2],     g_bWol[CC * CC / 2];
__device__ uint32_t g_bAh[NQ * CC / 2],      g_bAl[NQ * CC / 2];

// ---------------------------------------------------------------------------
static __device__ __forceinline__ uint32_t smem_u32(const void* p) {
    uint32_t a;
    asm("{ .reg .u64 t; cvta.to.shared.u64 t, %1; cvt.u32.u64 %0, t; }" : "=r"(a) : "l"(p));
    return a;
}
static __device__ __forceinline__ uint32_t packbf(float f0, float f1) {
    uint32_t r;
    asm("cvt.rn.bf16x2.f32 %0, %1, %2;" : "=r"(r) : "f"(f1), "f"(f0));
    return r;
}
static __device__ __forceinline__ float bflo(uint32_t r) { return __uint_as_float(r << 16); }
static __device__ __forceinline__ float bfhi(uint32_t r) { return __uint_as_float(r & 0xffff0000u); }
static __device__ __forceinline__ void cpa16(uint32_t dst, const void* src) {
    asm volatile("cp.async.cg.shared.global [%0], [%1], 16;" :: "r"(dst), "l"(src) : "memory");
}
#define CP_COMMIT asm volatile("cp.async.commit_group;" ::: "memory")
#define CP_WAIT1  asm volatile("cp.async.wait_group 1;" ::: "memory")
#define CP_WAIT0  asm volatile("cp.async.wait_group 0;" ::: "memory")

#define MMA_BF16(c, a0, a1, a2, a3, b0, b1)                                   \
    asm volatile(                                                             \
        "mma.sync.aligned.m16n8k16.row.col.f32.bf16.bf16.f32 "                \
        "{%0,%1,%2,%3},{%4,%5,%6,%7},{%8,%9},{%0,%1,%2,%3};"                  \
        : "+f"((c)[0]), "+f"((c)[1]), "+f"((c)[2]), "+f"((c)[3])              \
        : "r"(a0), "r"(a1), "r"(a2), "r"(a3), "r"(b0), "r"(b1))

#define LDSM4(r, a)                                                           \
    asm volatile("ldmatrix.sync.aligned.m8n8.x4.shared.b16 {%0,%1,%2,%3}, [%4];" \
        : "=r"((r)[0]), "=r"((r)[1]), "=r"((r)[2]), "=r"((r)[3]) : "r"(a))
#define LDSM2(r0, r1, a)                                                      \
    asm volatile("ldmatrix.sync.aligned.m8n8.x2.shared.b16 {%0,%1}, [%2];"    \
        : "=r"(r0), "=r"(r1) : "r"(a))

// ---------------------------------------------------------------------------
// Fused conversion: one grid covers q, k, v, Win, Wout splits + key_start.
// Region boundaries in float4 units.
#define N4_QKV (NQ * CC / 4)              // 1,048,576 each
#define N4_WI  (3 * CC * CC / 4)          // 196,608
#define N4_WO  (CC * CC / 4)              // 65,536
#define N4_TOTAL (3 * N4_QKV + N4_WI + N4_WO)

__global__ void __launch_bounds__(256) cvt_all_kernel(
    const float4* __restrict__ q, const float4* __restrict__ k,
    const float4* __restrict__ v, const float4* __restrict__ Win,
    const float4* __restrict__ Wout, const int* __restrict__ key_batch_cnt)
{
    if (blockIdx.x == 0 && threadIdx.x == 0) {
        int s = 0;
        for (int b = 0; b < BB; b++) { g_key_start[b] = s; s += key_batch_cnt[b]; }
    }

    int i = blockIdx.x * blockDim.x + threadIdx.x;
    if (i >= N4_TOTAL) return;

    const float4* src;
    uint2 *hi, *lo;
    int ri;
    if (i < N4_QKV) {
        src = q;  hi = (uint2*)g_bQh;  lo = (uint2*)g_bQl;  ri = i;
    } else if (i < 2 * N4_QKV) {
        src = k;  hi = (uint2*)g_bKh;  lo = (uint2*)g_bKl;  ri = i - N4_QKV;
    } else if (i < 3 * N4_QKV) {
        src = v;  hi = (uint2*)g_bVh;  lo = (uint2*)g_bVl;  ri = i - 2 * N4_QKV;
    } else if (i < 3 * N4_QKV + N4_WI) {
        src = Win;  hi = (uint2*)g_bWih;  lo = (uint2*)g_bWil;  ri = i - 3 * N4_QKV;
    } else {
        src = Wout; hi = (uint2*)g_bWoh;  lo = (uint2*)g_bWol;  ri = i - 3 * N4_QKV - N4_WI;
    }

    float4 f = src[ri];
    uint32_t h0 = packbf(f.x, f.y);
    uint32_t h1 = packbf(f.z, f.w);
    uint32_t l0 = packbf(f.x - bflo(h0), f.y - bfhi(h0));
    uint32_t l1 = packbf(f.z - bflo(h1), f.w - bfhi(h1));
    hi[ri] = make_uint2(h0, h1);
    lo[ri] = make_uint2(l0, l1);
}

// ===========================================================================
// Split-bf16 HMMA GEMM with ldmatrix fragment loads (champion, unchanged)
// ===========================================================================
#define SROWB 80
#define TILE_B (128 * SROWB)
#define STAGE_B (4 * TILE_B)
#define DSMEM_SIZE (2 * STAGE_B)

__device__ __forceinline__ void gemm_bf16_body(
    const uint32_t* __restrict__ Ah, const uint32_t* __restrict__ Al,
    const uint32_t* __restrict__ Bh, const uint32_t* __restrict__ Bl,
    const float* __restrict__ bias, float* __restrict__ Cout, float alpha)
{
    extern __shared__ char dsm[];
    const uint32_t sbase = smem_u32(dsm);

    const int t = threadIdx.x;
    const int lane = t & 31, warp = t >> 5;
    const int g = lane >> 2, tig = lane & 3;
    const int warpM = warp & 1, warpN = warp >> 1;
    const int row0 = blockIdx.y * 128, col0 = blockIdx.x * 128;

    const int lrow = lane & 7, lq = lane >> 3;
    const uint32_t aoff =
        (uint32_t)((warpM * 64 + lrow + (lq & 1) * 8) * SROWB) + (uint32_t)((lq >> 1) * 16);
    const uint32_t boff =
        (uint32_t)((warpN * 32 + lrow) * SROWB) + (uint32_t)((lq & 1) * 16);

    const int crow = t >> 1, chalf = t & 1;
    const uint32_t dstoff = (uint32_t)(crow * SROWB + chalf * 32);
    const size_t srcAbase = (size_t)(row0 + crow) * (CC / 2) + chalf * 8;
    const size_t srcBbase = (size_t)(col0 + crow) * (CC / 2) + chalf * 8;

    float acc[4][4][4];
#pragma unroll
    for (int m = 0; m < 4; m++)
#pragma unroll
        for (int n = 0; n < 4; n++)
#pragma unroll
            for (int j = 0; j < 4; j++) acc[m][n][j] = 0.0f;

#define ISSUE(kt, buf)                                                         \
    do {                                                                       \
        uint32_t sb = sbase + (buf) * STAGE_B;                                 \
        size_t ksrc = (size_t)(kt) * 16;                                       \
        cpa16(sb + dstoff,                  Ah + srcAbase + ksrc);             \
        cpa16(sb + dstoff + 16,             Ah + srcAbase + ksrc + 4);         \
        cpa16(sb + TILE_B + dstoff,         Al + srcAbase + ksrc);             \
        cpa16(sb + TILE_B + dstoff + 16,    Al + srcAbase + ksrc + 4);         \
        cpa16(sb + 2*TILE_B + dstoff,       Bh + srcBbase + ksrc);             \
        cpa16(sb + 2*TILE_B + dstoff + 16,  Bh + srcBbase + ksrc + 4);         \
        cpa16(sb + 3*TILE_B + dstoff,       Bl + srcBbase + ksrc);             \
        cpa16(sb + 3*TILE_B + dstoff + 16,  Bl + srcBbase + ksrc + 4);         \
    } while (0)

    const int NT = CC / 32;
    ISSUE(0, 0);
    CP_COMMIT;

    for (int kt = 0; kt < NT; kt++) {
        if (kt + 1 < NT) {
            ISSUE(kt + 1, (kt + 1) & 1);
            CP_COMMIT;
            CP_WAIT1;
        } else {
            CP_WAIT0;
        }
        __syncthreads();

        const uint32_t ab = sbase + (kt & 1) * STAGE_B;
#pragma unroll
        for (int sub = 0; sub < 2; sub++) {
            const uint32_t koff = sub * 32;
            const uint32_t aAddr = ab + aoff + koff;
            const uint32_t bAddr = ab + 2 * TILE_B + boff + koff;
            uint32_t af[4][4];

#pragma unroll
            for (int m = 0; m < 4; m++)
                LDSM4(af[m], aAddr + (uint32_t)(m * 16 * SROWB));
#pragma unroll
            for (int n = 0; n < 4; n++) {
                uint32_t bb = bAddr + (uint32_t)(n * 8 * SROWB);
                uint32_t bh0, bh1, bl0, bl1;
                LDSM2(bh0, bh1, bb);
                LDSM2(bl0, bl1, bb + TILE_B);
#pragma unroll
                for (int m = 0; m < 4; m++) {
                    MMA_BF16(acc[m][n], af[m][0], af[m][1], af[m][2], af[m][3], bh0, bh1);
                    MMA_BF16(acc[m][n], af[m][0], af[m][1], af[m][2], af[m][3], bl0, bl1);
                }
            }

#pragma unroll
            for (int m = 0; m < 4; m++)
                LDSM4(af[m], aAddr + TILE_B + (uint32_t)(m * 16 * SROWB));
#pragma unroll
            for (int n = 0; n < 4; n++) {
                uint32_t bh0, bh1;
                LDSM2(bh0, bh1, bAddr + (uint32_t)(n * 8 * SROWB));
#pragma unroll
                for (int m = 0; m < 4; m++)
                    MMA_BF16(acc[m][n], af[m][0], af[m][1], af[m][2], af[m][3], bh0, bh1);
            }
        }
        __syncthreads();
    }
#undef ISSUE

#pragma unroll
    for (int m = 0; m < 4; m++) {
        int rg = row0 + warpM * 64 + m * 16 + g;
#pragma unroll
        for (int n = 0; n < 4; n++) {
            int col = col0 + warpN * 32 + n * 8 + tig * 2;
            float b0 = __ldg(&bias[col]), b1 = __ldg(&bias[col + 1]);
            float2 o;
            o.x = alpha * (acc[m][n][0] + b0);
            o.y = alpha * (acc[m][n][1] + b1);
            *reinterpret_cast<float2*>(&Cout[(size_t)rg * CC + col]) = o;
            o.x = alpha * (acc[m][n][2] + b0);
            o.y = alpha * (acc[m][n][3] + b1);
            *reinterpret_cast<float2*>(&Cout[(size_t)(rg + 8) * CC + col]) = o;
        }
    }
}

__global__ void __launch_bounds__(256, 2) proj3_mma(const float* __restrict__ bin) {
    const int z = blockIdx.z;
    const uint32_t* Ahz = (z == 0) ? g_bQh : (z == 1) ? g_bKh : g_bVh;
    const uint32_t* Alz = (z == 0) ? g_bQl : (z == 1) ? g_bKl : g_bVl;
    float* Cz = (z == 0) ? g_q : (z == 1) ? g_k : g_v;
    const float alpha = (z == 0) ? 0.125f : 1.0f;
    gemm_bf16_body(Ahz, Alz,
                   g_bWih + (size_t)z * (CC * CC / 2),
                   g_bWil + (size_t)z * (CC * CC / 2),
                   bin + z * CC, Cz, alpha);
}

__global__ void __launch_bounds__(256, 2) outproj_mma(
    const float* __restrict__ bout, float* __restrict__ out) {
    gemm_bf16_body(g_bAh, g_bAl, g_bWoh, g_bWol, bout, out, 1.0f);
}

// ===========================================================================
// Sliced attention (R14 champion, unchanged)
// ===========================================================================
#define KROW 68
#define PBUF_BASE (512 * KROW)
#define ATTN_SMEM ((PBUF_BASE + 32 * 128) * 4)

__global__ void __launch_bounds__(1024) attn2_kernel(const int* __restrict__ index_pair)
{
    extern __shared__ float sk[];
    const uint32_t skaddr = smem_u32(sk);
    const int h = blockIdx.x, b = blockIdx.y;
    const int t = threadIdx.x, warp = t >> 5, lane = t & 31;
    const int qtr = lane >> 3, d_oct = lane & 7;
    const int ks = g_key_start[b];

    // ---- stage K slice [512 x 64] via cp.async ----
    {
        int seg = t & 15;
        int r0 = t >> 4;
#pragma unroll
        for (int p = 0; p < 8; p++) {
            int row = r0 + p * 64;
            cpa16(skaddr + (uint32_t)(row * KROW * 4 + seg * 16),
                  &g_k[(size_t)(ks + row) * CC + h * DD + seg * 4]);
        }
        CP_COMMIT; CP_WAIT0;
    }
    __syncthreads();

    // ---- phase 1: scores + softmax -> g_w (pipelined) ----
    {
        int n0 = b * 512 + warp;
        int2 iv = *reinterpret_cast<const int2*>(&index_pair[n0 * LL + lane * 2]);
        const float* qb0 = &g_q[(size_t)n0 * CC + h * DD];
        float4 q0 = *reinterpret_cast<const float4*>(&qb0[d_oct * 4]);
        float4 q1 = *reinterpret_cast<const float4*>(&qb0[32 + d_oct * 4]);

#pragma unroll 1
        for (int j = 0; j < 16; j++) {
            const int n = b * 512 + warp + 32 * j;
            int2 ivn; float4 q0n, q1n;
            if (j < 15) {
                int nn = n + 32;
                ivn = *reinterpret_cast<const int2*>(&index_pair[nn * LL + lane * 2]);
                const float* qbn = &g_q[(size_t)nn * CC + h * DD];
                q0n = *reinterpret_cast<const float4*>(&qbn[d_oct * 4]);
                q1n = *reinterpret_cast<const float4*>(&qbn[32 + d_oct * 4]);
            }

            float sc[16];
#pragma unroll
            for (int li = 0; li < 16; li++) {
                int src = qtr * 8 + (li >> 1);
                int raw = __shfl_sync(0xffffffffu, (li & 1) ? iv.y : iv.x, src);
                int row = (raw >= 0) ? raw : 0;
                const float* kr = &sk[row * KROW];
                float4 k0 = *reinterpret_cast<const float4*>(&kr[d_oct * 4]);
                float4 k1 = *reinterpret_cast<const float4*>(&kr[32 + d_oct * 4]);
                float s = q0.x * k0.x;
                s = fmaf(q0.y, k0.y, s); s = fmaf(q0.z, k0.z, s); s = fmaf(q0.w, k0.w, s);
                s = fmaf(q1.x, k1.x, s); s = fmaf(q1.y, k1.y, s);
                s = fmaf(q1.z, k1.z, s); s = fmaf(q1.w, k1.w, s);
                s += __shfl_xor_sync(0xffffffffu, s, 1);
                s += __shfl_xor_sync(0xffffffffu, s, 2);
                s += __shfl_xor_sync(0xffffffffu, s, 4);
                sc[li] = (raw >= 0) ? s : -1000.0f;
            }

            float m = sc[0];
#pragma unroll
            for (int li = 1; li < 16; li++) m = fmaxf(m, sc[li]);
            m = fmaxf(m, __shfl_xor_sync(0xffffffffu, m, 8));
            m = fmaxf(m, __shfl_xor_sync(0xffffffffu, m, 16));
            float sum = 0.0f;
#pragma unroll
            for (int li = 0; li < 16; li++) { sc[li] = __expf(sc[li] - m); sum += sc[li]; }
            sum += __shfl_xor_sync(0xffffffffu, sum, 8);
            sum += __shfl_xor_sync(0xffffffffu, sum, 16);
            float inv = 1.0f / sum;

            float* wdst = &g_w[((size_t)h * NQ + n) * LL];
            wdst[qtr * 16 + d_oct]     = sc[d_oct] * inv;
            wdst[qtr * 16 + d_oct + 8] = sc[d_oct + 8] * inv;

            iv = ivn; q0 = q0n; q1 = q1n;
        }
    }
    __syncthreads();

    // ---- stage V slice (overwrite K) via cp.async ----
    {
        int seg = t & 15;
        int r0 = t >> 4;
#pragma unroll
        for (int p = 0; p < 8; p++) {
            int row = r0 + p * 64;
            cpa16(skaddr + (uint32_t)(row * KROW * 4 + seg * 16),
                  &g_v[(size_t)(ks + row) * CC + h * DD + seg * 4]);
        }
        CP_COMMIT; CP_WAIT0;
    }
    __syncthreads();

    // ---- phase 2: weighted sum via smem pair buffer (pipelined) ----
    {
        const int pbase = PBUF_BASE + warp * 128;
        int n0 = b * 512 + warp;
        float2 wv = *reinterpret_cast<const float2*>(
            &g_w[((size_t)h * NQ + n0) * LL + lane * 2]);
        int2 iv = *reinterpret_cast<const int2*>(&index_pair[n0 * LL + lane * 2]);

#pragma unroll 1
        for (int j = 0; j < 16; j++) {
            const int n = b * 512 + warp + 32 * j;
            float2 wvn; int2 ivn;
            if (j < 15) {
                int nn = n + 32;
                wvn = *reinterpret_cast<const float2*>(
                    &g_w[((size_t)h * NQ + nn) * LL + lane * 2]);
                ivn = *reinterpret_cast<const int2*>(&index_pair[nn * LL + lane * 2]);
            }

            int r0 = ((iv.x >= 0) ? iv.x : 0) * KROW;
            int r1 = ((iv.y >= 0) ? iv.y : 0) * KROW;

            __syncwarp();
            float4 st4;
            st4.x = wv.x; st4.y = __int_as_float(r0);
            st4.z = wv.y; st4.w = __int_as_float(r1);
            *reinterpret_cast<float4*>(&sk[pbase + lane * 4]) = st4;
            __syncwarp();

            float2 acc = make_float2(0.0f, 0.0f);
#pragma unroll
            for (int l = 0; l < 64; l++) {
                float2 pr = *reinterpret_cast<const float2*>(&sk[pbase + l * 2]);
                int ro = __float_as_int(pr.y);
                float2 vv = *reinterpret_cast<const float2*>(&sk[ro + lane * 2]);
                acc.x = fmaf(pr.x, vv.x, acc.x);
                acc.y = fmaf(pr.x, vv.y, acc.y);
            }
            uint32_t hh = packbf(acc.x, acc.y);
            uint32_t ll = packbf(acc.x - bflo(hh), acc.y - bfhi(hh));
            size_t o2 = ((size_t)n * CC + h * DD + lane * 2) >> 1;
            g_bAh[o2] = hh;
            g_bAl[o2] = ll;

            wv = wvn; iv = ivn;
        }
    }
}

// aux[n,l] = mean over heads of w
__global__ void __launch_bounds__(256) aux_kernel(float* __restrict__ aux_out) {
    int i = blockIdx.x * 256 + threadIdx.x;
    float s = 0.0f;
#pragma unroll
    for (int h = 0; h < HH; h++) s += __ldg(&g_w[(size_t)h * (NQ * LL) + i]);
    aux_out[i] = s * 0.125f;
}

// ---------------------------------------------------------------------------
extern "C" void kernel_launch(void* const* d_in, const int* in_sizes, int n_in,
                              void* d_out, int out_size) {
    const float* query  = (const float*)d_in[0];
    const float* key    = (const float*)d_in[1];
    const float* value  = (const float*)d_in[2];
    const float* Win    = (const float*)d_in[3];
    const float* bin    = (const float*)d_in[4];
    const float* Wout   = (const float*)d_in[5];
    const float* bout   = (const float*)d_in[6];
    const int*   index_pair       = (const int*)d_in[7];
    const int*   key_batch_cnt    = (const int*)d_in[9];
    float* out = (float*)d_out;

    float* auxs;
    cudaGetSymbolAddress((void**)&auxs, g_aux_scratch);
    float* aux_out = (out_size >= NQ * CC + NQ * LL) ? (out + (size_t)NQ * CC) : auxs;

    cudaFuncSetAttribute(proj3_mma,    cudaFuncAttributeMaxDynamicSharedMemorySize, DSMEM_SIZE);
    cudaFuncSetAttribute(outproj_mma,  cudaFuncAttributeMaxDynamicSharedMemorySize, DSMEM_SIZE);
    cudaFuncSetAttribute(attn2_kernel, cudaFuncAttributeMaxDynamicSharedMemorySize, ATTN_SMEM);

    // fused: key_start + all fp32 -> split-bf16 conversions
    cvt_all_kernel<<<(N4_TOTAL + 255) / 256, 256>>>(
        (const float4*)query, (const float4*)key, (const float4*)value,
        (const float4*)Win, (const float4*)Wout, key_batch_cnt);

    dim3 gproj(CC / 128, NQ / 128, 3);
    proj3_mma<<<gproj, 256, DSMEM_SIZE>>>(bin);

    dim3 gattn(HH, BB);
    attn2_kernel<<<gattn, 1024, ATTN_SMEM>>>(index_pair);

    aux_kernel<<<NQ * LL / 256, 256>>>(aux_out);

    dim3 gout(CC / 128, NQ / 128);
    outproj_mma<<<gout, 256, DSMEM_SIZE>>>(bout, out);
}

// round 16
// speedup vs baseline: 1.1828x; 1.0007x over previous
#include <cuda_runtime.h>
#include <cstdint>

#define NQ 8192
#define MK 8192
#define BB 16
#define CC 512
#define LL 64
#define HH 8
#define DD 64

// fp32 intermediates
__device__ float g_q[NQ * CC];
__device__ float g_k[MK * CC];
__device__ float g_v[MK * CC];
__device__ float g_w[HH * NQ * LL];     // softmax weights scratch (16 MB)
__device__ float g_aux_scratch[NQ * LL];
__device__ int   g_key_start[BB];

// bf16 split operands (hi/lo), packed 2 elements per uint32
__device__ uint32_t g_bQh[NQ * CC / 2], g_bQl[NQ * CC / 2];
__device__ uint32_t g_bKh[MK * CC / 2], g_bKl[MK * CC / 2];
__device__ uint32_t g_bVh[MK * CC / 2], g_bVl[MK * CC / 2];
__device__ uint32_t g_bWih[3 * CC * CC / 2], g_bWil[3 * CC * CC / 2];
__device__ uint32_t g_bWoh[CC * CC / 2],     g_bWol[CC * CC / 2];
__device__ uint32_t g_bAh[NQ * CC / 2],      g_bAl[NQ * CC / 2];

// ---------------------------------------------------------------------------
static __device__ __forceinline__ uint32_t smem_u32(const void* p) {
    uint32_t a;
    asm("{ .reg .u64 t; cvta.to.shared.u64 t, %1; cvt.u32.u64 %0, t; }" : "=r"(a) : "l"(p));
    return a;
}
static __device__ __forceinline__ uint32_t packbf(float f0, float f1) {
    uint32_t r;
    asm("cvt.rn.bf16x2.f32 %0, %1, %2;" : "=r"(r) : "f"(f1), "f"(f0));
    return r;
}
static __device__ __forceinline__ float bflo(uint32_t r) { return __uint_as_float(r << 16); }
static __device__ __forceinline__ float bfhi(uint32_t r) { return __uint_as_float(r & 0xffff0000u); }
static __device__ __forceinline__ void cpa16(uint32_t dst, const void* src) {
    asm volatile("cp.async.cg.shared.global [%0], [%1], 16;" :: "r"(dst), "l"(src) : "memory");
}
#define CP_COMMIT asm volatile("cp.async.commit_group;" ::: "memory")
#define CP_WAIT1  asm volatile("cp.async.wait_group 1;" ::: "memory")
#define CP_WAIT0  asm volatile("cp.async.wait_group 0;" ::: "memory")

#define MMA_BF16(c, a0, a1, a2, a3, b0, b1)                                   \
    asm volatile(                                                             \
        "mma.sync.aligned.m16n8k16.row.col.f32.bf16.bf16.f32 "                \
        "{%0,%1,%2,%3},{%4,%5,%6,%7},{%8,%9},{%0,%1,%2,%3};"                  \
        : "+f"((c)[0]), "+f"((c)[1]), "+f"((c)[2]), "+f"((c)[3])              \
        : "r"(a0), "r"(a1), "r"(a2), "r"(a3), "r"(b0), "r"(b1))

#define LDSM4(r, a)                                                           \
    asm volatile("ldmatrix.sync.aligned.m8n8.x4.shared.b16 {%0,%1,%2,%3}, [%4];" \
        : "=r"((r)[0]), "=r"((r)[1]), "=r"((r)[2]), "=r"((r)[3]) : "r"(a))
#define LDSM2(r0, r1, a)                                                      \
    asm volatile("ldmatrix.sync.aligned.m8n8.x2.shared.b16 {%0,%1}, [%2];"    \
        : "=r"(r0), "=r"(r1) : "r"(a))

// ---------------------------------------------------------------------------
// Fused conversion: one grid covers q, k, v, Win, Wout splits + key_start.
#define N4_QKV (NQ * CC / 4)
#define N4_WI  (3 * CC * CC / 4)
#define N4_WO  (CC * CC / 4)
#define N4_TOTAL (3 * N4_QKV + N4_WI + N4_WO)

__global__ void __launch_bounds__(256) cvt_all_kernel(
    const float4* __restrict__ q, const float4* __restrict__ k,
    const float4* __restrict__ v, const float4* __restrict__ Win,
    const float4* __restrict__ Wout, const int* __restrict__ key_batch_cnt)
{
    if (blockIdx.x == 0 && threadIdx.x == 0) {
        int s = 0;
        for (int b = 0; b < BB; b++) { g_key_start[b] = s; s += key_batch_cnt[b]; }
    }

    int i = blockIdx.x * blockDim.x + threadIdx.x;
    if (i >= N4_TOTAL) return;

    const float4* src;
    uint2 *hi, *lo;
    int ri;
    if (i < N4_QKV) {
        src = q;  hi = (uint2*)g_bQh;  lo = (uint2*)g_bQl;  ri = i;
    } else if (i < 2 * N4_QKV) {
        src = k;  hi = (uint2*)g_bKh;  lo = (uint2*)g_bKl;  ri = i - N4_QKV;
    } else if (i < 3 * N4_QKV) {
        src = v;  hi = (uint2*)g_bVh;  lo = (uint2*)g_bVl;  ri = i - 2 * N4_QKV;
    } else if (i < 3 * N4_QKV + N4_WI) {
        src = Win;  hi = (uint2*)g_bWih;  lo = (uint2*)g_bWil;  ri = i - 3 * N4_QKV;
    } else {
        src = Wout; hi = (uint2*)g_bWoh;  lo = (uint2*)g_bWol;  ri = i - 3 * N4_QKV - N4_WI;
    }

    float4 f = src[ri];
    uint32_t h0 = packbf(f.x, f.y);
    uint32_t h1 = packbf(f.z, f.w);
    uint32_t l0 = packbf(f.x - bflo(h0), f.y - bfhi(h0));
    uint32_t l1 = packbf(f.z - bflo(h1), f.w - bfhi(h1));
    hi[ri] = make_uint2(h0, h1);
    lo[ri] = make_uint2(l0, l1);
}

// zero the aux output region (atomics accumulate into it)
__global__ void __launch_bounds__(256) zero_aux_kernel(float4* __restrict__ aux4) {
    aux4[blockIdx.x * 256 + threadIdx.x] = make_float4(0.f, 0.f, 0.f, 0.f);
}

// ===========================================================================
// Split-bf16 HMMA GEMM with ldmatrix fragment loads (champion, unchanged)
// ===========================================================================
#define SROWB 80
#define TILE_B (128 * SROWB)
#define STAGE_B (4 * TILE_B)
#define DSMEM_SIZE (2 * STAGE_B)

__device__ __forceinline__ void gemm_bf16_body(
    const uint32_t* __restrict__ Ah, const uint32_t* __restrict__ Al,
    const uint32_t* __restrict__ Bh, const uint32_t* __restrict__ Bl,
    const float* __restrict__ bias, float* __restrict__ Cout, float alpha)
{
    extern __shared__ char dsm[];
    const uint32_t sbase = smem_u32(dsm);

    const int t = threadIdx.x;
    const int lane = t & 31, warp = t >> 5;
    const int g = lane >> 2, tig = lane & 3;
    const int warpM = warp & 1, warpN = warp >> 1;
    const int row0 = blockIdx.y * 128, col0 = blockIdx.x * 128;

    const int lrow = lane & 7, lq = lane >> 3;
    const uint32_t aoff =
        (uint32_t)((warpM * 64 + lrow + (lq & 1) * 8) * SROWB) + (uint32_t)((lq >> 1) * 16);
    const uint32_t boff =
        (uint32_t)((warpN * 32 + lrow) * SROWB) + (uint32_t)((lq & 1) * 16);

    const int crow = t >> 1, chalf = t & 1;
    const uint32_t dstoff = (uint32_t)(crow * SROWB + chalf * 32);
    const size_t srcAbase = (size_t)(row0 + crow) * (CC / 2) + chalf * 8;
    const size_t srcBbase = (size_t)(col0 + crow) * (CC / 2) + chalf * 8;

    float acc[4][4][4];
#pragma unroll
    for (int m = 0; m < 4; m++)
#pragma unroll
        for (int n = 0; n < 4; n++)
#pragma unroll
            for (int j = 0; j < 4; j++) acc[m][n][j] = 0.0f;

#define ISSUE(kt, buf)                                                         \
    do {                                                                       \
        uint32_t sb = sbase + (buf) * STAGE_B;                                 \
        size_t ksrc = (size_t)(kt) * 16;                                       \
        cpa16(sb + dstoff,                  Ah + srcAbase + ksrc);             \
        cpa16(sb + dstoff + 16,             Ah + srcAbase + ksrc + 4);         \
        cpa16(sb + TILE_B + dstoff,         Al + srcAbase + ksrc);             \
        cpa16(sb + TILE_B + dstoff + 16,    Al + srcAbase + ksrc + 4);         \
        cpa16(sb + 2*TILE_B + dstoff,       Bh + srcBbase + ksrc);             \
        cpa16(sb + 2*TILE_B + dstoff + 16,  Bh + srcBbase + ksrc + 4);         \
        cpa16(sb + 3*TILE_B + dstoff,       Bl + srcBbase + ksrc);             \
        cpa16(sb + 3*TILE_B + dstoff + 16,  Bl + srcBbase + ksrc + 4);         \
    } while (0)

    const int NT = CC / 32;
    ISSUE(0, 0);
    CP_COMMIT;

    for (int kt = 0; kt < NT; kt++) {
        if (kt + 1 < NT) {
            ISSUE(kt + 1, (kt + 1) & 1);
            CP_COMMIT;
            CP_WAIT1;
        } else {
            CP_WAIT0;
        }
        __syncthreads();

        const uint32_t ab = sbase + (kt & 1) * STAGE_B;
#pragma unroll
        for (int sub = 0; sub < 2; sub++) {
            const uint32_t koff = sub * 32;
            const uint32_t aAddr = ab + aoff + koff;
            const uint32_t bAddr = ab + 2 * TILE_B + boff + koff;
            uint32_t af[4][4];

#pragma unroll
            for (int m = 0; m < 4; m++)
                LDSM4(af[m], aAddr + (uint32_t)(m * 16 * SROWB));
#pragma unroll
            for (int n = 0; n < 4; n++) {
                uint32_t bb = bAddr + (uint32_t)(n * 8 * SROWB);
                uint32_t bh0, bh1, bl0, bl1;
                LDSM2(bh0, bh1, bb);
                LDSM2(bl0, bl1, bb + TILE_B);
#pragma unroll
                for (int m = 0; m < 4; m++) {
                    MMA_BF16(acc[m][n], af[m][0], af[m][1], af[m][2], af[m][3], bh0, bh1);
                    MMA_BF16(acc[m][n], af[m][0], af[m][1], af[m][2], af[m][3], bl0, bl1);
                }
            }

#pragma unroll
            for (int m = 0; m < 4; m++)
                LDSM4(af[m], aAddr + TILE_B + (uint32_t)(m * 16 * SROWB));
#pragma unroll
            for (int n = 0; n < 4; n++) {
                uint32_t bh0, bh1;
                LDSM2(bh0, bh1, bAddr + (uint32_t)(n * 8 * SROWB));
#pragma unroll
                for (int m = 0; m < 4; m++)
                    MMA_BF16(acc[m][n], af[m][0], af[m][1], af[m][2], af[m][3], bh0, bh1);
            }
        }
        __syncthreads();
    }
#undef ISSUE

#pragma unroll
    for (int m = 0; m < 4; m++) {
        int rg = row0 + warpM * 64 + m * 16 + g;
#pragma unroll
        for (int n = 0; n < 4; n++) {
            int col = col0 + warpN * 32 + n * 8 + tig * 2;
            float b0 = __ldg(&bias[col]), b1 = __ldg(&bias[col + 1]);
            float2 o;
            o.x = alpha * (acc[m][n][0] + b0);
            o.y = alpha * (acc[m][n][1] + b1);
            *reinterpret_cast<float2*>(&Cout[(size_t)rg * CC + col]) = o;
            o.x = alpha * (acc[m][n][2] + b0);
            o.y = alpha * (acc[m][n][3] + b1);
            *reinterpret_cast<float2*>(&Cout[(size_t)(rg + 8) * CC + col]) = o;
        }
    }
}

__global__ void __launch_bounds__(256, 2) proj3_mma(const float* __restrict__ bin) {
    const int z = blockIdx.z;
    const uint32_t* Ahz = (z == 0) ? g_bQh : (z == 1) ? g_bKh : g_bVh;
    const uint32_t* Alz = (z == 0) ? g_bQl : (z == 1) ? g_bKl : g_bVl;
    float* Cz = (z == 0) ? g_q : (z == 1) ? g_k : g_v;
    const float alpha = (z == 0) ? 0.125f : 1.0f;
    gemm_bf16_body(Ahz, Alz,
                   g_bWih + (size_t)z * (CC * CC / 2),
                   g_bWil + (size_t)z * (CC * CC / 2),
                   bin + z * CC, Cz, alpha);
}

__global__ void __launch_bounds__(256, 2) outproj_mma(
    const float* __restrict__ bout, float* __restrict__ out) {
    gemm_bf16_body(g_bAh, g_bAl, g_bWoh, g_bWol, bout, out, 1.0f);
}

// ===========================================================================
// Sliced attention with fused aux accumulation (RED.ADD into aux_out).
// ===========================================================================
#define KROW 68
#define PBUF_BASE (512 * KROW)
#define ATTN_SMEM ((PBUF_BASE + 32 * 128) * 4)

__global__ void __launch_bounds__(1024) attn2_kernel(
    const int* __restrict__ index_pair, float* __restrict__ aux_out)
{
    extern __shared__ float sk[];
    const uint32_t skaddr = smem_u32(sk);
    const int h = blockIdx.x, b = blockIdx.y;
    const int t = threadIdx.x, warp = t >> 5, lane = t & 31;
    const int qtr = lane >> 3, d_oct = lane & 7;
    const int ks = g_key_start[b];

    // ---- stage K slice [512 x 64] via cp.async ----
    {
        int seg = t & 15;
        int r0 = t >> 4;
#pragma unroll
        for (int p = 0; p < 8; p++) {
            int row = r0 + p * 64;
            cpa16(skaddr + (uint32_t)(row * KROW * 4 + seg * 16),
                  &g_k[(size_t)(ks + row) * CC + h * DD + seg * 4]);
        }
        CP_COMMIT; CP_WAIT0;
    }
    __syncthreads();

    // ---- phase 1: scores + softmax -> g_w + aux atomics (pipelined) ----
    {
        int n0 = b * 512 + warp;
        int2 iv = *reinterpret_cast<const int2*>(&index_pair[n0 * LL + lane * 2]);
        const float* qb0 = &g_q[(size_t)n0 * CC + h * DD];
        float4 q0 = *reinterpret_cast<const float4*>(&qb0[d_oct * 4]);
        float4 q1 = *reinterpret_cast<const float4*>(&qb0[32 + d_oct * 4]);

#pragma unroll 1
        for (int j = 0; j < 16; j++) {
            const int n = b * 512 + warp + 32 * j;
            int2 ivn; float4 q0n, q1n;
            if (j < 15) {
                int nn = n + 32;
                ivn = *reinterpret_cast<const int2*>(&index_pair[nn * LL + lane * 2]);
                const float* qbn = &g_q[(size_t)nn * CC + h * DD];
                q0n = *reinterpret_cast<const float4*>(&qbn[d_oct * 4]);
                q1n = *reinterpret_cast<const float4*>(&qbn[32 + d_oct * 4]);
            }

            float sc[16];
#pragma unroll
            for (int li = 0; li < 16; li++) {
                int src = qtr * 8 + (li >> 1);
                int raw = __shfl_sync(0xffffffffu, (li & 1) ? iv.y : iv.x, src);
                int row = (raw >= 0) ? raw : 0;
                const float* kr = &sk[row * KROW];
                float4 k0 = *reinterpret_cast<const float4*>(&kr[d_oct * 4]);
                float4 k1 = *reinterpret_cast<const float4*>(&kr[32 + d_oct * 4]);
                float s = q0.x * k0.x;
                s = fmaf(q0.y, k0.y, s); s = fmaf(q0.z, k0.z, s); s = fmaf(q0.w, k0.w, s);
                s = fmaf(q1.x, k1.x, s); s = fmaf(q1.y, k1.y, s);
                s = fmaf(q1.z, k1.z, s); s = fmaf(q1.w, k1.w, s);
                s += __shfl_xor_sync(0xffffffffu, s, 1);
                s += __shfl_xor_sync(0xffffffffu, s, 2);
                s += __shfl_xor_sync(0xffffffffu, s, 4);
                sc[li] = (raw >= 0) ? s : -1000.0f;
            }

            float m = sc[0];
#pragma unroll
            for (int li = 1; li < 16; li++) m = fmaxf(m, sc[li]);
            m = fmaxf(m, __shfl_xor_sync(0xffffffffu, m, 8));
            m = fmaxf(m, __shfl_xor_sync(0xffffffffu, m, 16));
            float sum = 0.0f;
#pragma unroll
            for (int li = 0; li < 16; li++) { sc[li] = __expf(sc[li] - m); sum += sc[li]; }
            sum += __shfl_xor_sync(0xffffffffu, sum, 8);
            sum += __shfl_xor_sync(0xffffffffu, sum, 16);
            float inv = 1.0f / sum;

            float w0 = sc[d_oct] * inv;
            float w1 = sc[d_oct + 8] * inv;
            float* wdst = &g_w[((size_t)h * NQ + n) * LL];
            wdst[qtr * 16 + d_oct]     = w0;
            wdst[qtr * 16 + d_oct + 8] = w1;
            // fused aux: mean over heads accumulated via reduction atomics
            float* adst = &aux_out[(size_t)n * LL];
            atomicAdd(&adst[qtr * 16 + d_oct],     w0 * 0.125f);
            atomicAdd(&adst[qtr * 16 + d_oct + 8], w1 * 0.125f);

            iv = ivn; q0 = q0n; q1 = q1n;
        }
    }
    __syncthreads();

    // ---- stage V slice (overwrite K) via cp.async ----
    {
        int seg = t & 15;
        int r0 = t >> 4;
#pragma unroll
        for (int p = 0; p < 8; p++) {
            int row = r0 + p * 64;
            cpa16(skaddr + (uint32_t)(row * KROW * 4 + seg * 16),
                  &g_v[(size_t)(ks + row) * CC + h * DD + seg * 4]);
        }
        CP_COMMIT; CP_WAIT0;
    }
    __syncthreads();

    // ---- phase 2: weighted sum via smem pair buffer (pipelined) ----
    {
        const int pbase = PBUF_BASE + warp * 128;
        int n0 = b * 512 + warp;
        float2 wv = *reinterpret_cast<const float2*>(
            &g_w[((size_t)h * NQ + n0) * LL + lane * 2]);
        int2 iv = *reinterpret_cast<const int2*>(&index_pair[n0 * LL + lane * 2]);

#pragma unroll 1
        for (int j = 0; j < 16; j++) {
            const int n = b * 512 + warp + 32 * j;
            float2 wvn; int2 ivn;
            if (j < 15) {
                int nn = n + 32;
                wvn = *reinterpret_cast<const float2*>(
                    &g_w[((size_t)h * NQ + nn) * LL + lane * 2]);
                ivn = *reinterpret_cast<const int2*>(&index_pair[nn * LL + lane * 2]);
            }

            int r0 = ((iv.x >= 0) ? iv.x : 0) * KROW;
            int r1 = ((iv.y >= 0) ? iv.y : 0) * KROW;

            __syncwarp();
            float4 st4;
            st4.x = wv.x; st4.y = __int_as_float(r0);
            st4.z = wv.y; st4.w = __int_as_float(r1);
            *reinterpret_cast<float4*>(&sk[pbase + lane * 4]) = st4;
            __syncwarp();

            float2 acc = make_float2(0.0f, 0.0f);
#pragma unroll
            for (int l = 0; l < 64; l++) {
                float2 pr = *reinterpret_cast<const float2*>(&sk[pbase + l * 2]);
                int ro = __float_as_int(pr.y);
                float2 vv = *reinterpret_cast<const float2*>(&sk[ro + lane * 2]);
                acc.x = fmaf(pr.x, vv.x, acc.x);
                acc.y = fmaf(pr.x, vv.y, acc.y);
            }
            uint32_t hh = packbf(acc.x, acc.y);
            uint32_t ll = packbf(acc.x - bflo(hh), acc.y - bfhi(hh));
            size_t o2 = ((size_t)n * CC + h * DD + lane * 2) >> 1;
            g_bAh[o2] = hh;
            g_bAl[o2] = ll;

            wv = wvn; iv = ivn;
        }
    }
}

// ---------------------------------------------------------------------------
extern "C" void kernel_launch(void* const* d_in, const int* in_sizes, int n_in,
                              void* d_out, int out_size) {
    const float* query  = (const float*)d_in[0];
    const float* key    = (const float*)d_in[1];
    const float* value  = (const float*)d_in[2];
    const float* Win    = (const float*)d_in[3];
    const float* bin    = (const float*)d_in[4];
    const float* Wout   = (const float*)d_in[5];
    const float* bout   = (const float*)d_in[6];
    const int*   index_pair       = (const int*)d_in[7];
    const int*   key_batch_cnt    = (const int*)d_in[9];
    float* out = (float*)d_out;

    float* auxs;
    cudaGetSymbolAddress((void**)&auxs, g_aux_scratch);
    float* aux_out = (out_size >= NQ * CC + NQ * LL) ? (out + (size_t)NQ * CC) : auxs;

    cudaFuncSetAttribute(proj3_mma,    cudaFuncAttributeMaxDynamicSharedMemorySize, DSMEM_SIZE);
    cudaFuncSetAttribute(outproj_mma,  cudaFuncAttributeMaxDynamicSharedMemorySize, DSMEM_SIZE);
    cudaFuncSetAttribute(attn2_kernel, cudaFuncAttributeMaxDynamicSharedMemorySize, ATTN_SMEM);

    // fused: key_start + all fp32 -> split-bf16 conversions
    cvt_all_kernel<<<(N4_TOTAL + 255) / 256, 256>>>(
        (const float4*)query, (const float4*)key, (const float4*)value,
        (const float4*)Win, (const float4*)Wout, key_batch_cnt);

    // zero the aux region (attention accumulates into it atomically)
    zero_aux_kernel<<<NQ * LL / 4 / 256, 256>>>((float4*)aux_out);

    dim3 gproj(CC / 128, NQ / 128, 3);
    proj3_mma<<<gproj, 256, DSMEM_SIZE>>>(bin);

    dim3 gattn(HH, BB);
    attn2_kernel<<<gattn, 1024, ATTN_SMEM>>>(index_pair, aux_out);

    dim3 gout(CC / 128, NQ / 128);
    outproj_mma<<<gout, 256, DSMEM_SIZE>>>(bout, out);
}

// round 17
// speedup vs baseline: 1.1940x; 1.0095x over previous
#include <cuda_runtime.h>
#include <cstdint>

#define NQ 8192
#define MK 8192
#define BB 16
#define CC 512
#define LL 64
#define HH 8
#define DD 64

// fp32 intermediates
__device__ float g_q[NQ * CC];
__device__ float g_k[MK * CC];
__device__ float g_v[MK * CC];
__device__ float g_w[HH * NQ * LL];     // softmax weights scratch (16 MB)
__device__ float g_aux_scratch[NQ * LL];
__device__ int   g_key_start[BB];

// bf16 split operands (hi/lo), packed 2 elements per uint32
__device__ uint32_t g_bQh[NQ * CC / 2], g_bQl[NQ * CC / 2];
__device__ uint32_t g_bKh[MK * CC / 2], g_bKl[MK * CC / 2];
__device__ uint32_t g_bVh[MK * CC / 2], g_bVl[MK * CC / 2];
__device__ uint32_t g_bWih[3 * CC * CC / 2], g_bWil[3 * CC * CC / 2];
__device__ uint32_t g_bWoh[CC * CC / 2],     g_bWol[CC * CC / 2];
__device__ uint32_t g_bAh[NQ * CC / 2],      g_bAl[NQ * CC / 2];

// ---------------------------------------------------------------------------
static __device__ __forceinline__ uint32_t smem_u32(const void* p) {
    uint32_t a;
    asm("{ .reg .u64 t; cvta.to.shared.u64 t, %1; cvt.u32.u64 %0, t; }" : "=r"(a) : "l"(p));
    return a;
}
static __device__ __forceinline__ uint32_t packbf(float f0, float f1) {
    uint32_t r;
    asm("cvt.rn.bf16x2.f32 %0, %1, %2;" : "=r"(r) : "f"(f1), "f"(f0));
    return r;
}
static __device__ __forceinline__ float bflo(uint32_t r) { return __uint_as_float(r << 16); }
static __device__ __forceinline__ float bfhi(uint32_t r) { return __uint_as_float(r & 0xffff0000u); }
static __device__ __forceinline__ void cpa16(uint32_t dst, const void* src) {
    asm volatile("cp.async.cg.shared.global [%0], [%1], 16;" :: "r"(dst), "l"(src) : "memory");
}
#define CP_COMMIT asm volatile("cp.async.commit_group;" ::: "memory")
#define CP_WAIT1  asm volatile("cp.async.wait_group 1;" ::: "memory")
#define CP_WAIT0  asm volatile("cp.async.wait_group 0;" ::: "memory")

#define MMA_BF16(c, a0, a1, a2, a3, b0, b1)                                   \
    asm volatile(                                                             \
        "mma.sync.aligned.m16n8k16.row.col.f32.bf16.bf16.f32 "                \
        "{%0,%1,%2,%3},{%4,%5,%6,%7},{%8,%9},{%0,%1,%2,%3};"                  \
        : "+f"((c)[0]), "+f"((c)[1]), "+f"((c)[2]), "+f"((c)[3])              \
        : "r"(a0), "r"(a1), "r"(a2), "r"(a3), "r"(b0), "r"(b1))

#define LDSM4(r, a)                                                           \
    asm volatile("ldmatrix.sync.aligned.m8n8.x4.shared.b16 {%0,%1,%2,%3}, [%4];" \
        : "=r"((r)[0]), "=r"((r)[1]), "=r"((r)[2]), "=r"((r)[3]) : "r"(a))
#define LDSM2(r0, r1, a)                                                      \
    asm volatile("ldmatrix.sync.aligned.m8n8.x2.shared.b16 {%0,%1}, [%2];"    \
        : "=r"(r0), "=r"(r1) : "r"(a))

// ---------------------------------------------------------------------------
// Fused conversion + key_start + aux zeroing, one grid.
#define N4_QKV (NQ * CC / 4)
#define N4_WI  (3 * CC * CC / 4)
#define N4_WO  (CC * CC / 4)
#define N4_CVT (3 * N4_QKV + N4_WI + N4_WO)
#define N4_AUX (NQ * LL / 4)
#define N4_TOTAL (N4_CVT + N4_AUX)

__global__ void __launch_bounds__(256) cvt_all_kernel(
    const float4* __restrict__ q, const float4* __restrict__ k,
    const float4* __restrict__ v, const float4* __restrict__ Win,
    const float4* __restrict__ Wout, const int* __restrict__ key_batch_cnt,
    float4* __restrict__ aux4)
{
    if (blockIdx.x == 0 && threadIdx.x == 0) {
        int s = 0;
        for (int b = 0; b < BB; b++) { g_key_start[b] = s; s += key_batch_cnt[b]; }
    }

    int i = blockIdx.x * blockDim.x + threadIdx.x;
    if (i >= N4_TOTAL) return;
    if (i >= N4_CVT) {                  // aux zero region
        aux4[i - N4_CVT] = make_float4(0.f, 0.f, 0.f, 0.f);
        return;
    }

    const float4* src;
    uint2 *hi, *lo;
    int ri;
    if (i < N4_QKV) {
        src = q;  hi = (uint2*)g_bQh;  lo = (uint2*)g_bQl;  ri = i;
    } else if (i < 2 * N4_QKV) {
        src = k;  hi = (uint2*)g_bKh;  lo = (uint2*)g_bKl;  ri = i - N4_QKV;
    } else if (i < 3 * N4_QKV) {
        src = v;  hi = (uint2*)g_bVh;  lo = (uint2*)g_bVl;  ri = i - 2 * N4_QKV;
    } else if (i < 3 * N4_QKV + N4_WI) {
        src = Win;  hi = (uint2*)g_bWih;  lo = (uint2*)g_bWil;  ri = i - 3 * N4_QKV;
    } else {
        src = Wout; hi = (uint2*)g_bWoh;  lo = (uint2*)g_bWol;  ri = i - 3 * N4_QKV - N4_WI;
    }

    float4 f = src[ri];
    uint32_t h0 = packbf(f.x, f.y);
    uint32_t h1 = packbf(f.z, f.w);
    uint32_t l0 = packbf(f.x - bflo(h0), f.y - bfhi(h0));
    uint32_t l1 = packbf(f.z - bflo(h1), f.w - bfhi(h1));
    hi[ri] = make_uint2(h0, h1);
    lo[ri] = make_uint2(l0, l1);
}

// ===========================================================================
// Split-bf16 HMMA GEMM with ldmatrix fragment loads (champion, unchanged)
// ===========================================================================
#define SROWB 80
#define TILE_B (128 * SROWB)
#define STAGE_B (4 * TILE_B)
#define DSMEM_SIZE (2 * STAGE_B)

__device__ __forceinline__ void gemm_bf16_body(
    const uint32_t* __restrict__ Ah, const uint32_t* __restrict__ Al,
    const uint32_t* __restrict__ Bh, const uint32_t* __restrict__ Bl,
    const float* __restrict__ bias, float* __restrict__ Cout, float alpha)
{
    extern __shared__ char dsm[];
    const uint32_t sbase = smem_u32(dsm);

    const int t = threadIdx.x;
    const int lane = t & 31, warp = t >> 5;
    const int g = lane >> 2, tig = lane & 3;
    const int warpM = warp & 1, warpN = warp >> 1;
    const int row0 = blockIdx.y * 128, col0 = blockIdx.x * 128;

    const int lrow = lane & 7, lq = lane >> 3;
    const uint32_t aoff =
        (uint32_t)((warpM * 64 + lrow + (lq & 1) * 8) * SROWB) + (uint32_t)((lq >> 1) * 16);
    const uint32_t boff =
        (uint32_t)((warpN * 32 + lrow) * SROWB) + (uint32_t)((lq & 1) * 16);

    const int crow = t >> 1, chalf = t & 1;
    const uint32_t dstoff = (uint32_t)(crow * SROWB + chalf * 32);
    const size_t srcAbase = (size_t)(row0 + crow) * (CC / 2) + chalf * 8;
    const size_t srcBbase = (size_t)(col0 + crow) * (CC / 2) + chalf * 8;

    float acc[4][4][4];
#pragma unroll
    for (int m = 0; m < 4; m++)
#pragma unroll
        for (int n = 0; n < 4; n++)
#pragma unroll
            for (int j = 0; j < 4; j++) acc[m][n][j] = 0.0f;

#define ISSUE(kt, buf)                                                         \
    do {                                                                       \
        uint32_t sb = sbase + (buf) * STAGE_B;                                 \
        size_t ksrc = (size_t)(kt) * 16;                                       \
        cpa16(sb + dstoff,                  Ah + srcAbase + ksrc);             \
        cpa16(sb + dstoff + 16,             Ah + srcAbase + ksrc + 4);         \
        cpa16(sb + TILE_B + dstoff,         Al + srcAbase + ksrc);             \
        cpa16(sb + TILE_B + dstoff + 16,    Al + srcAbase + ksrc + 4);         \
        cpa16(sb + 2*TILE_B + dstoff,       Bh + srcBbase + ksrc);             \
        cpa16(sb + 2*TILE_B + dstoff + 16,  Bh + srcBbase + ksrc + 4);         \
        cpa16(sb + 3*TILE_B + dstoff,       Bl + srcBbase + ksrc);             \
        cpa16(sb + 3*TILE_B + dstoff + 16,  Bl + srcBbase + ksrc + 4);         \
    } while (0)

    const int NT = CC / 32;
    ISSUE(0, 0);
    CP_COMMIT;

    for (int kt = 0; kt < NT; kt++) {
        if (kt + 1 < NT) {
            ISSUE(kt + 1, (kt + 1) & 1);
            CP_COMMIT;
            CP_WAIT1;
        } else {
            CP_WAIT0;
        }
        __syncthreads();

        const uint32_t ab = sbase + (kt & 1) * STAGE_B;
#pragma unroll
        for (int sub = 0; sub < 2; sub++) {
            const uint32_t koff = sub * 32;
            const uint32_t aAddr = ab + aoff + koff;
            const uint32_t bAddr = ab + 2 * TILE_B + boff + koff;
            uint32_t af[4][4];

#pragma unroll
            for (int m = 0; m < 4; m++)
                LDSM4(af[m], aAddr + (uint32_t)(m * 16 * SROWB));
#pragma unroll
            for (int n = 0; n < 4; n++) {
                uint32_t bb = bAddr + (uint32_t)(n * 8 * SROWB);
                uint32_t bh0, bh1, bl0, bl1;
                LDSM2(bh0, bh1, bb);
                LDSM2(bl0, bl1, bb + TILE_B);
#pragma unroll
                for (int m = 0; m < 4; m++) {
                    MMA_BF16(acc[m][n], af[m][0], af[m][1], af[m][2], af[m][3], bh0, bh1);
                    MMA_BF16(acc[m][n], af[m][0], af[m][1], af[m][2], af[m][3], bl0, bl1);
                }
            }

#pragma unroll
            for (int m = 0; m < 4; m++)
                LDSM4(af[m], aAddr + TILE_B + (uint32_t)(m * 16 * SROWB));
#pragma unroll
            for (int n = 0; n < 4; n++) {
                uint32_t bh0, bh1;
                LDSM2(bh0, bh1, bAddr + (uint32_t)(n * 8 * SROWB));
#pragma unroll
                for (int m = 0; m < 4; m++)
                    MMA_BF16(acc[m][n], af[m][0], af[m][1], af[m][2], af[m][3], bh0, bh1);
            }
        }
        __syncthreads();
    }
#undef ISSUE

#pragma unroll
    for (int m = 0; m < 4; m++) {
        int rg = row0 + warpM * 64 + m * 16 + g;
#pragma unroll
        for (int n = 0; n < 4; n++) {
            int col = col0 + warpN * 32 + n * 8 + tig * 2;
            float b0 = __ldg(&bias[col]), b1 = __ldg(&bias[col + 1]);
            float2 o;
            o.x = alpha * (acc[m][n][0] + b0);
            o.y = alpha * (acc[m][n][1] + b1);
            *reinterpret_cast<float2*>(&Cout[(size_t)rg * CC + col]) = o;
            o.x = alpha * (acc[m][n][2] + b0);
            o.y = alpha * (acc[m][n][3] + b1);
            *reinterpret_cast<float2*>(&Cout[(size_t)(rg + 8) * CC + col]) = o;
        }
    }
}

__global__ void __launch_bounds__(256, 2) proj3_mma(const float* __restrict__ bin) {
    const int z = blockIdx.z;
    const uint32_t* Ahz = (z == 0) ? g_bQh : (z == 1) ? g_bKh : g_bVh;
    const uint32_t* Alz = (z == 0) ? g_bQl : (z == 1) ? g_bKl : g_bVl;
    float* Cz = (z == 0) ? g_q : (z == 1) ? g_k : g_v;
    const float alpha = (z == 0) ? 0.125f : 1.0f;
    gemm_bf16_body(Ahz, Alz,
                   g_bWih + (size_t)z * (CC * CC / 2),
                   g_bWil + (size_t)z * (CC * CC / 2),
                   bin + z * CC, Cz, alpha);
}

__global__ void __launch_bounds__(256, 2) outproj_mma(
    const float* __restrict__ bout, float* __restrict__ out) {
    gemm_bf16_body(g_bAh, g_bAl, g_bWoh, g_bWol, bout, out, 1.0f);
}

// ===========================================================================
// Sliced attention: no phase-1 prefetch (register relief), double-buffered
// pair smem in phase 2 (one __syncwarp per j), fused aux atomics.
// ===========================================================================
#define KROW 68
#define PBUF_BASE (512 * KROW)
#define ATTN_SMEM ((PBUF_BASE + 32 * 256) * 4)   // 2 pair buffers per warp

__global__ void __launch_bounds__(1024) attn2_kernel(
    const int* __restrict__ index_pair, float* __restrict__ aux_out)
{
    extern __shared__ float sk[];
    const uint32_t skaddr = smem_u32(sk);
    const int h = blockIdx.x, b = blockIdx.y;
    const int t = threadIdx.x, warp = t >> 5, lane = t & 31;
    const int qtr = lane >> 3, d_oct = lane & 7;
    const int ks = g_key_start[b];

    // ---- stage K slice [512 x 64] via cp.async ----
    {
        int seg = t & 15;
        int r0 = t >> 4;
#pragma unroll
        for (int p = 0; p < 8; p++) {
            int row = r0 + p * 64;
            cpa16(skaddr + (uint32_t)(row * KROW * 4 + seg * 16),
                  &g_k[(size_t)(ks + row) * CC + h * DD + seg * 4]);
        }
        CP_COMMIT; CP_WAIT0;
    }
    __syncthreads();

    // ---- phase 1: scores + softmax -> g_w + aux atomics ----
#pragma unroll 1
    for (int j = 0; j < 16; j++) {
        const int n = b * 512 + warp + 32 * j;
        int2 iv = *reinterpret_cast<const int2*>(&index_pair[n * LL + lane * 2]);
        const float* qb = &g_q[(size_t)n * CC + h * DD];
        float4 q0 = *reinterpret_cast<const float4*>(&qb[d_oct * 4]);
        float4 q1 = *reinterpret_cast<const float4*>(&qb[32 + d_oct * 4]);

        float sc[16];
#pragma unroll
        for (int li = 0; li < 16; li++) {
            int src = qtr * 8 + (li >> 1);
            int raw = __shfl_sync(0xffffffffu, (li & 1) ? iv.y : iv.x, src);
            int row = (raw >= 0) ? raw : 0;
            const float* kr = &sk[row * KROW];
            float4 k0 = *reinterpret_cast<const float4*>(&kr[d_oct * 4]);
            float4 k1 = *reinterpret_cast<const float4*>(&kr[32 + d_oct * 4]);
            float s = q0.x * k0.x;
            s = fmaf(q0.y, k0.y, s); s = fmaf(q0.z, k0.z, s); s = fmaf(q0.w, k0.w, s);
            s = fmaf(q1.x, k1.x, s); s = fmaf(q1.y, k1.y, s);
            s = fmaf(q1.z, k1.z, s); s = fmaf(q1.w, k1.w, s);
            s += __shfl_xor_sync(0xffffffffu, s, 1);
            s += __shfl_xor_sync(0xffffffffu, s, 2);
            s += __shfl_xor_sync(0xffffffffu, s, 4);
            sc[li] = (raw >= 0) ? s : -1000.0f;
        }

        float m = sc[0];
#pragma unroll
        for (int li = 1; li < 16; li++) m = fmaxf(m, sc[li]);
        m = fmaxf(m, __shfl_xor_sync(0xffffffffu, m, 8));
        m = fmaxf(m, __shfl_xor_sync(0xffffffffu, m, 16));
        float sum = 0.0f;
#pragma unroll
        for (int li = 0; li < 16; li++) { sc[li] = __expf(sc[li] - m); sum += sc[li]; }
        sum += __shfl_xor_sync(0xffffffffu, sum, 8);
        sum += __shfl_xor_sync(0xffffffffu, sum, 16);
        float inv = 1.0f / sum;

        float w0 = sc[d_oct] * inv;
        float w1 = sc[d_oct + 8] * inv;
        float* wdst = &g_w[((size_t)h * NQ + n) * LL];
        wdst[qtr * 16 + d_oct]     = w0;
        wdst[qtr * 16 + d_oct + 8] = w1;
        float* adst = &aux_out[(size_t)n * LL];
        atomicAdd(&adst[qtr * 16 + d_oct],     w0 * 0.125f);
        atomicAdd(&adst[qtr * 16 + d_oct + 8], w1 * 0.125f);
    }
    __syncthreads();

    // ---- stage V slice (overwrite K) via cp.async ----
    {
        int seg = t & 15;
        int r0 = t >> 4;
#pragma unroll
        for (int p = 0; p < 8; p++) {
            int row = r0 + p * 64;
            cpa16(skaddr + (uint32_t)(row * KROW * 4 + seg * 16),
                  &g_v[(size_t)(ks + row) * CC + h * DD + seg * 4]);
        }
        CP_COMMIT; CP_WAIT0;
    }
    __syncthreads();

    // ---- phase 2: weighted sum, double-buffered pair smem (pipelined) ----
    {
        int n0 = b * 512 + warp;
        float2 wv = *reinterpret_cast<const float2*>(
            &g_w[((size_t)h * NQ + n0) * LL + lane * 2]);
        int2 iv = *reinterpret_cast<const int2*>(&index_pair[n0 * LL + lane * 2]);

#pragma unroll 1
        for (int j = 0; j < 16; j++) {
            const int n = b * 512 + warp + 32 * j;
            float2 wvn; int2 ivn;
            if (j < 15) {
                int nn = n + 32;
                wvn = *reinterpret_cast<const float2*>(
                    &g_w[((size_t)h * NQ + nn) * LL + lane * 2]);
                ivn = *reinterpret_cast<const int2*>(&index_pair[nn * LL + lane * 2]);
            }

            const int pbase = PBUF_BASE + warp * 256 + (j & 1) * 128;
            int r0 = ((iv.x >= 0) ? iv.x : 0) * KROW;
            int r1 = ((iv.y >= 0) ? iv.y : 0) * KROW;

            float4 st4;
            st4.x = wv.x; st4.y = __int_as_float(r0);
            st4.z = wv.y; st4.w = __int_as_float(r1);
            *reinterpret_cast<float4*>(&sk[pbase + lane * 4]) = st4;
            __syncwarp();

            float2 acc = make_float2(0.0f, 0.0f);
#pragma unroll
            for (int l = 0; l < 64; l++) {
                float2 pr = *reinterpret_cast<const float2*>(&sk[pbase + l * 2]);
                int ro = __float_as_int(pr.y);
                float2 vv = *reinterpret_cast<const float2*>(&sk[ro + lane * 2]);
                acc.x = fmaf(pr.x, vv.x, acc.x);
                acc.y = fmaf(pr.x, vv.y, acc.y);
            }
            uint32_t hh = packbf(acc.x, acc.y);
            uint32_t ll = packbf(acc.x - bflo(hh), acc.y - bfhi(hh));
            size_t o2 = ((size_t)n * CC + h * DD + lane * 2) >> 1;
            g_bAh[o2] = hh;
            g_bAl[o2] = ll;

            wv = wvn; iv = ivn;
        }
    }
}

// ---------------------------------------------------------------------------
extern "C" void kernel_launch(void* const* d_in, const int* in_sizes, int n_in,
                              void* d_out, int out_size) {
    const float* query  = (const float*)d_in[0];
    const float* key    = (const float*)d_in[1];
    const float* value  = (const float*)d_in[2];
    const float* Win    = (const float*)d_in[3];
    const float* bin    = (const float*)d_in[4];
    const float* Wout   = (const float*)d_in[5];
    const float* bout   = (const float*)d_in[6];
    const int*   index_pair       = (const int*)d_in[7];
    const int*   key_batch_cnt    = (const int*)d_in[9];
    float* out = (float*)d_out;

    float* auxs;
    cudaGetSymbolAddress((void**)&auxs, g_aux_scratch);
    float* aux_out = (out_size >= NQ * CC + NQ * LL) ? (out + (size_t)NQ * CC) : auxs;

    cudaFuncSetAttribute(proj3_mma,    cudaFuncAttributeMaxDynamicSharedMemorySize, DSMEM_SIZE);
    cudaFuncSetAttribute(outproj_mma,  cudaFuncAttributeMaxDynamicSharedMemorySize, DSMEM_SIZE);
    cudaFuncSetAttribute(attn2_kernel, cudaFuncAttributeMaxDynamicSharedMemorySize, ATTN_SMEM);

    // fused: key_start + conversions + aux zeroing
    cvt_all_kernel<<<(N4_TOTAL + 255) / 256, 256>>>(
        (const float4*)query, (const float4*)key, (const float4*)value,
        (const float4*)Win, (const float4*)Wout, key_batch_cnt, (float4*)aux_out);

    dim3 gproj(CC / 128, NQ / 128, 3);
    proj3_mma<<<gproj, 256, DSMEM_SIZE>>>(bin);

    dim3 gattn(HH, BB);
    attn2_kernel<<<gattn, 1024, ATTN_SMEM>>>(index_pair, aux_out);

    dim3 gout(CC / 128, NQ / 128);
    outproj_mma<<<gout, 256, DSMEM_SIZE>>>(bout, out);
}